// round 1
// baseline (speedup 1.0000x reference)
#include <cuda_runtime.h>
#include <math.h>

// ---------------- scratch ----------------
#define Bsz 8
#define Nseq 1024
#define Cdim 768
#define Hh 8
#define Dd 96
#define Qq 8

__device__ float g_qkv[Bsz * Nseq * 3 * Cdim];          // 18.9M floats
__device__ float g_attn[(size_t)Bsz * Hh * Nseq * Nseq]; // 67.1M floats
__device__ float g_qout[Bsz * Nseq * Cdim];
__device__ float g_cout[Bsz * Nseq * Cdim];
__device__ float g_fused[Bsz * Nseq * Cdim];
__device__ float g_xmean[Bsz * Cdim];
__device__ float g_fw[Bsz * Cdim];

// ---------------- generic NN GEMM: C = A@B (+bias) (+resid) ----------------
// BM=128, BN=64, BK=16, 256 threads, 8x4 microtile. M%128==0, N%64==0, K%16==0.
__global__ void gemm_nn_kernel(const float* __restrict__ A, const float* __restrict__ B,
                               const float* __restrict__ bias, const float* __restrict__ resid,
                               float* __restrict__ C, int M, int N, int K,
                               int lda, int ldb, int ldc) {
    __shared__ float As[16][128];
    __shared__ float Bs[16][64];
    int tid = threadIdx.x;
    int m0 = blockIdx.y * 128;
    int n0 = blockIdx.x * 64;
    int ty = tid >> 4, tx = tid & 15;
    int r0 = ty * 8, c0 = tx * 4;
    float acc[8][4] = {};
    for (int k0 = 0; k0 < K; k0 += 16) {
#pragma unroll
        for (int i = 0; i < 8; i++) {
            int idx = tid + i * 256;
            int m = idx >> 4, kk = idx & 15;
            As[kk][m] = A[(size_t)(m0 + m) * lda + k0 + kk];
        }
#pragma unroll
        for (int i = 0; i < 4; i++) {
            int idx = tid + i * 256;
            int kk = idx >> 6, n = idx & 63;
            Bs[kk][n] = B[(size_t)(k0 + kk) * ldb + n0 + n];
        }
        __syncthreads();
#pragma unroll
        for (int kk = 0; kk < 16; kk++) {
            float a[8], bv[4];
#pragma unroll
            for (int i = 0; i < 8; i++) a[i] = As[kk][r0 + i];
#pragma unroll
            for (int j = 0; j < 4; j++) bv[j] = Bs[kk][c0 + j];
#pragma unroll
            for (int i = 0; i < 8; i++)
#pragma unroll
                for (int j = 0; j < 4; j++) acc[i][j] += a[i] * bv[j];
        }
        __syncthreads();
    }
#pragma unroll
    for (int i = 0; i < 8; i++) {
        int m = m0 + r0 + i;
#pragma unroll
        for (int j = 0; j < 4; j++) {
            int n = n0 + c0 + j;
            float v = acc[i][j];
            if (bias) v += bias[n];
            if (resid) v += resid[(size_t)m * ldc + n];
            C[(size_t)m * ldc + n] = v;
        }
    }
}

// ---------------- scores: attn[b,h,n,m] = scale * q[n,:].k[m,:] (NT) ----------------
__global__ void scores_kernel(const float* __restrict__ qkv, float* __restrict__ attn) {
    __shared__ float As[16][128];
    __shared__ float Bs[16][64];
    int z = blockIdx.z;
    int b = z >> 3, h = z & 7;
    const float* qbase = qkv + (size_t)b * Nseq * 2304 + h * Dd;
    const float* kbase = qbase + 768;
    float* cbase = attn + (size_t)z * Nseq * Nseq;
    int tid = threadIdx.x;
    int n0 = blockIdx.y * 128;  // q rows
    int m0 = blockIdx.x * 64;   // k cols
    int ty = tid >> 4, tx = tid & 15;
    int r0 = ty * 8, c0 = tx * 4;
    float acc[8][4] = {};
    for (int k0 = 0; k0 < Dd; k0 += 16) {
#pragma unroll
        for (int i = 0; i < 8; i++) {
            int idx = tid + i * 256;
            int m = idx >> 4, kk = idx & 15;
            As[kk][m] = qbase[(size_t)(n0 + m) * 2304 + k0 + kk];
        }
#pragma unroll
        for (int i = 0; i < 4; i++) {
            int idx = tid + i * 256;
            int m = idx >> 4, kk = idx & 15;
            Bs[kk][m] = kbase[(size_t)(m0 + m) * 2304 + k0 + kk];
        }
        __syncthreads();
#pragma unroll
        for (int kk = 0; kk < 16; kk++) {
            float a[8], bv[4];
#pragma unroll
            for (int i = 0; i < 8; i++) a[i] = As[kk][r0 + i];
#pragma unroll
            for (int j = 0; j < 4; j++) bv[j] = Bs[kk][c0 + j];
#pragma unroll
            for (int i = 0; i < 8; i++)
#pragma unroll
                for (int j = 0; j < 4; j++) acc[i][j] += a[i] * bv[j];
        }
        __syncthreads();
    }
    const float scale = 0.10206207261596577f;  // 96^-0.5
#pragma unroll
    for (int i = 0; i < 8; i++)
#pragma unroll
        for (int j = 0; j < 4; j++)
            cbase[(size_t)(n0 + r0 + i) * Nseq + m0 + c0 + j] = acc[i][j] * scale;
}

// ---------------- row softmax over 1024 ----------------
__global__ void softmax_rows(float* __restrict__ attn) {
    __shared__ float redm[8], reds[8];
    size_t row = blockIdx.x;
    float* p = attn + row * Nseq;
    int tid = threadIdx.x;
    float v[4];
    float mx = -1e30f;
#pragma unroll
    for (int i = 0; i < 4; i++) { v[i] = p[tid + i * 256]; mx = fmaxf(mx, v[i]); }
#pragma unroll
    for (int o = 16; o > 0; o >>= 1) mx = fmaxf(mx, __shfl_xor_sync(~0u, mx, o));
    int w = tid >> 5, lane = tid & 31;
    if (lane == 0) redm[w] = mx;
    __syncthreads();
    mx = redm[0];
#pragma unroll
    for (int i = 1; i < 8; i++) mx = fmaxf(mx, redm[i]);
    float sum = 0.f;
#pragma unroll
    for (int i = 0; i < 4; i++) { v[i] = expf(v[i] - mx); sum += v[i]; }
#pragma unroll
    for (int o = 16; o > 0; o >>= 1) sum += __shfl_xor_sync(~0u, sum, o);
    if (lane == 0) reds[w] = sum;
    __syncthreads();
    sum = 0.f;
#pragma unroll
    for (int i = 0; i < 8; i++) sum += reds[i];
    float inv = 1.f / sum;
#pragma unroll
    for (int i = 0; i < 4; i++) p[tid + i * 256] = v[i] * inv;
}

// ---------------- attn @ v  -> cout[b,n,h*96+d] ----------------
__global__ void attnv_kernel(const float* __restrict__ attn, const float* __restrict__ qkv,
                             float* __restrict__ cout) {
    __shared__ float As[32][64];  // As[k][m]
    __shared__ float Bs[32][96];
    int z = blockIdx.z;
    int b = z >> 3, h = z & 7;
    const float* abase = attn + (size_t)z * Nseq * Nseq;
    const float* vbase = qkv + (size_t)b * Nseq * 2304 + 1536 + h * Dd;
    int n0 = blockIdx.x * 64;
    int tid = threadIdx.x;
    int ty = tid >> 4, tx = tid & 15;
    int r0 = ty * 4, c0 = tx * 6;
    float acc[4][6] = {};
    for (int k0 = 0; k0 < Nseq; k0 += 32) {
#pragma unroll
        for (int i = 0; i < 8; i++) {
            int idx = tid + i * 256;
            int m = idx >> 5, kk = idx & 31;
            As[kk][m] = abase[(size_t)(n0 + m) * Nseq + k0 + kk];
        }
#pragma unroll
        for (int i = 0; i < 12; i++) {
            int idx = tid + i * 256;
            int kk = idx / 96, n = idx % 96;
            Bs[kk][n] = vbase[(size_t)(k0 + kk) * 2304 + n];
        }
        __syncthreads();
#pragma unroll
        for (int kk = 0; kk < 32; kk++) {
            float a[4], bv[6];
#pragma unroll
            for (int i = 0; i < 4; i++) a[i] = As[kk][r0 + i];
#pragma unroll
            for (int j = 0; j < 6; j++) bv[j] = Bs[kk][c0 + j];
#pragma unroll
            for (int i = 0; i < 4; i++)
#pragma unroll
                for (int j = 0; j < 6; j++) acc[i][j] += a[i] * bv[j];
        }
        __syncthreads();
    }
#pragma unroll
    for (int i = 0; i < 4; i++) {
        size_t ob = ((size_t)b * Nseq + n0 + r0 + i) * Cdim + h * Dd;
#pragma unroll
        for (int j = 0; j < 6; j++) cout[ob + c0 + j] = acc[i][j];
    }
}

// ---------------- quantum per-token pipeline (1 warp / token) ----------------
__device__ __forceinline__ void embed_warp(const float* vec, float* hid, float* ebuf,
                                           const float* __restrict__ w1, const float* __restrict__ b1,
                                           const float* __restrict__ w2, const float* __restrict__ b2,
                                           int lane, float* sre, float* sim, bool accum) {
#pragma unroll
    for (int jj = 0; jj < 2; jj++) {
        int j = lane + jj * 32;
        float a = b1[j];
        for (int d = 0; d < 96; d++) a += vec[d] * w1[d * 64 + j];
        hid[j] = fmaxf(a, 0.f);
    }
    __syncwarp();
    if (lane < 16) {
        float a = b2[lane];
        for (int t = 0; t < 64; t++) a += hid[t] * w2[t * 16 + lane];
        ebuf[lane] = a;
    }
    __syncwarp();
    if (lane < 8) {
        float mx = ebuf[0];
        for (int i = 1; i < 8; i++) mx = fmaxf(mx, ebuf[i]);
        float sum = 0.f;
        for (int i = 0; i < 8; i++) sum += expf(ebuf[i] - mx);
        float amp = expf(ebuf[lane] - mx) / sum;
        float ph = ebuf[8 + lane];
        float cr = amp * cosf(ph), ci = amp * sinf(ph);
        if (accum) { sre[lane] += cr; sim[lane] += ci; }
        else       { sre[lane] = cr;  sim[lane] = ci; }
    }
    __syncwarp();
}

__global__ void quantum_kernel(const float* __restrict__ qkv,
                               const float* __restrict__ qe_w1, const float* __restrict__ qe_b1,
                               const float* __restrict__ qe_w2, const float* __restrict__ qe_b2,
                               const float* __restrict__ ke_w1, const float* __restrict__ ke_b1,
                               const float* __restrict__ ke_w2, const float* __restrict__ ke_b2,
                               const float* __restrict__ gate_params, const float* __restrict__ ent_params,
                               const float* __restrict__ md_w1, const float* __restrict__ md_b1,
                               const float* __restrict__ md_w2, const float* __restrict__ md_b2,
                               const float* __restrict__ gumbel, float* __restrict__ qout) {
    __shared__ float vec[8][96];
    __shared__ float hid[8][64];
    __shared__ float ebuf[8][16];
    __shared__ float sre[8][8], sim[8][8], tre[8][8], tim[8][8];
    int w = threadIdx.x >> 5;
    int lane = threadIdx.x & 31;
    int wg = blockIdx.x * 8 + w;  // token id: ((b*8+h)*1024+n)
    int b = wg >> 13;
    int h = (wg >> 10) & 7;
    int n = wg & 1023;
    size_t rowoff = (size_t)(b * Nseq + n) * 2304;
    int qoff = h * Dd;

    // Q embed
    vec[w][lane]      = qkv[rowoff + qoff + lane];
    vec[w][lane + 32] = qkv[rowoff + qoff + lane + 32];
    vec[w][lane + 64] = qkv[rowoff + qoff + lane + 64];
    __syncwarp();
    embed_warp(vec[w], hid[w], ebuf[w], qe_w1, qe_b1, qe_w2, qe_b2, lane, sre[w], sim[w], false);

    // K embed (accumulate)
    vec[w][lane]      = qkv[rowoff + 768 + qoff + lane];
    vec[w][lane + 32] = qkv[rowoff + 768 + qoff + lane + 32];
    vec[w][lane + 64] = qkv[rowoff + 768 + qoff + lane + 64];
    __syncwarp();
    embed_warp(vec[w], hid[w], ebuf[w], ke_w1, ke_b1, ke_w2, ke_b2, lane, sre[w], sim[w], true);

    // variational, depth 2
#pragma unroll
    for (int layer = 0; layer < 2; layer++) {
        if (lane < 8) {
            float ry = gate_params[(layer * 8 + lane) * 3 + 1];
            float rz = gate_params[(layer * 8 + lane) * 3 + 2];
            float re = sre[w][lane], im = sim[w][lane];
            float cz = cosf(rz), sz = sinf(rz);
            float nr = re * cz - im * sz, ni = re * sz + im * cz;
            float f = cosf(0.5f * ry);
            tre[w][lane] = nr * f; tim[w][lane] = ni * f;
        }
        __syncwarp();
        if (lane < 8) {
            float ar = tre[w][lane], ai = tim[w][lane];
            if (lane > 0) {
                float s = 1.f / (1.f + expf(-ent_params[layer * 7 + lane - 1]));
                ar += s * tre[w][lane - 1];
                ai += s * tim[w][lane - 1];
            }
            sre[w][lane] = ar; sim[w][lane] = ai;
        }
        __syncwarp();
    }

    // probs softmax -> gumbel meas softmax
    if (lane < 8) ebuf[w][lane] = sre[w][lane] * sre[w][lane] + sim[w][lane] * sim[w][lane];
    __syncwarp();
    if (lane < 8) {
        float mx = ebuf[w][0];
        for (int i = 1; i < 8; i++) mx = fmaxf(mx, ebuf[w][i]);
        float sum = 0.f;
        for (int i = 0; i < 8; i++) sum += expf(ebuf[w][i] - mx);
        float prob = expf(ebuf[w][lane] - mx) / sum;
        float g = gumbel[(size_t)wg * 8 + lane];
        tre[w][lane] = 2.f * (logf(prob + 1e-10f) + g);
    }
    __syncwarp();
    if (lane < 8) {
        float mx = tre[w][0];
        for (int i = 1; i < 8; i++) mx = fmaxf(mx, tre[w][i]);
        float sum = 0.f;
        for (int i = 0; i < 8; i++) sum += expf(tre[w][i] - mx);
        ebuf[w][lane] = expf(tre[w][lane] - mx) / sum;  // meas
    }
    __syncwarp();

    // measure MLP: 8 -> 64 (relu) -> 96
#pragma unroll
    for (int jj = 0; jj < 2; jj++) {
        int j = lane + jj * 32;
        float a = md_b1[j];
        for (int i = 0; i < 8; i++) a += ebuf[w][i] * md_w1[i * 64 + j];
        hid[w][j] = fmaxf(a, 0.f);
    }
    __syncwarp();
    size_t outbase = (size_t)(b * Nseq + n) * Cdim + h * Dd;
#pragma unroll
    for (int dd = 0; dd < 3; dd++) {
        int d = lane + dd * 32;
        float a = md_b2[d];
        for (int t = 0; t < 64; t++) a += hid[w][t] * md_w2[t * 96 + d];
        float vv = qkv[rowoff + 1536 + qoff + d];
        qout[outbase + d] = a * vv;
    }
}

// ---------------- mean over N ----------------
__global__ void colmean_kernel(const float* __restrict__ x, float* __restrict__ xmean) {
    int b = blockIdx.y;
    int c = blockIdx.x * 256 + threadIdx.x;
    const float* p = x + (size_t)b * Nseq * Cdim + c;
    float s = 0.f;
    for (int n = 0; n < Nseq; n++) s += p[(size_t)n * Cdim];
    xmean[b * Cdim + c] = s * (1.0f / 1024.0f);
}

// ---------------- fw = sigmoid(xmean @ w_proj + b_proj) ----------------
__global__ void fw_kernel(const float* __restrict__ xmean, const float* __restrict__ w_proj,
                          const float* __restrict__ b_proj, float* __restrict__ fw) {
    __shared__ float xm[768];
    int b = blockIdx.x;
    int c = threadIdx.x;
    xm[c] = xmean[b * Cdim + c];
    __syncthreads();
    float s = b_proj[c];
    for (int k = 0; k < 768; k++) s += xm[k] * w_proj[(size_t)k * 768 + c];
    fw[b * Cdim + c] = 1.f / (1.f + expf(-s));
}

// ---------------- fused = fw*qout + (1-fw)*cout ----------------
__global__ void fuse_kernel(const float* __restrict__ fw, const float* __restrict__ qout,
                            const float* __restrict__ cout, float* __restrict__ fused) {
    size_t i = (size_t)blockIdx.x * 256 + threadIdx.x;
    int c = (int)(i % 768);
    int b = (int)(i / ((size_t)Nseq * Cdim));
    float f = fw[b * Cdim + c];
    fused[i] = f * qout[i] + (1.f - f) * cout[i];
}

// ---------------- layernorm ----------------
__global__ void layernorm_kernel(const float* __restrict__ y, const float* __restrict__ gamma,
                                 const float* __restrict__ beta, float* __restrict__ out) {
    __shared__ float red1[8], red2[8];
    size_t row = blockIdx.x;
    const float* p = y + row * Cdim;
    int tid = threadIdx.x;
    float v[3];
    float s = 0.f;
#pragma unroll
    for (int i = 0; i < 3; i++) { v[i] = p[tid + i * 256]; s += v[i]; }
#pragma unroll
    for (int o = 16; o > 0; o >>= 1) s += __shfl_xor_sync(~0u, s, o);
    int w = tid >> 5, lane = tid & 31;
    if (lane == 0) red1[w] = s;
    __syncthreads();
    s = 0.f;
#pragma unroll
    for (int i = 0; i < 8; i++) s += red1[i];
    float mu = s * (1.0f / 768.0f);
    float vs = 0.f;
#pragma unroll
    for (int i = 0; i < 3; i++) { float d = v[i] - mu; vs += d * d; }
#pragma unroll
    for (int o = 16; o > 0; o >>= 1) vs += __shfl_xor_sync(~0u, vs, o);
    if (lane == 0) red2[w] = vs;
    __syncthreads();
    vs = 0.f;
#pragma unroll
    for (int i = 0; i < 8; i++) vs += red2[i];
    float inv = rsqrtf(vs * (1.0f / 768.0f) + 1e-5f);
#pragma unroll
    for (int i = 0; i < 3; i++) {
        int c = tid + i * 256;
        out[row * Cdim + c] = (v[i] - mu) * inv * gamma[c] + beta[c];
    }
}

// ---------------- launch ----------------
extern "C" void kernel_launch(void* const* d_in, const int* in_sizes, int n_in,
                              void* d_out, int out_size) {
    const float* x      = (const float*)d_in[0];
    const float* w_qkv  = (const float*)d_in[1];
    const float* b_qkv  = (const float*)d_in[2];
    const float* w_proj = (const float*)d_in[3];
    const float* b_proj = (const float*)d_in[4];
    const float* gamma  = (const float*)d_in[5];
    const float* beta   = (const float*)d_in[6];
    const float* qe_w1  = (const float*)d_in[7];
    const float* qe_b1  = (const float*)d_in[8];
    const float* qe_w2  = (const float*)d_in[9];
    const float* qe_b2  = (const float*)d_in[10];
    const float* ke_w1  = (const float*)d_in[11];
    const float* ke_b1  = (const float*)d_in[12];
    const float* ke_w2  = (const float*)d_in[13];
    const float* ke_b2  = (const float*)d_in[14];
    // d_in[15..18] = ve_* : dead code in reference, skipped
    const float* gate_params = (const float*)d_in[19];
    const float* ent_params  = (const float*)d_in[20];
    const float* md_w1  = (const float*)d_in[21];
    const float* md_b1  = (const float*)d_in[22];
    const float* md_w2  = (const float*)d_in[23];
    const float* md_b2  = (const float*)d_in[24];
    const float* gumbel = (const float*)d_in[25];
    float* out = (float*)d_out;

    float *qkv, *attn, *qout, *cout, *fused, *xmean, *fw;
    cudaGetSymbolAddress((void**)&qkv, g_qkv);
    cudaGetSymbolAddress((void**)&attn, g_attn);
    cudaGetSymbolAddress((void**)&qout, g_qout);
    cudaGetSymbolAddress((void**)&cout, g_cout);
    cudaGetSymbolAddress((void**)&fused, g_fused);
    cudaGetSymbolAddress((void**)&xmean, g_xmean);
    cudaGetSymbolAddress((void**)&fw, g_fw);

    // 1. qkv = x @ w_qkv + b_qkv   (8192 x 2304 x 768)
    gemm_nn_kernel<<<dim3(2304 / 64, 8192 / 128), 256>>>(x, w_qkv, b_qkv, nullptr, qkv,
                                                         8192, 2304, 768, 768, 2304, 2304);
    // 2. quantum path -> qout (attn_w * v, already (B,N,C) layout)
    quantum_kernel<<<8192, 256>>>(qkv, qe_w1, qe_b1, qe_w2, qe_b2,
                                  ke_w1, ke_b1, ke_w2, ke_b2,
                                  gate_params, ent_params,
                                  md_w1, md_b1, md_w2, md_b2, gumbel, qout);
    // 3. scores  4. softmax  5. attn@v -> cout
    scores_kernel<<<dim3(1024 / 64, 1024 / 128, 64), 256>>>(qkv, attn);
    softmax_rows<<<65536, 256>>>(attn);
    attnv_kernel<<<dim3(1024 / 64, 1, 64), 256>>>(attn, qkv, cout);
    // 6-7. gate
    colmean_kernel<<<dim3(3, 8), 256>>>(x, xmean);
    fw_kernel<<<8, 768>>>(xmean, w_proj, b_proj, fw);
    // 8. fuse
    fuse_kernel<<<(8192 * 768) / 256, 256>>>(fw, qout, cout, fused);
    // 9. y = x + fused @ w_proj + b_proj  (reuse qout as y)
    gemm_nn_kernel<<<dim3(768 / 64, 8192 / 128), 256>>>(fused, w_proj, b_proj, x, qout,
                                                        8192, 768, 768, 768, 768, 768);
    // 10. layernorm
    layernorm_kernel<<<8192, 256>>>(qout, gamma, beta, out);
}

// round 2
// speedup vs baseline: 1.4739x; 1.4739x over previous
#include <cuda_runtime.h>
#include <math.h>

// ---------------- scratch ----------------
#define Bsz 8
#define Nseq 1024
#define Cdim 768
#define Hh 8
#define Dd 96
#define Qq 8

__device__ float g_qkv[Bsz * Nseq * 3 * Cdim];
__device__ float g_attn[(size_t)Bsz * Hh * Nseq * Nseq];
__device__ float g_qout[Bsz * Nseq * Cdim];
__device__ float g_fused[Bsz * Nseq * Cdim];
__device__ float g_xmean[Bsz * Cdim];
__device__ float g_fw[Bsz * Cdim];

// ================= 128x128x8 double-buffered SGEMM (NN) =================
// C = A@B (+bias) (+resid). M%128==0, N%128==0, K%8==0, lda%4==0, ldb%4==0.
__global__ __launch_bounds__(256, 2)
void gemm_nn128(const float* __restrict__ A, const float* __restrict__ B,
                const float* __restrict__ bias, const float* __restrict__ resid,
                float* __restrict__ C, int M, int N, int K,
                int lda, int ldb, int ldc) {
    __shared__ float As[2][8][128];
    __shared__ float Bs[2][8][128];
    int tid = threadIdx.x;
    int m0 = blockIdx.y * 128, n0 = blockIdx.x * 128;
    int arow = tid >> 1, apart = tid & 1;
    int bcol = (tid & 31) * 4, bkk = tid >> 5;
    const float* Aptr = A + (size_t)(m0 + arow) * lda + apart * 4;
    const float* Bptr = B + (size_t)bkk * ldb + n0 + bcol;
    int ty = tid >> 4, tx = tid & 15;
    float acc[8][8] = {};

    float4 av = *(const float4*)Aptr;
    float4 bv = *(const float4*)Bptr;
    As[0][apart * 4 + 0][arow] = av.x;
    As[0][apart * 4 + 1][arow] = av.y;
    As[0][apart * 4 + 2][arow] = av.z;
    As[0][apart * 4 + 3][arow] = av.w;
    *(float4*)&Bs[0][bkk][bcol] = bv;
    __syncthreads();

    int buf = 0;
    for (int k0 = 8; k0 <= K; k0 += 8) {
        bool more = (k0 < K);
        if (more) {
            av = *(const float4*)(Aptr + k0);
            bv = *(const float4*)(Bptr + (size_t)k0 * ldb);
        }
#pragma unroll
        for (int kk = 0; kk < 8; kk++) {
            float4 a0 = *(float4*)&As[buf][kk][ty * 8];
            float4 a1 = *(float4*)&As[buf][kk][ty * 8 + 4];
            float4 b0 = *(float4*)&Bs[buf][kk][tx * 8];
            float4 b1 = *(float4*)&Bs[buf][kk][tx * 8 + 4];
            float a[8] = {a0.x, a0.y, a0.z, a0.w, a1.x, a1.y, a1.z, a1.w};
            float b[8] = {b0.x, b0.y, b0.z, b0.w, b1.x, b1.y, b1.z, b1.w};
#pragma unroll
            for (int i = 0; i < 8; i++)
#pragma unroll
                for (int j = 0; j < 8; j++) acc[i][j] += a[i] * b[j];
        }
        if (more) {
            As[buf ^ 1][apart * 4 + 0][arow] = av.x;
            As[buf ^ 1][apart * 4 + 1][arow] = av.y;
            As[buf ^ 1][apart * 4 + 2][arow] = av.z;
            As[buf ^ 1][apart * 4 + 3][arow] = av.w;
            *(float4*)&Bs[buf ^ 1][bkk][bcol] = bv;
            __syncthreads();
            buf ^= 1;
        }
    }

    float4 bias0 = make_float4(0.f, 0.f, 0.f, 0.f), bias1 = bias0;
    if (bias) {
        bias0 = *(const float4*)(bias + n0 + tx * 8);
        bias1 = *(const float4*)(bias + n0 + tx * 8 + 4);
    }
#pragma unroll
    for (int i = 0; i < 8; i++) {
        size_t row = m0 + ty * 8 + i;
        float* cp = C + row * ldc + n0 + tx * 8;
        float4 r0 = make_float4(acc[i][0] + bias0.x, acc[i][1] + bias0.y,
                                acc[i][2] + bias0.z, acc[i][3] + bias0.w);
        float4 r1 = make_float4(acc[i][4] + bias1.x, acc[i][5] + bias1.y,
                                acc[i][6] + bias1.z, acc[i][7] + bias1.w);
        if (resid) {
            const float* rp = resid + row * ldc + n0 + tx * 8;
            float4 x0 = *(const float4*)rp;
            float4 x1 = *(const float4*)(rp + 4);
            r0.x += x0.x; r0.y += x0.y; r0.z += x0.z; r0.w += x0.w;
            r1.x += x1.x; r1.y += x1.y; r1.z += x1.z; r1.w += x1.w;
        }
        *(float4*)cp = r0;
        *(float4*)(cp + 4) = r1;
    }
}

// ================= scores (NT): attn = scale * Q @ K^T, 128x128x8 =================
__global__ __launch_bounds__(256, 2)
void scores_kernel(const float* __restrict__ qkv, float* __restrict__ attn) {
    __shared__ float As[2][8][128];
    __shared__ float Bs[2][8][128];
    int z = blockIdx.z;
    int b = z >> 3, h = z & 7;
    const float* qbase = qkv + (size_t)b * Nseq * 2304 + h * Dd;
    const float* kbase = qbase + 768;
    float* cbase = attn + (size_t)z * Nseq * Nseq;
    int tid = threadIdx.x;
    int n0 = blockIdx.y * 128;  // q rows
    int m0 = blockIdx.x * 128;  // k rows
    int row = tid >> 1, part = tid & 1;
    const float* Aptr = qbase + (size_t)(n0 + row) * 2304 + part * 4;
    const float* Bptr = kbase + (size_t)(m0 + row) * 2304 + part * 4;
    int ty = tid >> 4, tx = tid & 15;
    float acc[8][8] = {};

    float4 av = *(const float4*)Aptr;
    float4 bv = *(const float4*)Bptr;
    As[0][part * 4 + 0][row] = av.x; As[0][part * 4 + 1][row] = av.y;
    As[0][part * 4 + 2][row] = av.z; As[0][part * 4 + 3][row] = av.w;
    Bs[0][part * 4 + 0][row] = bv.x; Bs[0][part * 4 + 1][row] = bv.y;
    Bs[0][part * 4 + 2][row] = bv.z; Bs[0][part * 4 + 3][row] = bv.w;
    __syncthreads();

    int buf = 0;
    for (int k0 = 8; k0 <= Dd; k0 += 8) {
        bool more = (k0 < Dd);
        if (more) {
            av = *(const float4*)(Aptr + k0);
            bv = *(const float4*)(Bptr + k0);
        }
#pragma unroll
        for (int kk = 0; kk < 8; kk++) {
            float4 a0 = *(float4*)&As[buf][kk][ty * 8];
            float4 a1 = *(float4*)&As[buf][kk][ty * 8 + 4];
            float4 b0 = *(float4*)&Bs[buf][kk][tx * 8];
            float4 b1 = *(float4*)&Bs[buf][kk][tx * 8 + 4];
            float a[8] = {a0.x, a0.y, a0.z, a0.w, a1.x, a1.y, a1.z, a1.w};
            float b[8] = {b0.x, b0.y, b0.z, b0.w, b1.x, b1.y, b1.z, b1.w};
#pragma unroll
            for (int i = 0; i < 8; i++)
#pragma unroll
                for (int j = 0; j < 8; j++) acc[i][j] += a[i] * b[j];
        }
        if (more) {
            As[buf ^ 1][part * 4 + 0][row] = av.x; As[buf ^ 1][part * 4 + 1][row] = av.y;
            As[buf ^ 1][part * 4 + 2][row] = av.z; As[buf ^ 1][part * 4 + 3][row] = av.w;
            Bs[buf ^ 1][part * 4 + 0][row] = bv.x; Bs[buf ^ 1][part * 4 + 1][row] = bv.y;
            Bs[buf ^ 1][part * 4 + 2][row] = bv.z; Bs[buf ^ 1][part * 4 + 3][row] = bv.w;
            __syncthreads();
            buf ^= 1;
        }
    }
    const float scale = 0.10206207261596577f;  // 96^-0.5
#pragma unroll
    for (int i = 0; i < 8; i++) {
        float* cp = cbase + (size_t)(n0 + ty * 8 + i) * Nseq + m0 + tx * 8;
        float4 r0 = make_float4(acc[i][0] * scale, acc[i][1] * scale,
                                acc[i][2] * scale, acc[i][3] * scale);
        float4 r1 = make_float4(acc[i][4] * scale, acc[i][5] * scale,
                                acc[i][6] * scale, acc[i][7] * scale);
        *(float4*)cp = r0;
        *(float4*)(cp + 4) = r1;
    }
}

// ================= row softmax over 1024 (float4) =================
__global__ void softmax_rows(float* __restrict__ attn) {
    __shared__ float redm[8], reds[8];
    size_t row = blockIdx.x;
    float4* p = (float4*)(attn + row * Nseq);
    int tid = threadIdx.x;
    float4 v = p[tid];
    float mx = fmaxf(fmaxf(v.x, v.y), fmaxf(v.z, v.w));
#pragma unroll
    for (int o = 16; o > 0; o >>= 1) mx = fmaxf(mx, __shfl_xor_sync(~0u, mx, o));
    int w = tid >> 5, lane = tid & 31;
    if (lane == 0) redm[w] = mx;
    __syncthreads();
    mx = redm[0];
#pragma unroll
    for (int i = 1; i < 8; i++) mx = fmaxf(mx, redm[i]);
    v.x = expf(v.x - mx); v.y = expf(v.y - mx);
    v.z = expf(v.z - mx); v.w = expf(v.w - mx);
    float sum = v.x + v.y + v.z + v.w;
#pragma unroll
    for (int o = 16; o > 0; o >>= 1) sum += __shfl_xor_sync(~0u, sum, o);
    if (lane == 0) reds[w] = sum;
    __syncthreads();
    sum = 0.f;
#pragma unroll
    for (int i = 0; i < 8; i++) sum += reds[i];
    float inv = 1.f / sum;
    v.x *= inv; v.y *= inv; v.z *= inv; v.w *= inv;
    p[tid] = v;
}

// ================= attn @ v with fused gate blend =================
// fused[b,n,h*96+c] = fw*qout + (1-fw)*(attn@v)
__global__ __launch_bounds__(256, 2)
void attnv_kernel(const float* __restrict__ attn, const float* __restrict__ qkv,
                  const float* __restrict__ qout, const float* __restrict__ fw,
                  float* __restrict__ fused) {
    __shared__ float As[2][8][128];
    __shared__ float Bs[2][8][96];
    int z = blockIdx.z;
    int b = z >> 3, h = z & 7;
    const float* abase = attn + (size_t)z * Nseq * Nseq;
    const float* vbase = qkv + (size_t)b * Nseq * 2304 + 1536 + h * Dd;
    int n0 = blockIdx.x * 128;
    int tid = threadIdx.x;
    int arow = tid >> 1, apart = tid & 1;
    const float* Aptr = abase + (size_t)(n0 + arow) * Nseq + apart * 4;
    int bi0 = tid, bi1 = tid + 256, bi2 = tid + 512;
    int bk0 = bi0 / 96, bn0 = bi0 % 96;
    int bk1 = bi1 / 96, bn1 = bi1 % 96;
    int bk2 = bi2 / 96, bn2 = bi2 % 96;
    int ty = tid >> 4, tx = tid & 15;
    float acc[8][6] = {};

    float4 av = *(const float4*)Aptr;
    float b0 = vbase[(size_t)bk0 * 2304 + bn0];
    float b1 = vbase[(size_t)bk1 * 2304 + bn1];
    float b2 = vbase[(size_t)bk2 * 2304 + bn2];
    As[0][apart * 4 + 0][arow] = av.x; As[0][apart * 4 + 1][arow] = av.y;
    As[0][apart * 4 + 2][arow] = av.z; As[0][apart * 4 + 3][arow] = av.w;
    Bs[0][bk0][bn0] = b0; Bs[0][bk1][bn1] = b1; Bs[0][bk2][bn2] = b2;
    __syncthreads();

    int buf = 0;
    for (int k0 = 8; k0 <= Nseq; k0 += 8) {
        bool more = (k0 < Nseq);
        if (more) {
            av = *(const float4*)(Aptr + k0);
            b0 = vbase[(size_t)(k0 + bk0) * 2304 + bn0];
            b1 = vbase[(size_t)(k0 + bk1) * 2304 + bn1];
            b2 = vbase[(size_t)(k0 + bk2) * 2304 + bn2];
        }
#pragma unroll
        for (int kk = 0; kk < 8; kk++) {
            float4 a0 = *(float4*)&As[buf][kk][ty * 8];
            float4 a1 = *(float4*)&As[buf][kk][ty * 8 + 4];
            float a[8] = {a0.x, a0.y, a0.z, a0.w, a1.x, a1.y, a1.z, a1.w};
            float bb[6];
#pragma unroll
            for (int j = 0; j < 6; j++) bb[j] = Bs[buf][kk][tx * 6 + j];
#pragma unroll
            for (int i = 0; i < 8; i++)
#pragma unroll
                for (int j = 0; j < 6; j++) acc[i][j] += a[i] * bb[j];
        }
        if (more) {
            As[buf ^ 1][apart * 4 + 0][arow] = av.x; As[buf ^ 1][apart * 4 + 1][arow] = av.y;
            As[buf ^ 1][apart * 4 + 2][arow] = av.z; As[buf ^ 1][apart * 4 + 3][arow] = av.w;
            Bs[buf ^ 1][bk0][bn0] = b0; Bs[buf ^ 1][bk1][bn1] = b1; Bs[buf ^ 1][bk2][bn2] = b2;
            __syncthreads();
            buf ^= 1;
        }
    }

    float f[6];
#pragma unroll
    for (int j = 0; j < 6; j++) f[j] = fw[b * Cdim + h * Dd + tx * 6 + j];
#pragma unroll
    for (int i = 0; i < 8; i++) {
        size_t ob = ((size_t)b * Nseq + n0 + ty * 8 + i) * Cdim + h * Dd + tx * 6;
#pragma unroll
        for (int j = 0; j < 6; j++)
            fused[ob + j] = f[j] * qout[ob + j] + (1.f - f[j]) * acc[i][j];
    }
}

// ================= quantum per-token pipeline (1 warp / token) =================
__device__ __forceinline__ void embed_warp(const float* vec, float* hid, float* ebuf,
                                           const float* __restrict__ w1, const float* __restrict__ b1,
                                           const float* __restrict__ w2, const float* __restrict__ b2,
                                           int lane, float* sre, float* sim, bool accum) {
#pragma unroll
    for (int jj = 0; jj < 2; jj++) {
        int j = lane + jj * 32;
        float a = b1[j];
        for (int d = 0; d < 96; d++) a += vec[d] * w1[d * 64 + j];
        hid[j] = fmaxf(a, 0.f);
    }
    __syncwarp();
    if (lane < 16) {
        float a = b2[lane];
        for (int t = 0; t < 64; t++) a += hid[t] * w2[t * 16 + lane];
        ebuf[lane] = a;
    }
    __syncwarp();
    if (lane < 8) {
        float mx = ebuf[0];
        for (int i = 1; i < 8; i++) mx = fmaxf(mx, ebuf[i]);
        float sum = 0.f;
        for (int i = 0; i < 8; i++) sum += expf(ebuf[i] - mx);
        float amp = expf(ebuf[lane] - mx) / sum;
        float ph = ebuf[8 + lane];
        float cr = amp * cosf(ph), ci = amp * sinf(ph);
        if (accum) { sre[lane] += cr; sim[lane] += ci; }
        else       { sre[lane] = cr;  sim[lane] = ci; }
    }
    __syncwarp();
}

__global__ void quantum_kernel(const float* __restrict__ qkv,
                               const float* __restrict__ qe_w1, const float* __restrict__ qe_b1,
                               const float* __restrict__ qe_w2, const float* __restrict__ qe_b2,
                               const float* __restrict__ ke_w1, const float* __restrict__ ke_b1,
                               const float* __restrict__ ke_w2, const float* __restrict__ ke_b2,
                               const float* __restrict__ gate_params, const float* __restrict__ ent_params,
                               const float* __restrict__ md_w1, const float* __restrict__ md_b1,
                               const float* __restrict__ md_w2, const float* __restrict__ md_b2,
                               const float* __restrict__ gumbel, float* __restrict__ qout) {
    __shared__ float vec[8][96];
    __shared__ float hid[8][64];
    __shared__ float ebuf[8][16];
    __shared__ float sre[8][8], sim[8][8], tre[8][8], tim[8][8];
    int w = threadIdx.x >> 5;
    int lane = threadIdx.x & 31;
    int wg = blockIdx.x * 8 + w;
    int b = wg >> 13;
    int h = (wg >> 10) & 7;
    int n = wg & 1023;
    size_t rowoff = (size_t)(b * Nseq + n) * 2304;
    int qoff = h * Dd;

    vec[w][lane]      = qkv[rowoff + qoff + lane];
    vec[w][lane + 32] = qkv[rowoff + qoff + lane + 32];
    vec[w][lane + 64] = qkv[rowoff + qoff + lane + 64];
    __syncwarp();
    embed_warp(vec[w], hid[w], ebuf[w], qe_w1, qe_b1, qe_w2, qe_b2, lane, sre[w], sim[w], false);

    vec[w][lane]      = qkv[rowoff + 768 + qoff + lane];
    vec[w][lane + 32] = qkv[rowoff + 768 + qoff + lane + 32];
    vec[w][lane + 64] = qkv[rowoff + 768 + qoff + lane + 64];
    __syncwarp();
    embed_warp(vec[w], hid[w], ebuf[w], ke_w1, ke_b1, ke_w2, ke_b2, lane, sre[w], sim[w], true);

#pragma unroll
    for (int layer = 0; layer < 2; layer++) {
        if (lane < 8) {
            float ry = gate_params[(layer * 8 + lane) * 3 + 1];
            float rz = gate_params[(layer * 8 + lane) * 3 + 2];
            float re = sre[w][lane], im = sim[w][lane];
            float cz = cosf(rz), sz = sinf(rz);
            float nr = re * cz - im * sz, ni = re * sz + im * cz;
            float f = cosf(0.5f * ry);
            tre[w][lane] = nr * f; tim[w][lane] = ni * f;
        }
        __syncwarp();
        if (lane < 8) {
            float ar = tre[w][lane], ai = tim[w][lane];
            if (lane > 0) {
                float s = 1.f / (1.f + expf(-ent_params[layer * 7 + lane - 1]));
                ar += s * tre[w][lane - 1];
                ai += s * tim[w][lane - 1];
            }
            sre[w][lane] = ar; sim[w][lane] = ai;
        }
        __syncwarp();
    }

    if (lane < 8) ebuf[w][lane] = sre[w][lane] * sre[w][lane] + sim[w][lane] * sim[w][lane];
    __syncwarp();
    if (lane < 8) {
        float mx = ebuf[w][0];
        for (int i = 1; i < 8; i++) mx = fmaxf(mx, ebuf[w][i]);
        float sum = 0.f;
        for (int i = 0; i < 8; i++) sum += expf(ebuf[w][i] - mx);
        float prob = expf(ebuf[w][lane] - mx) / sum;
        float g = gumbel[(size_t)wg * 8 + lane];
        tre[w][lane] = 2.f * (logf(prob + 1e-10f) + g);
    }
    __syncwarp();
    if (lane < 8) {
        float mx = tre[w][0];
        for (int i = 1; i < 8; i++) mx = fmaxf(mx, tre[w][i]);
        float sum = 0.f;
        for (int i = 0; i < 8; i++) sum += expf(tre[w][i] - mx);
        ebuf[w][lane] = expf(tre[w][lane] - mx) / sum;
    }
    __syncwarp();

#pragma unroll
    for (int jj = 0; jj < 2; jj++) {
        int j = lane + jj * 32;
        float a = md_b1[j];
        for (int i = 0; i < 8; i++) a += ebuf[w][i] * md_w1[i * 64 + j];
        hid[w][j] = fmaxf(a, 0.f);
    }
    __syncwarp();
    size_t outbase = (size_t)(b * Nseq + n) * Cdim + h * Dd;
#pragma unroll
    for (int dd = 0; dd < 3; dd++) {
        int d = lane + dd * 32;
        float a = md_b2[d];
        for (int t = 0; t < 64; t++) a += hid[w][t] * md_w2[t * 96 + d];
        float vv = qkv[rowoff + 1536 + qoff + d];
        qout[outbase + d] = a * vv;
    }
}

// ================= mean over N =================
__global__ void colmean_kernel(const float* __restrict__ x, float* __restrict__ xmean) {
    int b = blockIdx.y;
    int c = blockIdx.x * 256 + threadIdx.x;
    const float* p = x + (size_t)b * Nseq * Cdim + c;
    float s = 0.f;
    for (int n = 0; n < Nseq; n++) s += p[(size_t)n * Cdim];
    xmean[b * Cdim + c] = s * (1.0f / 1024.0f);
}

// ================= fw = sigmoid(xmean @ w_proj + b_proj) =================
__global__ void fw_kernel(const float* __restrict__ xmean, const float* __restrict__ w_proj,
                          const float* __restrict__ b_proj, float* __restrict__ fw) {
    __shared__ float xm[768];
    int b = blockIdx.x;
    int c = threadIdx.x;
    xm[c] = xmean[b * Cdim + c];
    __syncthreads();
    float s = b_proj[c];
    for (int k = 0; k < 768; k++) s += xm[k] * w_proj[(size_t)k * 768 + c];
    fw[b * Cdim + c] = 1.f / (1.f + expf(-s));
}

// ================= layernorm =================
__global__ void layernorm_kernel(const float* __restrict__ y, const float* __restrict__ gamma,
                                 const float* __restrict__ beta, float* __restrict__ out) {
    __shared__ float red1[8], red2[8];
    size_t row = blockIdx.x;
    const float* p = y + row * Cdim;
    int tid = threadIdx.x;
    float v[3];
    float s = 0.f;
#pragma unroll
    for (int i = 0; i < 3; i++) { v[i] = p[tid + i * 256]; s += v[i]; }
#pragma unroll
    for (int o = 16; o > 0; o >>= 1) s += __shfl_xor_sync(~0u, s, o);
    int w = tid >> 5, lane = tid & 31;
    if (lane == 0) red1[w] = s;
    __syncthreads();
    s = 0.f;
#pragma unroll
    for (int i = 0; i < 8; i++) s += red1[i];
    float mu = s * (1.0f / 768.0f);
    float vs = 0.f;
#pragma unroll
    for (int i = 0; i < 3; i++) { float d = v[i] - mu; vs += d * d; }
#pragma unroll
    for (int o = 16; o > 0; o >>= 1) vs += __shfl_xor_sync(~0u, vs, o);
    if (lane == 0) red2[w] = vs;
    __syncthreads();
    vs = 0.f;
#pragma unroll
    for (int i = 0; i < 8; i++) vs += red2[i];
    float inv = rsqrtf(vs * (1.0f / 768.0f) + 1e-5f);
#pragma unroll
    for (int i = 0; i < 3; i++) {
        int c = tid + i * 256;
        out[row * Cdim + c] = (v[i] - mu) * inv * gamma[c] + beta[c];
    }
}

// ================= launch =================
extern "C" void kernel_launch(void* const* d_in, const int* in_sizes, int n_in,
                              void* d_out, int out_size) {
    const float* x      = (const float*)d_in[0];
    const float* w_qkv  = (const float*)d_in[1];
    const float* b_qkv  = (const float*)d_in[2];
    const float* w_proj = (const float*)d_in[3];
    const float* b_proj = (const float*)d_in[4];
    const float* gamma  = (const float*)d_in[5];
    const float* beta   = (const float*)d_in[6];
    const float* qe_w1  = (const float*)d_in[7];
    const float* qe_b1  = (const float*)d_in[8];
    const float* qe_w2  = (const float*)d_in[9];
    const float* qe_b2  = (const float*)d_in[10];
    const float* ke_w1  = (const float*)d_in[11];
    const float* ke_b1  = (const float*)d_in[12];
    const float* ke_w2  = (const float*)d_in[13];
    const float* ke_b2  = (const float*)d_in[14];
    const float* gate_params = (const float*)d_in[19];
    const float* ent_params  = (const float*)d_in[20];
    const float* md_w1  = (const float*)d_in[21];
    const float* md_b1  = (const float*)d_in[22];
    const float* md_w2  = (const float*)d_in[23];
    const float* md_b2  = (const float*)d_in[24];
    const float* gumbel = (const float*)d_in[25];
    float* out = (float*)d_out;

    float *qkv, *attn, *qout, *fused, *xmean, *fw;
    cudaGetSymbolAddress((void**)&qkv, g_qkv);
    cudaGetSymbolAddress((void**)&attn, g_attn);
    cudaGetSymbolAddress((void**)&qout, g_qout);
    cudaGetSymbolAddress((void**)&fused, g_fused);
    cudaGetSymbolAddress((void**)&xmean, g_xmean);
    cudaGetSymbolAddress((void**)&fw, g_fw);

    // gate path (depends only on x)
    colmean_kernel<<<dim3(3, 8), 256>>>(x, xmean);
    fw_kernel<<<8, 768>>>(xmean, w_proj, b_proj, fw);
    // qkv = x @ w_qkv + b_qkv   (8192 x 2304 x 768)
    gemm_nn128<<<dim3(2304 / 128, 8192 / 128), 256>>>(x, w_qkv, b_qkv, nullptr, qkv,
                                                      8192, 2304, 768, 768, 2304, 2304);
    // quantum path -> qout
    quantum_kernel<<<8192, 256>>>(qkv, qe_w1, qe_b1, qe_w2, qe_b2,
                                  ke_w1, ke_b1, ke_w2, ke_b2,
                                  gate_params, ent_params,
                                  md_w1, md_b1, md_w2, md_b2, gumbel, qout);
    // classical attention
    scores_kernel<<<dim3(1024 / 128, 1024 / 128, 64), 256>>>(qkv, attn);
    softmax_rows<<<65536, 256>>>(attn);
    attnv_kernel<<<dim3(1024 / 128, 1, 64), 256>>>(attn, qkv, qout, fw, fused);
    // y = x + fused @ w_proj + b_proj  (reuse qout as y)
    gemm_nn128<<<dim3(768 / 128, 8192 / 128), 256>>>(fused, w_proj, b_proj, x, qout,
                                                     8192, 768, 768, 768, 768, 768);
    // layernorm
    layernorm_kernel<<<8192, 256>>>(qout, gamma, beta, out);
}

// round 3
// speedup vs baseline: 2.4828x; 1.6845x over previous
#include <cuda_runtime.h>
#include <math.h>
#include <stdint.h>

// ---------------- scratch ----------------
#define Bsz 8
#define Nseq 1024
#define Cdim 768
#define Hh 8
#define Dd 96
#define Qq 8

__device__ float g_qkv[Bsz * Nseq * 3 * Cdim];
__device__ float g_attn[(size_t)Bsz * Hh * Nseq * Nseq];
__device__ float g_qout[Bsz * Nseq * Cdim];
__device__ float g_fused[Bsz * Nseq * Cdim];
__device__ float g_xmean[Bsz * Cdim];
__device__ float g_fw[Bsz * Cdim];

// ---------------- tf32 mma helpers ----------------
__device__ __forceinline__ float to_tf32(float x) {
    uint32_t u;
    asm("cvt.rna.tf32.f32 %0, %1;" : "=r"(u) : "f"(x));
    return __uint_as_float(u);
}

__device__ __forceinline__ void mma_tf32(float* c, const uint32_t* a, const uint32_t* b) {
    asm volatile(
        "mma.sync.aligned.m16n8k8.row.col.f32.tf32.tf32.f32 "
        "{%0,%1,%2,%3}, {%4,%5,%6,%7}, {%8,%9}, {%0,%1,%2,%3};"
        : "+f"(c[0]), "+f"(c[1]), "+f"(c[2]), "+f"(c[3])
        : "r"(a[0]), "r"(a[1]), "r"(a[2]), "r"(a[3]), "r"(b[0]), "r"(b[1]));
}

// ================= tf32 MMA GEMM (NN): C = A@B (+bias)(+resid) =================
// BM=128, BN=128, BK=8. 256 threads = 8 warps (2x4), warp tile 64x32.
__global__ __launch_bounds__(256)
void mma_nn(const float* __restrict__ A, const float* __restrict__ B,
            const float* __restrict__ bias, const float* __restrict__ resid,
            float* __restrict__ C, int K, int lda, int ldb, int ldc) {
    __shared__ float As[2][8][136];
    __shared__ float Bs[2][8][136];
    int tid = threadIdx.x;
    int m0 = blockIdx.y * 128, n0 = blockIdx.x * 128;
    int arow = tid >> 1, ak = (tid & 1) * 4;
    int bk = tid >> 5, bcol = (tid & 31) * 4;
    const float* Ap = A + (size_t)(m0 + arow) * lda + ak;
    const float* Bp = B + (size_t)bk * ldb + n0 + bcol;

    int wid = tid >> 5, lane = tid & 31;
    int wm = (wid >> 2) * 64, wn = (wid & 3) * 32;
    int grp = lane >> 2, tig = lane & 3;
    float acc[4][4][4] = {};

    {
        float4 av = *(const float4*)Ap;
        float4 bv = *(const float4*)Bp;
        As[0][ak + 0][arow] = to_tf32(av.x); As[0][ak + 1][arow] = to_tf32(av.y);
        As[0][ak + 2][arow] = to_tf32(av.z); As[0][ak + 3][arow] = to_tf32(av.w);
        float4 bc = make_float4(to_tf32(bv.x), to_tf32(bv.y), to_tf32(bv.z), to_tf32(bv.w));
        *(float4*)&Bs[0][bk][bcol] = bc;
    }
    __syncthreads();

    int S = K / 8, buf = 0;
    for (int s = 1; s <= S; s++) {
        bool more = (s < S);
        float4 av, bv;
        if (more) {
            av = *(const float4*)(Ap + s * 8);
            bv = *(const float4*)(Bp + (size_t)s * 8 * ldb);
        }
        uint32_t a[4][4], b[4][2];
#pragma unroll
        for (int mi = 0; mi < 4; mi++) {
            int r = wm + mi * 16 + grp;
            a[mi][0] = __float_as_uint(As[buf][tig][r]);
            a[mi][1] = __float_as_uint(As[buf][tig][r + 8]);
            a[mi][2] = __float_as_uint(As[buf][tig + 4][r]);
            a[mi][3] = __float_as_uint(As[buf][tig + 4][r + 8]);
        }
#pragma unroll
        for (int nj = 0; nj < 4; nj++) {
            int c = wn + nj * 8 + grp;
            b[nj][0] = __float_as_uint(Bs[buf][tig][c]);
            b[nj][1] = __float_as_uint(Bs[buf][tig + 4][c]);
        }
#pragma unroll
        for (int mi = 0; mi < 4; mi++)
#pragma unroll
            for (int nj = 0; nj < 4; nj++) mma_tf32(acc[mi][nj], a[mi], b[nj]);
        if (more) {
            As[buf ^ 1][ak + 0][arow] = to_tf32(av.x); As[buf ^ 1][ak + 1][arow] = to_tf32(av.y);
            As[buf ^ 1][ak + 2][arow] = to_tf32(av.z); As[buf ^ 1][ak + 3][arow] = to_tf32(av.w);
            float4 bc = make_float4(to_tf32(bv.x), to_tf32(bv.y), to_tf32(bv.z), to_tf32(bv.w));
            *(float4*)&Bs[buf ^ 1][bk][bcol] = bc;
            __syncthreads();
            buf ^= 1;
        }
    }

#pragma unroll
    for (int nj = 0; nj < 4; nj++) {
        int c = n0 + wn + nj * 8 + tig * 2;
        float bi0 = bias ? bias[c] : 0.f;
        float bi1 = bias ? bias[c + 1] : 0.f;
#pragma unroll
        for (int mi = 0; mi < 4; mi++) {
            size_t r = m0 + wm + mi * 16 + grp;
            float2 lo = make_float2(acc[mi][nj][0] + bi0, acc[mi][nj][1] + bi1);
            float2 hi = make_float2(acc[mi][nj][2] + bi0, acc[mi][nj][3] + bi1);
            if (resid) {
                float2 r0 = *(const float2*)(resid + r * ldc + c);
                float2 r1 = *(const float2*)(resid + (r + 8) * ldc + c);
                lo.x += r0.x; lo.y += r0.y; hi.x += r1.x; hi.y += r1.y;
            }
            *(float2*)(C + r * ldc + c) = lo;
            *(float2*)(C + (r + 8) * ldc + c) = hi;
        }
    }
}

// ================= tf32 MMA scores (NT): attn = scale * Q @ K^T =================
__global__ __launch_bounds__(256)
void mma_scores(const float* __restrict__ qkv, float* __restrict__ attn) {
    __shared__ float As[2][8][136];
    __shared__ float Bs[2][8][136];
    int z = blockIdx.z;
    int b = z >> 3, h = z & 7;
    const float* qbase = qkv + (size_t)b * Nseq * 2304 + h * Dd;
    const float* kbase = qbase + 768;
    float* cbase = attn + (size_t)z * Nseq * Nseq;
    int tid = threadIdx.x;
    int n0 = blockIdx.y * 128;  // q rows
    int m0 = blockIdx.x * 128;  // k rows
    int arow = tid >> 1, ak = (tid & 1) * 4;
    const float* Ap = qbase + (size_t)(n0 + arow) * 2304 + ak;
    const float* Bp = kbase + (size_t)(m0 + arow) * 2304 + ak;

    int wid = tid >> 5, lane = tid & 31;
    int wm = (wid >> 2) * 64, wn = (wid & 3) * 32;
    int grp = lane >> 2, tig = lane & 3;
    float acc[4][4][4] = {};

    {
        float4 av = *(const float4*)Ap;
        float4 bv = *(const float4*)Bp;
        As[0][ak + 0][arow] = to_tf32(av.x); As[0][ak + 1][arow] = to_tf32(av.y);
        As[0][ak + 2][arow] = to_tf32(av.z); As[0][ak + 3][arow] = to_tf32(av.w);
        Bs[0][ak + 0][arow] = to_tf32(bv.x); Bs[0][ak + 1][arow] = to_tf32(bv.y);
        Bs[0][ak + 2][arow] = to_tf32(bv.z); Bs[0][ak + 3][arow] = to_tf32(bv.w);
    }
    __syncthreads();

    int S = Dd / 8, buf = 0;
    for (int s = 1; s <= S; s++) {
        bool more = (s < S);
        float4 av, bv;
        if (more) {
            av = *(const float4*)(Ap + s * 8);
            bv = *(const float4*)(Bp + s * 8);
        }
        uint32_t a[4][4], b[4][2];
#pragma unroll
        for (int mi = 0; mi < 4; mi++) {
            int r = wm + mi * 16 + grp;
            a[mi][0] = __float_as_uint(As[buf][tig][r]);
            a[mi][1] = __float_as_uint(As[buf][tig][r + 8]);
            a[mi][2] = __float_as_uint(As[buf][tig + 4][r]);
            a[mi][3] = __float_as_uint(As[buf][tig + 4][r + 8]);
        }
#pragma unroll
        for (int nj = 0; nj < 4; nj++) {
            int c = wn + nj * 8 + grp;
            b[nj][0] = __float_as_uint(Bs[buf][tig][c]);
            b[nj][1] = __float_as_uint(Bs[buf][tig + 4][c]);
        }
#pragma unroll
        for (int mi = 0; mi < 4; mi++)
#pragma unroll
            for (int nj = 0; nj < 4; nj++) mma_tf32(acc[mi][nj], a[mi], b[nj]);
        if (more) {
            As[buf ^ 1][ak + 0][arow] = to_tf32(av.x); As[buf ^ 1][ak + 1][arow] = to_tf32(av.y);
            As[buf ^ 1][ak + 2][arow] = to_tf32(av.z); As[buf ^ 1][ak + 3][arow] = to_tf32(av.w);
            Bs[buf ^ 1][ak + 0][arow] = to_tf32(bv.x); Bs[buf ^ 1][ak + 1][arow] = to_tf32(bv.y);
            Bs[buf ^ 1][ak + 2][arow] = to_tf32(bv.z); Bs[buf ^ 1][ak + 3][arow] = to_tf32(bv.w);
            __syncthreads();
            buf ^= 1;
        }
    }

    const float scale = 0.10206207261596577f;  // 96^-0.5
#pragma unroll
    for (int nj = 0; nj < 4; nj++) {
        int c = m0 + wn + nj * 8 + tig * 2;
#pragma unroll
        for (int mi = 0; mi < 4; mi++) {
            size_t r = n0 + wm + mi * 16 + grp;
            float2 lo = make_float2(acc[mi][nj][0] * scale, acc[mi][nj][1] * scale);
            float2 hi = make_float2(acc[mi][nj][2] * scale, acc[mi][nj][3] * scale);
            *(float2*)(cbase + r * Nseq + c) = lo;
            *(float2*)(cbase + (r + 8) * Nseq + c) = hi;
        }
    }
}

// ================= tf32 MMA attn@v with fused gate blend =================
// BM=128 (tokens), BN=96 (head dim), BK=8. warp tile 64x24 (4 m x 3 n tiles).
__global__ __launch_bounds__(256)
void mma_attnv(const float* __restrict__ attn, const float* __restrict__ qkv,
               const float* __restrict__ qout, const float* __restrict__ fw,
               float* __restrict__ fused) {
    __shared__ float As[2][8][136];
    __shared__ float Bs[2][8][104];
    int z = blockIdx.z;
    int b = z >> 3, h = z & 7;
    const float* abase = attn + (size_t)z * Nseq * Nseq;
    const float* vbase = qkv + (size_t)b * Nseq * 2304 + 1536 + h * Dd;
    int n0 = blockIdx.x * 128;
    int tid = threadIdx.x;
    int arow = tid >> 1, ak = (tid & 1) * 4;
    const float* Ap = abase + (size_t)(n0 + arow) * Nseq + ak;
    int bk = tid / 24, bcol = (tid % 24) * 4;   // valid for tid < 192
    const float* Bp = vbase + (size_t)bk * 2304 + bcol;
    bool bact = (tid < 192);

    int wid = tid >> 5, lane = tid & 31;
    int wm = (wid >> 2) * 64, wn = (wid & 3) * 24;
    int grp = lane >> 2, tig = lane & 3;
    float acc[4][3][4] = {};

    {
        float4 av = *(const float4*)Ap;
        As[0][ak + 0][arow] = to_tf32(av.x); As[0][ak + 1][arow] = to_tf32(av.y);
        As[0][ak + 2][arow] = to_tf32(av.z); As[0][ak + 3][arow] = to_tf32(av.w);
        if (bact) {
            float4 bv = *(const float4*)Bp;
            float4 bc = make_float4(to_tf32(bv.x), to_tf32(bv.y), to_tf32(bv.z), to_tf32(bv.w));
            *(float4*)&Bs[0][bk][bcol] = bc;
        }
    }
    __syncthreads();

    int S = Nseq / 8, buf = 0;
    for (int s = 1; s <= S; s++) {
        bool more = (s < S);
        float4 av, bv;
        if (more) {
            av = *(const float4*)(Ap + s * 8);
            if (bact) bv = *(const float4*)(Bp + (size_t)s * 8 * 2304);
        }
        uint32_t a[4][4], bfr[3][2];
#pragma unroll
        for (int mi = 0; mi < 4; mi++) {
            int r = wm + mi * 16 + grp;
            a[mi][0] = __float_as_uint(As[buf][tig][r]);
            a[mi][1] = __float_as_uint(As[buf][tig][r + 8]);
            a[mi][2] = __float_as_uint(As[buf][tig + 4][r]);
            a[mi][3] = __float_as_uint(As[buf][tig + 4][r + 8]);
        }
#pragma unroll
        for (int nj = 0; nj < 3; nj++) {
            int c = wn + nj * 8 + grp;
            bfr[nj][0] = __float_as_uint(Bs[buf][tig][c]);
            bfr[nj][1] = __float_as_uint(Bs[buf][tig + 4][c]);
        }
#pragma unroll
        for (int mi = 0; mi < 4; mi++)
#pragma unroll
            for (int nj = 0; nj < 3; nj++) mma_tf32(acc[mi][nj], a[mi], bfr[nj]);
        if (more) {
            As[buf ^ 1][ak + 0][arow] = to_tf32(av.x); As[buf ^ 1][ak + 1][arow] = to_tf32(av.y);
            As[buf ^ 1][ak + 2][arow] = to_tf32(av.z); As[buf ^ 1][ak + 3][arow] = to_tf32(av.w);
            if (bact) {
                float4 bc = make_float4(to_tf32(bv.x), to_tf32(bv.y), to_tf32(bv.z), to_tf32(bv.w));
                *(float4*)&Bs[buf ^ 1][bk][bcol] = bc;
            }
            __syncthreads();
            buf ^= 1;
        }
    }

#pragma unroll
    for (int nj = 0; nj < 3; nj++) {
        int c = wn + nj * 8 + tig * 2;
        float f0 = fw[b * Cdim + h * Dd + c];
        float f1 = fw[b * Cdim + h * Dd + c + 1];
#pragma unroll
        for (int mi = 0; mi < 4; mi++) {
            size_t r = n0 + wm + mi * 16 + grp;
            size_t ob0 = ((size_t)b * Nseq + r) * Cdim + h * Dd + c;
            size_t ob1 = ((size_t)b * Nseq + r + 8) * Cdim + h * Dd + c;
            float2 q0 = *(const float2*)(qout + ob0);
            float2 q1 = *(const float2*)(qout + ob1);
            float2 lo = make_float2(f0 * q0.x + (1.f - f0) * acc[mi][nj][0],
                                    f1 * q0.y + (1.f - f1) * acc[mi][nj][1]);
            float2 hi = make_float2(f0 * q1.x + (1.f - f0) * acc[mi][nj][2],
                                    f1 * q1.y + (1.f - f1) * acc[mi][nj][3]);
            *(float2*)(fused + ob0) = lo;
            *(float2*)(fused + ob1) = hi;
        }
    }
}

// ================= row softmax over 1024 (float4) =================
__global__ void softmax_rows(float* __restrict__ attn) {
    __shared__ float redm[8], reds[8];
    size_t row = blockIdx.x;
    float4* p = (float4*)(attn + row * Nseq);
    int tid = threadIdx.x;
    float4 v = p[tid];
    float mx = fmaxf(fmaxf(v.x, v.y), fmaxf(v.z, v.w));
#pragma unroll
    for (int o = 16; o > 0; o >>= 1) mx = fmaxf(mx, __shfl_xor_sync(~0u, mx, o));
    int w = tid >> 5, lane = tid & 31;
    if (lane == 0) redm[w] = mx;
    __syncthreads();
    mx = redm[0];
#pragma unroll
    for (int i = 1; i < 8; i++) mx = fmaxf(mx, redm[i]);
    v.x = expf(v.x - mx); v.y = expf(v.y - mx);
    v.z = expf(v.z - mx); v.w = expf(v.w - mx);
    float sum = v.x + v.y + v.z + v.w;
#pragma unroll
    for (int o = 16; o > 0; o >>= 1) sum += __shfl_xor_sync(~0u, sum, o);
    if (lane == 0) reds[w] = sum;
    __syncthreads();
    sum = 0.f;
#pragma unroll
    for (int i = 0; i < 8; i++) sum += reds[i];
    float inv = 1.f / sum;
    v.x *= inv; v.y *= inv; v.z *= inv; v.w *= inv;
    p[tid] = v;
}

// ================= quantum per-token pipeline (1 warp / token) =================
__device__ __forceinline__ void embed_warp(const float* vec, float* hid, float* ebuf,
                                           const float* __restrict__ w1, const float* __restrict__ b1,
                                           const float* __restrict__ w2, const float* __restrict__ b2,
                                           int lane, float* sre, float* sim, bool accum) {
#pragma unroll
    for (int jj = 0; jj < 2; jj++) {
        int j = lane + jj * 32;
        float a = b1[j];
        for (int d = 0; d < 96; d++) a += vec[d] * w1[d * 64 + j];
        hid[j] = fmaxf(a, 0.f);
    }
    __syncwarp();
    if (lane < 16) {
        float a = b2[lane];
        for (int t = 0; t < 64; t++) a += hid[t] * w2[t * 16 + lane];
        ebuf[lane] = a;
    }
    __syncwarp();
    if (lane < 8) {
        float mx = ebuf[0];
        for (int i = 1; i < 8; i++) mx = fmaxf(mx, ebuf[i]);
        float sum = 0.f;
        for (int i = 0; i < 8; i++) sum += expf(ebuf[i] - mx);
        float amp = expf(ebuf[lane] - mx) / sum;
        float ph = ebuf[8 + lane];
        float cr = amp * cosf(ph), ci = amp * sinf(ph);
        if (accum) { sre[lane] += cr; sim[lane] += ci; }
        else       { sre[lane] = cr;  sim[lane] = ci; }
    }
    __syncwarp();
}

__global__ void quantum_kernel(const float* __restrict__ qkv,
                               const float* __restrict__ qe_w1, const float* __restrict__ qe_b1,
                               const float* __restrict__ qe_w2, const float* __restrict__ qe_b2,
                               const float* __restrict__ ke_w1, const float* __restrict__ ke_b1,
                               const float* __restrict__ ke_w2, const float* __restrict__ ke_b2,
                               const float* __restrict__ gate_params, const float* __restrict__ ent_params,
                               const float* __restrict__ md_w1, const float* __restrict__ md_b1,
                               const float* __restrict__ md_w2, const float* __restrict__ md_b2,
                               const float* __restrict__ gumbel, float* __restrict__ qout) {
    __shared__ float vec[8][96];
    __shared__ float hid[8][64];
    __shared__ float ebuf[8][16];
    __shared__ float sre[8][8], sim[8][8], tre[8][8], tim[8][8];
    int w = threadIdx.x >> 5;
    int lane = threadIdx.x & 31;
    int wg = blockIdx.x * 8 + w;
    int b = wg >> 13;
    int h = (wg >> 10) & 7;
    int n = wg & 1023;
    size_t rowoff = (size_t)(b * Nseq + n) * 2304;
    int qoff = h * Dd;

    vec[w][lane]      = qkv[rowoff + qoff + lane];
    vec[w][lane + 32] = qkv[rowoff + qoff + lane + 32];
    vec[w][lane + 64] = qkv[rowoff + qoff + lane + 64];
    __syncwarp();
    embed_warp(vec[w], hid[w], ebuf[w], qe_w1, qe_b1, qe_w2, qe_b2, lane, sre[w], sim[w], false);

    vec[w][lane]      = qkv[rowoff + 768 + qoff + lane];
    vec[w][lane + 32] = qkv[rowoff + 768 + qoff + lane + 32];
    vec[w][lane + 64] = qkv[rowoff + 768 + qoff + lane + 64];
    __syncwarp();
    embed_warp(vec[w], hid[w], ebuf[w], ke_w1, ke_b1, ke_w2, ke_b2, lane, sre[w], sim[w], true);

#pragma unroll
    for (int layer = 0; layer < 2; layer++) {
        if (lane < 8) {
            float ry = gate_params[(layer * 8 + lane) * 3 + 1];
            float rz = gate_params[(layer * 8 + lane) * 3 + 2];
            float re = sre[w][lane], im = sim[w][lane];
            float cz = cosf(rz), sz = sinf(rz);
            float nr = re * cz - im * sz, ni = re * sz + im * cz;
            float f = cosf(0.5f * ry);
            tre[w][lane] = nr * f; tim[w][lane] = ni * f;
        }
        __syncwarp();
        if (lane < 8) {
            float ar = tre[w][lane], ai = tim[w][lane];
            if (lane > 0) {
                float s = 1.f / (1.f + expf(-ent_params[layer * 7 + lane - 1]));
                ar += s * tre[w][lane - 1];
                ai += s * tim[w][lane - 1];
            }
            sre[w][lane] = ar; sim[w][lane] = ai;
        }
        __syncwarp();
    }

    if (lane < 8) ebuf[w][lane] = sre[w][lane] * sre[w][lane] + sim[w][lane] * sim[w][lane];
    __syncwarp();
    if (lane < 8) {
        float mx = ebuf[w][0];
        for (int i = 1; i < 8; i++) mx = fmaxf(mx, ebuf[w][i]);
        float sum = 0.f;
        for (int i = 0; i < 8; i++) sum += expf(ebuf[w][i] - mx);
        float prob = expf(ebuf[w][lane] - mx) / sum;
        float g = gumbel[(size_t)wg * 8 + lane];
        tre[w][lane] = 2.f * (logf(prob + 1e-10f) + g);
    }
    __syncwarp();
    if (lane < 8) {
        float mx = tre[w][0];
        for (int i = 1; i < 8; i++) mx = fmaxf(mx, tre[w][i]);
        float sum = 0.f;
        for (int i = 0; i < 8; i++) sum += expf(tre[w][i] - mx);
        ebuf[w][lane] = expf(tre[w][lane] - mx) / sum;
    }
    __syncwarp();

#pragma unroll
    for (int jj = 0; jj < 2; jj++) {
        int j = lane + jj * 32;
        float a = md_b1[j];
        for (int i = 0; i < 8; i++) a += ebuf[w][i] * md_w1[i * 64 + j];
        hid[w][j] = fmaxf(a, 0.f);
    }
    __syncwarp();
    size_t outbase = (size_t)(b * Nseq + n) * Cdim + h * Dd;
#pragma unroll
    for (int dd = 0; dd < 3; dd++) {
        int d = lane + dd * 32;
        float a = md_b2[d];
        for (int t = 0; t < 64; t++) a += hid[w][t] * md_w2[t * 96 + d];
        float vv = qkv[rowoff + 1536 + qoff + d];
        qout[outbase + d] = a * vv;
    }
}

// ================= mean over N =================
__global__ void colmean_kernel(const float* __restrict__ x, float* __restrict__ xmean) {
    int b = blockIdx.y;
    int c = blockIdx.x * 256 + threadIdx.x;
    const float* p = x + (size_t)b * Nseq * Cdim + c;
    float s = 0.f;
    for (int n = 0; n < Nseq; n++) s += p[(size_t)n * Cdim];
    xmean[b * Cdim + c] = s * (1.0f / 1024.0f);
}

// ================= fw = sigmoid(xmean @ w_proj + b_proj) =================
__global__ void fw_kernel(const float* __restrict__ xmean, const float* __restrict__ w_proj,
                          const float* __restrict__ b_proj, float* __restrict__ fw) {
    __shared__ float xm[768];
    int b = blockIdx.x;
    int c = threadIdx.x;
    xm[c] = xmean[b * Cdim + c];
    __syncthreads();
    float s = b_proj[c];
    for (int k = 0; k < 768; k++) s += xm[k] * w_proj[(size_t)k * 768 + c];
    fw[b * Cdim + c] = 1.f / (1.f + expf(-s));
}

// ================= layernorm =================
__global__ void layernorm_kernel(const float* __restrict__ y, const float* __restrict__ gamma,
                                 const float* __restrict__ beta, float* __restrict__ out) {
    __shared__ float red1[8], red2[8];
    size_t row = blockIdx.x;
    const float* p = y + row * Cdim;
    int tid = threadIdx.x;
    float v[3];
    float s = 0.f;
#pragma unroll
    for (int i = 0; i < 3; i++) { v[i] = p[tid + i * 256]; s += v[i]; }
#pragma unroll
    for (int o = 16; o > 0; o >>= 1) s += __shfl_xor_sync(~0u, s, o);
    int w = tid >> 5, lane = tid & 31;
    if (lane == 0) red1[w] = s;
    __syncthreads();
    s = 0.f;
#pragma unroll
    for (int i = 0; i < 8; i++) s += red1[i];
    float mu = s * (1.0f / 768.0f);
    float vs = 0.f;
#pragma unroll
    for (int i = 0; i < 3; i++) { float d = v[i] - mu; vs += d * d; }
#pragma unroll
    for (int o = 16; o > 0; o >>= 1) vs += __shfl_xor_sync(~0u, vs, o);
    if (lane == 0) red2[w] = vs;
    __syncthreads();
    vs = 0.f;
#pragma unroll
    for (int i = 0; i < 8; i++) vs += red2[i];
    float inv = rsqrtf(vs * (1.0f / 768.0f) + 1e-5f);
#pragma unroll
    for (int i = 0; i < 3; i++) {
        int c = tid + i * 256;
        out[row * Cdim + c] = (v[i] - mu) * inv * gamma[c] + beta[c];
    }
}

// ================= launch =================
extern "C" void kernel_launch(void* const* d_in, const int* in_sizes, int n_in,
                              void* d_out, int out_size) {
    const float* x      = (const float*)d_in[0];
    const float* w_qkv  = (const float*)d_in[1];
    const float* b_qkv  = (const float*)d_in[2];
    const float* w_proj = (const float*)d_in[3];
    const float* b_proj = (const float*)d_in[4];
    const float* gamma  = (const float*)d_in[5];
    const float* beta   = (const float*)d_in[6];
    const float* qe_w1  = (const float*)d_in[7];
    const float* qe_b1  = (const float*)d_in[8];
    const float* qe_w2  = (const float*)d_in[9];
    const float* qe_b2  = (const float*)d_in[10];
    const float* ke_w1  = (const float*)d_in[11];
    const float* ke_b1  = (const float*)d_in[12];
    const float* ke_w2  = (const float*)d_in[13];
    const float* ke_b2  = (const float*)d_in[14];
    const float* gate_params = (const float*)d_in[19];
    const float* ent_params  = (const float*)d_in[20];
    const float* md_w1  = (const float*)d_in[21];
    const float* md_b1  = (const float*)d_in[22];
    const float* md_w2  = (const float*)d_in[23];
    const float* md_b2  = (const float*)d_in[24];
    const float* gumbel = (const float*)d_in[25];
    float* out = (float*)d_out;

    float *qkv, *attn, *qout, *fused, *xmean, *fw;
    cudaGetSymbolAddress((void**)&qkv, g_qkv);
    cudaGetSymbolAddress((void**)&attn, g_attn);
    cudaGetSymbolAddress((void**)&qout, g_qout);
    cudaGetSymbolAddress((void**)&fused, g_fused);
    cudaGetSymbolAddress((void**)&xmean, g_xmean);
    cudaGetSymbolAddress((void**)&fw, g_fw);

    // gate path (depends only on x)
    colmean_kernel<<<dim3(3, 8), 256>>>(x, xmean);
    fw_kernel<<<8, 768>>>(xmean, w_proj, b_proj, fw);
    // qkv = x @ w_qkv + b_qkv   (8192 x 2304 x 768)
    mma_nn<<<dim3(2304 / 128, 8192 / 128), 256>>>(x, w_qkv, b_qkv, nullptr, qkv,
                                                  768, 768, 2304, 2304);
    // quantum path -> qout
    quantum_kernel<<<8192, 256>>>(qkv, qe_w1, qe_b1, qe_w2, qe_b2,
                                  ke_w1, ke_b1, ke_w2, ke_b2,
                                  gate_params, ent_params,
                                  md_w1, md_b1, md_w2, md_b2, gumbel, qout);
    // classical attention
    mma_scores<<<dim3(1024 / 128, 1024 / 128, 64), 256>>>(qkv, attn);
    softmax_rows<<<65536, 256>>>(attn);
    mma_attnv<<<dim3(1024 / 128, 1, 64), 256>>>(attn, qkv, qout, fw, fused);
    // y = x + fused @ w_proj + b_proj  (reuse qout as y)
    mma_nn<<<dim3(768 / 128, 8192 / 128), 256>>>(fused, w_proj, b_proj, x, qout,
                                                 768, 768, 768, 768);
    // layernorm
    layernorm_kernel<<<8192, 256>>>(qout, gamma, beta, out);
}

// round 4
// speedup vs baseline: 2.6378x; 1.0624x over previous
#include <cuda_runtime.h>
#include <math.h>
#include <stdint.h>

// ---------------- scratch ----------------
#define Bsz 8
#define Nseq 1024
#define Cdim 768
#define Hh 8
#define Dd 96
#define Qq 8

__device__ float g_qkv[Bsz * Nseq * 3 * Cdim];
__device__ float g_attn[(size_t)Bsz * Hh * Nseq * Nseq];
__device__ float g_qout[Bsz * Nseq * Cdim];
__device__ float g_fused[Bsz * Nseq * Cdim];
__device__ float g_xmean[Bsz * Cdim];
__device__ float g_fw[Bsz * Cdim];

// ---------------- tf32 mma helpers ----------------
__device__ __forceinline__ float to_tf32(float x) {
    uint32_t u;
    asm("cvt.rna.tf32.f32 %0, %1;" : "=r"(u) : "f"(x));
    return __uint_as_float(u);
}

__device__ __forceinline__ void mma_tf32(float* c, const uint32_t* a, const uint32_t* b) {
    asm volatile(
        "mma.sync.aligned.m16n8k8.row.col.f32.tf32.tf32.f32 "
        "{%0,%1,%2,%3}, {%4,%5,%6,%7}, {%8,%9}, {%0,%1,%2,%3};"
        : "+f"(c[0]), "+f"(c[1]), "+f"(c[2]), "+f"(c[3])
        : "r"(a[0]), "r"(a[1]), "r"(a[2]), "r"(a[3]), "r"(b[0]), "r"(b[1]));
}

// ================= tf32 MMA GEMM (NN): C = A@B (+bias)(+resid) =================
__global__ __launch_bounds__(256)
void mma_nn(const float* __restrict__ A, const float* __restrict__ B,
            const float* __restrict__ bias, const float* __restrict__ resid,
            float* __restrict__ C, int K, int lda, int ldb, int ldc) {
    __shared__ float As[2][8][136];
    __shared__ float Bs[2][8][136];
    int tid = threadIdx.x;
    int m0 = blockIdx.y * 128, n0 = blockIdx.x * 128;
    int arow = tid >> 1, ak = (tid & 1) * 4;
    int bk = tid >> 5, bcol = (tid & 31) * 4;
    const float* Ap = A + (size_t)(m0 + arow) * lda + ak;
    const float* Bp = B + (size_t)bk * ldb + n0 + bcol;

    int wid = tid >> 5, lane = tid & 31;
    int wm = (wid >> 2) * 64, wn = (wid & 3) * 32;
    int grp = lane >> 2, tig = lane & 3;
    float acc[4][4][4] = {};

    {
        float4 av = *(const float4*)Ap;
        float4 bv = *(const float4*)Bp;
        As[0][ak + 0][arow] = to_tf32(av.x); As[0][ak + 1][arow] = to_tf32(av.y);
        As[0][ak + 2][arow] = to_tf32(av.z); As[0][ak + 3][arow] = to_tf32(av.w);
        float4 bc = make_float4(to_tf32(bv.x), to_tf32(bv.y), to_tf32(bv.z), to_tf32(bv.w));
        *(float4*)&Bs[0][bk][bcol] = bc;
    }
    __syncthreads();

    int S = K / 8, buf = 0;
    for (int s = 1; s <= S; s++) {
        bool more = (s < S);
        float4 av, bv;
        if (more) {
            av = *(const float4*)(Ap + s * 8);
            bv = *(const float4*)(Bp + (size_t)s * 8 * ldb);
        }
        uint32_t a[4][4], b[4][2];
#pragma unroll
        for (int mi = 0; mi < 4; mi++) {
            int r = wm + mi * 16 + grp;
            a[mi][0] = __float_as_uint(As[buf][tig][r]);
            a[mi][1] = __float_as_uint(As[buf][tig][r + 8]);
            a[mi][2] = __float_as_uint(As[buf][tig + 4][r]);
            a[mi][3] = __float_as_uint(As[buf][tig + 4][r + 8]);
        }
#pragma unroll
        for (int nj = 0; nj < 4; nj++) {
            int c = wn + nj * 8 + grp;
            b[nj][0] = __float_as_uint(Bs[buf][tig][c]);
            b[nj][1] = __float_as_uint(Bs[buf][tig + 4][c]);
        }
#pragma unroll
        for (int mi = 0; mi < 4; mi++)
#pragma unroll
            for (int nj = 0; nj < 4; nj++) mma_tf32(acc[mi][nj], a[mi], b[nj]);
        if (more) {
            As[buf ^ 1][ak + 0][arow] = to_tf32(av.x); As[buf ^ 1][ak + 1][arow] = to_tf32(av.y);
            As[buf ^ 1][ak + 2][arow] = to_tf32(av.z); As[buf ^ 1][ak + 3][arow] = to_tf32(av.w);
            float4 bc = make_float4(to_tf32(bv.x), to_tf32(bv.y), to_tf32(bv.z), to_tf32(bv.w));
            *(float4*)&Bs[buf ^ 1][bk][bcol] = bc;
            __syncthreads();
            buf ^= 1;
        }
    }

#pragma unroll
    for (int nj = 0; nj < 4; nj++) {
        int c = n0 + wn + nj * 8 + tig * 2;
        float bi0 = bias ? bias[c] : 0.f;
        float bi1 = bias ? bias[c + 1] : 0.f;
#pragma unroll
        for (int mi = 0; mi < 4; mi++) {
            size_t r = m0 + wm + mi * 16 + grp;
            float2 lo = make_float2(acc[mi][nj][0] + bi0, acc[mi][nj][1] + bi1);
            float2 hi = make_float2(acc[mi][nj][2] + bi0, acc[mi][nj][3] + bi1);
            if (resid) {
                float2 r0 = *(const float2*)(resid + r * ldc + c);
                float2 r1 = *(const float2*)(resid + (r + 8) * ldc + c);
                lo.x += r0.x; lo.y += r0.y; hi.x += r1.x; hi.y += r1.y;
            }
            *(float2*)(C + r * ldc + c) = lo;
            *(float2*)(C + (r + 8) * ldc + c) = hi;
        }
    }
}

// ================= tf32 MMA scores (NT): attn = scale * Q @ K^T =================
__global__ __launch_bounds__(256)
void mma_scores(const float* __restrict__ qkv, float* __restrict__ attn) {
    __shared__ float As[2][8][136];
    __shared__ float Bs[2][8][136];
    int z = blockIdx.z;
    int b = z >> 3, h = z & 7;
    const float* qbase = qkv + (size_t)b * Nseq * 2304 + h * Dd;
    const float* kbase = qbase + 768;
    float* cbase = attn + (size_t)z * Nseq * Nseq;
    int tid = threadIdx.x;
    int n0 = blockIdx.y * 128;
    int m0 = blockIdx.x * 128;
    int arow = tid >> 1, ak = (tid & 1) * 4;
    const float* Ap = qbase + (size_t)(n0 + arow) * 2304 + ak;
    const float* Bp = kbase + (size_t)(m0 + arow) * 2304 + ak;

    int wid = tid >> 5, lane = tid & 31;
    int wm = (wid >> 2) * 64, wn = (wid & 3) * 32;
    int grp = lane >> 2, tig = lane & 3;
    float acc[4][4][4] = {};

    {
        float4 av = *(const float4*)Ap;
        float4 bv = *(const float4*)Bp;
        As[0][ak + 0][arow] = to_tf32(av.x); As[0][ak + 1][arow] = to_tf32(av.y);
        As[0][ak + 2][arow] = to_tf32(av.z); As[0][ak + 3][arow] = to_tf32(av.w);
        Bs[0][ak + 0][arow] = to_tf32(bv.x); Bs[0][ak + 1][arow] = to_tf32(bv.y);
        Bs[0][ak + 2][arow] = to_tf32(bv.z); Bs[0][ak + 3][arow] = to_tf32(bv.w);
    }
    __syncthreads();

    int S = Dd / 8, buf = 0;
    for (int s = 1; s <= S; s++) {
        bool more = (s < S);
        float4 av, bv;
        if (more) {
            av = *(const float4*)(Ap + s * 8);
            bv = *(const float4*)(Bp + s * 8);
        }
        uint32_t a[4][4], b[4][2];
#pragma unroll
        for (int mi = 0; mi < 4; mi++) {
            int r = wm + mi * 16 + grp;
            a[mi][0] = __float_as_uint(As[buf][tig][r]);
            a[mi][1] = __float_as_uint(As[buf][tig][r + 8]);
            a[mi][2] = __float_as_uint(As[buf][tig + 4][r]);
            a[mi][3] = __float_as_uint(As[buf][tig + 4][r + 8]);
        }
#pragma unroll
        for (int nj = 0; nj < 4; nj++) {
            int c = wn + nj * 8 + grp;
            b[nj][0] = __float_as_uint(Bs[buf][tig][c]);
            b[nj][1] = __float_as_uint(Bs[buf][tig + 4][c]);
        }
#pragma unroll
        for (int mi = 0; mi < 4; mi++)
#pragma unroll
            for (int nj = 0; nj < 4; nj++) mma_tf32(acc[mi][nj], a[mi], b[nj]);
        if (more) {
            As[buf ^ 1][ak + 0][arow] = to_tf32(av.x); As[buf ^ 1][ak + 1][arow] = to_tf32(av.y);
            As[buf ^ 1][ak + 2][arow] = to_tf32(av.z); As[buf ^ 1][ak + 3][arow] = to_tf32(av.w);
            Bs[buf ^ 1][ak + 0][arow] = to_tf32(bv.x); Bs[buf ^ 1][ak + 1][arow] = to_tf32(bv.y);
            Bs[buf ^ 1][ak + 2][arow] = to_tf32(bv.z); Bs[buf ^ 1][ak + 3][arow] = to_tf32(bv.w);
            __syncthreads();
            buf ^= 1;
        }
    }

    const float scale = 0.10206207261596577f;
#pragma unroll
    for (int nj = 0; nj < 4; nj++) {
        int c = m0 + wn + nj * 8 + tig * 2;
#pragma unroll
        for (int mi = 0; mi < 4; mi++) {
            size_t r = n0 + wm + mi * 16 + grp;
            float2 lo = make_float2(acc[mi][nj][0] * scale, acc[mi][nj][1] * scale);
            float2 hi = make_float2(acc[mi][nj][2] * scale, acc[mi][nj][3] * scale);
            *(float2*)(cbase + r * Nseq + c) = lo;
            *(float2*)(cbase + (r + 8) * Nseq + c) = hi;
        }
    }
}

// ================= tf32 MMA attn@v with fused gate blend =================
__global__ __launch_bounds__(256)
void mma_attnv(const float* __restrict__ attn, const float* __restrict__ qkv,
               const float* __restrict__ qout, const float* __restrict__ fw,
               float* __restrict__ fused) {
    __shared__ float As[2][8][136];
    __shared__ float Bs[2][8][104];
    int z = blockIdx.z;
    int b = z >> 3, h = z & 7;
    const float* abase = attn + (size_t)z * Nseq * Nseq;
    const float* vbase = qkv + (size_t)b * Nseq * 2304 + 1536 + h * Dd;
    int n0 = blockIdx.x * 128;
    int tid = threadIdx.x;
    int arow = tid >> 1, ak = (tid & 1) * 4;
    const float* Ap = abase + (size_t)(n0 + arow) * Nseq + ak;
    int bk = tid / 24, bcol = (tid % 24) * 4;
    const float* Bp = vbase + (size_t)bk * 2304 + bcol;
    bool bact = (tid < 192);

    int wid = tid >> 5, lane = tid & 31;
    int wm = (wid >> 2) * 64, wn = (wid & 3) * 24;
    int grp = lane >> 2, tig = lane & 3;
    float acc[4][3][4] = {};

    {
        float4 av = *(const float4*)Ap;
        As[0][ak + 0][arow] = to_tf32(av.x); As[0][ak + 1][arow] = to_tf32(av.y);
        As[0][ak + 2][arow] = to_tf32(av.z); As[0][ak + 3][arow] = to_tf32(av.w);
        if (bact) {
            float4 bv = *(const float4*)Bp;
            float4 bc = make_float4(to_tf32(bv.x), to_tf32(bv.y), to_tf32(bv.z), to_tf32(bv.w));
            *(float4*)&Bs[0][bk][bcol] = bc;
        }
    }
    __syncthreads();

    int S = Nseq / 8, buf = 0;
    for (int s = 1; s <= S; s++) {
        bool more = (s < S);
        float4 av, bv;
        if (more) {
            av = *(const float4*)(Ap + s * 8);
            if (bact) bv = *(const float4*)(Bp + (size_t)s * 8 * 2304);
        }
        uint32_t a[4][4], bfr[3][2];
#pragma unroll
        for (int mi = 0; mi < 4; mi++) {
            int r = wm + mi * 16 + grp;
            a[mi][0] = __float_as_uint(As[buf][tig][r]);
            a[mi][1] = __float_as_uint(As[buf][tig][r + 8]);
            a[mi][2] = __float_as_uint(As[buf][tig + 4][r]);
            a[mi][3] = __float_as_uint(As[buf][tig + 4][r + 8]);
        }
#pragma unroll
        for (int nj = 0; nj < 3; nj++) {
            int c = wn + nj * 8 + grp;
            bfr[nj][0] = __float_as_uint(Bs[buf][tig][c]);
            bfr[nj][1] = __float_as_uint(Bs[buf][tig + 4][c]);
        }
#pragma unroll
        for (int mi = 0; mi < 4; mi++)
#pragma unroll
            for (int nj = 0; nj < 3; nj++) mma_tf32(acc[mi][nj], a[mi], bfr[nj]);
        if (more) {
            As[buf ^ 1][ak + 0][arow] = to_tf32(av.x); As[buf ^ 1][ak + 1][arow] = to_tf32(av.y);
            As[buf ^ 1][ak + 2][arow] = to_tf32(av.z); As[buf ^ 1][ak + 3][arow] = to_tf32(av.w);
            if (bact) {
                float4 bc = make_float4(to_tf32(bv.x), to_tf32(bv.y), to_tf32(bv.z), to_tf32(bv.w));
                *(float4*)&Bs[buf ^ 1][bk][bcol] = bc;
            }
            __syncthreads();
            buf ^= 1;
        }
    }

#pragma unroll
    for (int nj = 0; nj < 3; nj++) {
        int c = wn + nj * 8 + tig * 2;
        float f0 = fw[b * Cdim + h * Dd + c];
        float f1 = fw[b * Cdim + h * Dd + c + 1];
#pragma unroll
        for (int mi = 0; mi < 4; mi++) {
            size_t r = n0 + wm + mi * 16 + grp;
            size_t ob0 = ((size_t)b * Nseq + r) * Cdim + h * Dd + c;
            size_t ob1 = ((size_t)b * Nseq + r + 8) * Cdim + h * Dd + c;
            float2 q0 = *(const float2*)(qout + ob0);
            float2 q1 = *(const float2*)(qout + ob1);
            float2 lo = make_float2(f0 * q0.x + (1.f - f0) * acc[mi][nj][0],
                                    f1 * q0.y + (1.f - f1) * acc[mi][nj][1]);
            float2 hi = make_float2(f0 * q1.x + (1.f - f0) * acc[mi][nj][2],
                                    f1 * q1.y + (1.f - f1) * acc[mi][nj][3]);
            *(float2*)(fused + ob0) = lo;
            *(float2*)(fused + ob1) = hi;
        }
    }
}

// ================= row softmax over 1024 (float4) =================
__global__ void softmax_rows(float* __restrict__ attn) {
    __shared__ float redm[8], reds[8];
    size_t row = blockIdx.x;
    float4* p = (float4*)(attn + row * Nseq);
    int tid = threadIdx.x;
    float4 v = p[tid];
    float mx = fmaxf(fmaxf(v.x, v.y), fmaxf(v.z, v.w));
#pragma unroll
    for (int o = 16; o > 0; o >>= 1) mx = fmaxf(mx, __shfl_xor_sync(~0u, mx, o));
    int w = tid >> 5, lane = tid & 31;
    if (lane == 0) redm[w] = mx;
    __syncthreads();
    mx = redm[0];
#pragma unroll
    for (int i = 1; i < 8; i++) mx = fmaxf(mx, redm[i]);
    v.x = expf(v.x - mx); v.y = expf(v.y - mx);
    v.z = expf(v.z - mx); v.w = expf(v.w - mx);
    float sum = v.x + v.y + v.z + v.w;
#pragma unroll
    for (int o = 16; o > 0; o >>= 1) sum += __shfl_xor_sync(~0u, sum, o);
    if (lane == 0) reds[w] = sum;
    __syncthreads();
    sum = 0.f;
#pragma unroll
    for (int i = 0; i < 8; i++) sum += reds[i];
    float inv = 1.f / sum;
    v.x *= inv; v.y *= inv; v.z *= inv; v.w *= inv;
    p[tid] = v;
}

// ================= quantum: thread-per-token =================
__device__ __forceinline__ void embed_token(const float* __restrict__ row,
                                            const float* __restrict__ w1s,
                                            const float* __restrict__ w2s,
                                            const float* __restrict__ b1,
                                            const float* __restrict__ b2,
                                            float* sre, float* sim, bool accum) {
    float acc[64];
#pragma unroll
    for (int j = 0; j < 64; j++) acc[j] = __ldg(&b1[j]);
    const float4* r4 = (const float4*)row;
#pragma unroll 1
    for (int d4 = 0; d4 < 24; d4++) {
        float4 v4 = __ldg(&r4[d4]);
        float vv[4] = {v4.x, v4.y, v4.z, v4.w};
#pragma unroll
        for (int s = 0; s < 4; s++) {
            float vd = vv[s];
            const float4* wr = (const float4*)&w1s[(d4 * 4 + s) * 64];
#pragma unroll
            for (int j4 = 0; j4 < 16; j4++) {
                float4 w = wr[j4];
                acc[j4 * 4 + 0] += vd * w.x;
                acc[j4 * 4 + 1] += vd * w.y;
                acc[j4 * 4 + 2] += vd * w.z;
                acc[j4 * 4 + 3] += vd * w.w;
            }
        }
    }
    float e[16];
#pragma unroll
    for (int i = 0; i < 16; i++) e[i] = __ldg(&b2[i]);
#pragma unroll 4
    for (int j = 0; j < 64; j++) {
        float hj = fmaxf(acc[j], 0.f);
        const float4* wr = (const float4*)&w2s[j * 16];
#pragma unroll
        for (int i4 = 0; i4 < 4; i4++) {
            float4 w = wr[i4];
            e[i4 * 4 + 0] += hj * w.x; e[i4 * 4 + 1] += hj * w.y;
            e[i4 * 4 + 2] += hj * w.z; e[i4 * 4 + 3] += hj * w.w;
        }
    }
    float mx = e[0];
#pragma unroll
    for (int i = 1; i < 8; i++) mx = fmaxf(mx, e[i]);
    float ex[8], s = 0.f;
#pragma unroll
    for (int i = 0; i < 8; i++) { ex[i] = __expf(e[i] - mx); s += ex[i]; }
    float inv = 1.f / s;
#pragma unroll
    for (int i = 0; i < 8; i++) {
        float amp = ex[i] * inv;
        float ph = e[8 + i];
        float cr = amp * __cosf(ph), ci = amp * __sinf(ph);
        if (accum) { sre[i] += cr; sim[i] += ci; }
        else       { sre[i] = cr;  sim[i] = ci; }
    }
}

__global__ __launch_bounds__(128)
void quantum_kernel2(const float* __restrict__ qkv,
                     const float* __restrict__ qe_w1, const float* __restrict__ qe_b1,
                     const float* __restrict__ qe_w2, const float* __restrict__ qe_b2,
                     const float* __restrict__ ke_w1, const float* __restrict__ ke_b1,
                     const float* __restrict__ ke_w2, const float* __restrict__ ke_b2,
                     const float* __restrict__ gate_params, const float* __restrict__ ent_params,
                     const float* __restrict__ md_w1, const float* __restrict__ md_b1,
                     const float* __restrict__ md_w2, const float* __restrict__ md_b2,
                     const float* __restrict__ gumbel, float* __restrict__ qout) {
    __shared__ float w1s[96 * 64];   // 24KB: qe_w1 -> ke_w1 -> md_w2
    __shared__ float w2s[64 * 16];   // 4KB:  qe_w2 -> ke_w2 -> md_w1
    __shared__ float gf[2][8], gcz[2][8], gsz[2][8], gs[2][8];

    int tid = threadIdx.x;
    // stage qe weights + gate precompute
    {
        const float4* s1 = (const float4*)qe_w1;
        float4* d1 = (float4*)w1s;
        for (int i = tid; i < 96 * 64 / 4; i += 128) d1[i] = s1[i];
        const float4* s2 = (const float4*)qe_w2;
        float4* d2 = (float4*)w2s;
        for (int i = tid; i < 64 * 16 / 4; i += 128) d2[i] = s2[i];
        if (tid < 16) {
            int l = tid >> 3, i = tid & 7;
            float ry = gate_params[(l * 8 + i) * 3 + 1];
            float rz = gate_params[(l * 8 + i) * 3 + 2];
            gf[l][i] = cosf(0.5f * ry);
            gcz[l][i] = cosf(rz);
            gsz[l][i] = sinf(rz);
        } else if (tid < 30) {
            int t = tid - 16, l = t / 7, i = t % 7;
            gs[l][i + 1] = 1.f / (1.f + expf(-ent_params[l * 7 + i]));
        }
    }
    __syncthreads();

    int wg = blockIdx.x * 128 + tid;      // ((b*8+h)*1024+n)
    int b = wg >> 13, h = (wg >> 10) & 7, n = wg & 1023;
    const float* base = qkv + (size_t)(b * Nseq + n) * 2304 + h * Dd;

    float sre[8], sim[8];
    embed_token(base, w1s, w2s, qe_b1, qe_b2, sre, sim, false);
    __syncthreads();
    // stage ke weights
    {
        const float4* s1 = (const float4*)ke_w1;
        float4* d1 = (float4*)w1s;
        for (int i = tid; i < 96 * 64 / 4; i += 128) d1[i] = s1[i];
        const float4* s2 = (const float4*)ke_w2;
        float4* d2 = (float4*)w2s;
        for (int i = tid; i < 64 * 16 / 4; i += 128) d2[i] = s2[i];
    }
    __syncthreads();
    embed_token(base + 768, w1s, w2s, ke_b1, ke_b2, sre, sim, true);

    // variational (2 layers), in registers
#pragma unroll
    for (int l = 0; l < 2; l++) {
#pragma unroll
        for (int i = 0; i < 8; i++) {
            float nr = sre[i] * gcz[l][i] - sim[i] * gsz[l][i];
            float ni = sre[i] * gsz[l][i] + sim[i] * gcz[l][i];
            sre[i] = nr * gf[l][i];
            sim[i] = ni * gf[l][i];
        }
#pragma unroll
        for (int i = 7; i >= 1; i--) {
            sre[i] += gs[l][i] * sre[i - 1];
            sim[i] += gs[l][i] * sim[i - 1];
        }
    }

    // probs softmax -> gumbel meas softmax
    float p[8], mx = -1e30f;
#pragma unroll
    for (int i = 0; i < 8; i++) { p[i] = sre[i] * sre[i] + sim[i] * sim[i]; mx = fmaxf(mx, p[i]); }
    float ssum = 0.f;
#pragma unroll
    for (int i = 0; i < 8; i++) { p[i] = __expf(p[i] - mx); ssum += p[i]; }
    float sinv = 1.f / ssum;
    float4 g0 = __ldg((const float4*)(gumbel + (size_t)wg * 8));
    float4 g1 = __ldg((const float4*)(gumbel + (size_t)wg * 8 + 4));
    float gv[8] = {g0.x, g0.y, g0.z, g0.w, g1.x, g1.y, g1.z, g1.w};
    float lg[8], mx2 = -1e30f;
#pragma unroll
    for (int i = 0; i < 8; i++) {
        lg[i] = 2.f * (__logf(p[i] * sinv + 1e-10f) + gv[i]);
        mx2 = fmaxf(mx2, lg[i]);
    }
    float meas[8], msum = 0.f;
#pragma unroll
    for (int i = 0; i < 8; i++) { meas[i] = __expf(lg[i] - mx2); msum += meas[i]; }
    float minv = 1.f / msum;
#pragma unroll
    for (int i = 0; i < 8; i++) meas[i] *= minv;

    __syncthreads();
    // stage md weights: md_w1 (8x64) -> w2s, md_w2 (64x96) -> w1s
    {
        const float4* s1 = (const float4*)md_w2;
        float4* d1 = (float4*)w1s;
        for (int i = tid; i < 64 * 96 / 4; i += 128) d1[i] = s1[i];
        const float4* s2 = (const float4*)md_w1;
        float4* d2 = (float4*)w2s;
        for (int i = tid; i < 8 * 64 / 4; i += 128) d2[i] = s2[i];
    }
    __syncthreads();

    // hid2 = relu(meas @ md_w1 + md_b1)
    float acc[64];
#pragma unroll
    for (int j = 0; j < 64; j++) acc[j] = __ldg(&md_b1[j]);
#pragma unroll
    for (int i = 0; i < 8; i++) {
        float mi = meas[i];
        const float4* wr = (const float4*)&w2s[i * 64];
#pragma unroll
        for (int j4 = 0; j4 < 16; j4++) {
            float4 w = wr[j4];
            acc[j4 * 4 + 0] += mi * w.x;
            acc[j4 * 4 + 1] += mi * w.y;
            acc[j4 * 4 + 2] += mi * w.z;
            acc[j4 * 4 + 3] += mi * w.w;
        }
    }
#pragma unroll
    for (int j = 0; j < 64; j++) acc[j] = fmaxf(acc[j], 0.f);

    // out = (hid2 @ md_w2 + md_b2) * v, in 4 tiles of 24
    const float* vrow = base + 1536;
    float* orow = qout + (size_t)(b * Nseq + n) * Cdim + h * Dd;
#pragma unroll 1
    for (int t = 0; t < 4; t++) {
        float o[24];
#pragma unroll
        for (int u = 0; u < 24; u++) o[u] = __ldg(&md_b2[t * 24 + u]);
#pragma unroll 4
        for (int j = 0; j < 64; j++) {
            float hj = acc[j];
            const float4* wr = (const float4*)&w1s[j * 96 + t * 24];
#pragma unroll
            for (int u4 = 0; u4 < 6; u4++) {
                float4 w = wr[u4];
                o[u4 * 4 + 0] += hj * w.x;
                o[u4 * 4 + 1] += hj * w.y;
                o[u4 * 4 + 2] += hj * w.z;
                o[u4 * 4 + 3] += hj * w.w;
            }
        }
#pragma unroll
        for (int u4 = 0; u4 < 6; u4++) {
            float4 vv = __ldg((const float4*)(vrow + t * 24 + u4 * 4));
            float4 ov = make_float4(o[u4 * 4 + 0] * vv.x, o[u4 * 4 + 1] * vv.y,
                                    o[u4 * 4 + 2] * vv.z, o[u4 * 4 + 3] * vv.w);
            *(float4*)(orow + t * 24 + u4 * 4) = ov;
        }
    }
}

// ================= mean over N =================
__global__ void colmean_kernel(const float* __restrict__ x, float* __restrict__ xmean) {
    int b = blockIdx.y;
    int c = blockIdx.x * 256 + threadIdx.x;
    const float* p = x + (size_t)b * Nseq * Cdim + c;
    float s = 0.f;
    for (int n = 0; n < Nseq; n++) s += p[(size_t)n * Cdim];
    xmean[b * Cdim + c] = s * (1.0f / 1024.0f);
}

// ================= fw = sigmoid(xmean @ w_proj + b_proj) =================
__global__ void fw_kernel(const float* __restrict__ xmean, const float* __restrict__ w_proj,
                          const float* __restrict__ b_proj, float* __restrict__ fw) {
    __shared__ float xm[768];
    int b = blockIdx.x;
    int c = threadIdx.x;
    xm[c] = xmean[b * Cdim + c];
    __syncthreads();
    float s = b_proj[c];
    for (int k = 0; k < 768; k++) s += xm[k] * w_proj[(size_t)k * 768 + c];
    fw[b * Cdim + c] = 1.f / (1.f + expf(-s));
}

// ================= layernorm =================
__global__ void layernorm_kernel(const float* __restrict__ y, const float* __restrict__ gamma,
                                 const float* __restrict__ beta, float* __restrict__ out) {
    __shared__ float red1[8], red2[8];
    size_t row = blockIdx.x;
    const float* p = y + row * Cdim;
    int tid = threadIdx.x;
    float v[3];
    float s = 0.f;
#pragma unroll
    for (int i = 0; i < 3; i++) { v[i] = p[tid + i * 256]; s += v[i]; }
#pragma unroll
    for (int o = 16; o > 0; o >>= 1) s += __shfl_xor_sync(~0u, s, o);
    int w = tid >> 5, lane = tid & 31;
    if (lane == 0) red1[w] = s;
    __syncthreads();
    s = 0.f;
#pragma unroll
    for (int i = 0; i < 8; i++) s += red1[i];
    float mu = s * (1.0f / 768.0f);
    float vs = 0.f;
#pragma unroll
    for (int i = 0; i < 3; i++) { float d = v[i] - mu; vs += d * d; }
#pragma unroll
    for (int o = 16; o > 0; o >>= 1) vs += __shfl_xor_sync(~0u, vs, o);
    if (lane == 0) red2[w] = vs;
    __syncthreads();
    vs = 0.f;
#pragma unroll
    for (int i = 0; i < 8; i++) vs += red2[i];
    float inv = rsqrtf(vs * (1.0f / 768.0f) + 1e-5f);
#pragma unroll
    for (int i = 0; i < 3; i++) {
        int c = tid + i * 256;
        out[row * Cdim + c] = (v[i] - mu) * inv * gamma[c] + beta[c];
    }
}

// ================= launch =================
extern "C" void kernel_launch(void* const* d_in, const int* in_sizes, int n_in,
                              void* d_out, int out_size) {
    const float* x      = (const float*)d_in[0];
    const float* w_qkv  = (const float*)d_in[1];
    const float* b_qkv  = (const float*)d_in[2];
    const float* w_proj = (const float*)d_in[3];
    const float* b_proj = (const float*)d_in[4];
    const float* gamma  = (const float*)d_in[5];
    const float* beta   = (const float*)d_in[6];
    const float* qe_w1  = (const float*)d_in[7];
    const float* qe_b1  = (const float*)d_in[8];
    const float* qe_w2  = (const float*)d_in[9];
    const float* qe_b2  = (const float*)d_in[10];
    const float* ke_w1  = (const float*)d_in[11];
    const float* ke_b1  = (const float*)d_in[12];
    const float* ke_w2  = (const float*)d_in[13];
    const float* ke_b2  = (const float*)d_in[14];
    const float* gate_params = (const float*)d_in[19];
    const float* ent_params  = (const float*)d_in[20];
    const float* md_w1  = (const float*)d_in[21];
    const float* md_b1  = (const float*)d_in[22];
    const float* md_w2  = (const float*)d_in[23];
    const float* md_b2  = (const float*)d_in[24];
    const float* gumbel = (const float*)d_in[25];
    float* out = (float*)d_out;

    float *qkv, *attn, *qout, *fused, *xmean, *fw;
    cudaGetSymbolAddress((void**)&qkv, g_qkv);
    cudaGetSymbolAddress((void**)&attn, g_attn);
    cudaGetSymbolAddress((void**)&qout, g_qout);
    cudaGetSymbolAddress((void**)&fused, g_fused);
    cudaGetSymbolAddress((void**)&xmean, g_xmean);
    cudaGetSymbolAddress((void**)&fw, g_fw);

    // gate path (depends only on x)
    colmean_kernel<<<dim3(3, 8), 256>>>(x, xmean);
    fw_kernel<<<8, 768>>>(xmean, w_proj, b_proj, fw);
    // qkv = x @ w_qkv + b_qkv
    mma_nn<<<dim3(2304 / 128, 8192 / 128), 256>>>(x, w_qkv, b_qkv, nullptr, qkv,
                                                  768, 768, 2304, 2304);
    // quantum path -> qout (thread per token)
    quantum_kernel2<<<512, 128>>>(qkv, qe_w1, qe_b1, qe_w2, qe_b2,
                                  ke_w1, ke_b1, ke_w2, ke_b2,
                                  gate_params, ent_params,
                                  md_w1, md_b1, md_w2, md_b2, gumbel, qout);
    // classical attention
    mma_scores<<<dim3(1024 / 128, 1024 / 128, 64), 256>>>(qkv, attn);
    softmax_rows<<<65536, 256>>>(attn);
    mma_attnv<<<dim3(1024 / 128, 1, 64), 256>>>(attn, qkv, qout, fw, fused);
    // y = x + fused @ w_proj + b_proj  (reuse qout as y)
    mma_nn<<<dim3(768 / 128, 8192 / 128), 256>>>(fused, w_proj, b_proj, x, qout,
                                                 768, 768, 768, 768);
    // layernorm
    layernorm_kernel<<<8192, 256>>>(qout, gamma, beta, out);
}

// round 5
// speedup vs baseline: 2.9069x; 1.1020x over previous
#include <cuda_runtime.h>
#include <math.h>
#include <stdint.h>

// ---------------- scratch ----------------
#define Bsz 8
#define Nseq 1024
#define Cdim 768
#define Hh 8
#define Dd 96
#define Qq 8

__device__ float g_qkv[Bsz * Nseq * 3 * Cdim];
__device__ float g_qout[Bsz * Nseq * Cdim];
__device__ float g_fused[Bsz * Nseq * Cdim];
__device__ float g_xmean[Bsz * Cdim];
__device__ float g_fw[Bsz * Cdim];

// ---------------- tf32 mma helpers ----------------
__device__ __forceinline__ float to_tf32(float x) {
    uint32_t u;
    asm("cvt.rna.tf32.f32 %0, %1;" : "=r"(u) : "f"(x));
    return __uint_as_float(u);
}

__device__ __forceinline__ void mma_tf32(float* c, const uint32_t* a, const uint32_t* b) {
    asm volatile(
        "mma.sync.aligned.m16n8k8.row.col.f32.tf32.tf32.f32 "
        "{%0,%1,%2,%3}, {%4,%5,%6,%7}, {%8,%9}, {%0,%1,%2,%3};"
        : "+f"(c[0]), "+f"(c[1]), "+f"(c[2]), "+f"(c[3])
        : "r"(a[0]), "r"(a[1]), "r"(a[2]), "r"(a[3]), "r"(b[0]), "r"(b[1]));
}

// ================= tf32 MMA GEMM (NN): C = A@B (+bias)(+resid) =================
__global__ __launch_bounds__(256)
void mma_nn(const float* __restrict__ A, const float* __restrict__ B,
            const float* __restrict__ bias, const float* __restrict__ resid,
            float* __restrict__ C, int K, int lda, int ldb, int ldc) {
    __shared__ float As[2][8][136];
    __shared__ float Bs[2][8][136];
    int tid = threadIdx.x;
    int m0 = blockIdx.y * 128, n0 = blockIdx.x * 128;
    int arow = tid >> 1, ak = (tid & 1) * 4;
    int bk = tid >> 5, bcol = (tid & 31) * 4;
    const float* Ap = A + (size_t)(m0 + arow) * lda + ak;
    const float* Bp = B + (size_t)bk * ldb + n0 + bcol;

    int wid = tid >> 5, lane = tid & 31;
    int wm = (wid >> 2) * 64, wn = (wid & 3) * 32;
    int grp = lane >> 2, tig = lane & 3;
    float acc[4][4][4] = {};

    {
        float4 av = *(const float4*)Ap;
        float4 bv = *(const float4*)Bp;
        As[0][ak + 0][arow] = to_tf32(av.x); As[0][ak + 1][arow] = to_tf32(av.y);
        As[0][ak + 2][arow] = to_tf32(av.z); As[0][ak + 3][arow] = to_tf32(av.w);
        float4 bc = make_float4(to_tf32(bv.x), to_tf32(bv.y), to_tf32(bv.z), to_tf32(bv.w));
        *(float4*)&Bs[0][bk][bcol] = bc;
    }
    __syncthreads();

    int S = K / 8, buf = 0;
    for (int s = 1; s <= S; s++) {
        bool more = (s < S);
        float4 av, bv;
        if (more) {
            av = *(const float4*)(Ap + s * 8);
            bv = *(const float4*)(Bp + (size_t)s * 8 * ldb);
        }
        uint32_t a[4][4], b[4][2];
#pragma unroll
        for (int mi = 0; mi < 4; mi++) {
            int r = wm + mi * 16 + grp;
            a[mi][0] = __float_as_uint(As[buf][tig][r]);
            a[mi][1] = __float_as_uint(As[buf][tig][r + 8]);
            a[mi][2] = __float_as_uint(As[buf][tig + 4][r]);
            a[mi][3] = __float_as_uint(As[buf][tig + 4][r + 8]);
        }
#pragma unroll
        for (int nj = 0; nj < 4; nj++) {
            int c = wn + nj * 8 + grp;
            b[nj][0] = __float_as_uint(Bs[buf][tig][c]);
            b[nj][1] = __float_as_uint(Bs[buf][tig + 4][c]);
        }
#pragma unroll
        for (int mi = 0; mi < 4; mi++)
#pragma unroll
            for (int nj = 0; nj < 4; nj++) mma_tf32(acc[mi][nj], a[mi], b[nj]);
        if (more) {
            As[buf ^ 1][ak + 0][arow] = to_tf32(av.x); As[buf ^ 1][ak + 1][arow] = to_tf32(av.y);
            As[buf ^ 1][ak + 2][arow] = to_tf32(av.z); As[buf ^ 1][ak + 3][arow] = to_tf32(av.w);
            float4 bc = make_float4(to_tf32(bv.x), to_tf32(bv.y), to_tf32(bv.z), to_tf32(bv.w));
            *(float4*)&Bs[buf ^ 1][bk][bcol] = bc;
            __syncthreads();
            buf ^= 1;
        }
    }

#pragma unroll
    for (int nj = 0; nj < 4; nj++) {
        int c = n0 + wn + nj * 8 + tig * 2;
        float bi0 = bias ? bias[c] : 0.f;
        float bi1 = bias ? bias[c + 1] : 0.f;
#pragma unroll
        for (int mi = 0; mi < 4; mi++) {
            size_t r = m0 + wm + mi * 16 + grp;
            float2 lo = make_float2(acc[mi][nj][0] + bi0, acc[mi][nj][1] + bi1);
            float2 hi = make_float2(acc[mi][nj][2] + bi0, acc[mi][nj][3] + bi1);
            if (resid) {
                float2 r0 = *(const float2*)(resid + r * ldc + c);
                float2 r1 = *(const float2*)(resid + (r + 8) * ldc + c);
                lo.x += r0.x; lo.y += r0.y; hi.x += r1.x; hi.y += r1.y;
            }
            *(float2*)(C + r * ldc + c) = lo;
            *(float2*)(C + (r + 8) * ldc + c) = hi;
        }
    }
}

// ================= fused flash attention + gate blend =================
// grid: (8 q-tiles, 64 bh). block 256 = 8 warps x 16 rows.
// smem: Qs[96][136] Ks[96][136] Vs[128][104], tf32 values.
#define LDQ 136
#define LDV 104
#define FLASH_SMEM ((2 * 96 * LDQ + 128 * LDV) * 4)

__global__ __launch_bounds__(256, 1)
void flash_kernel(const float* __restrict__ qkv, const float* __restrict__ qout,
                  const float* __restrict__ fw, float* __restrict__ fused) {
    extern __shared__ float smf[];
    float* Qs = smf;
    float* Ks = smf + 96 * LDQ;
    float* Vs = smf + 2 * 96 * LDQ;

    int tid = threadIdx.x;
    int z = blockIdx.y;
    int b = z >> 3, h = z & 7;
    int q0 = blockIdx.x * 128;
    const float* qbase = qkv + (size_t)b * Nseq * 2304 + h * Dd;
    const float* kbase = qbase + 768;
    const float* vbase = qbase + 1536;

    int lane = tid & 31, wid = tid >> 5;
    int grp = lane >> 2, tig = lane & 3;
    int wrow = wid * 16;

    // Q tile -> smem transposed [d][row]
    for (int i = tid; i < 3072; i += 256) {
        int f4 = i % 24, r = i / 24;
        float4 v = *(const float4*)(qbase + (size_t)(q0 + r) * 2304 + f4 * 4);
        Qs[(f4 * 4 + 0) * LDQ + r] = to_tf32(v.x);
        Qs[(f4 * 4 + 1) * LDQ + r] = to_tf32(v.y);
        Qs[(f4 * 4 + 2) * LDQ + r] = to_tf32(v.z);
        Qs[(f4 * 4 + 3) * LDQ + r] = to_tf32(v.w);
    }

    float o[12][4] = {};
    float m0 = -1e30f, m1 = -1e30f, l0 = 0.f, l1 = 0.f;
    const float scale = 0.10206207261596577f;  // 96^-0.5

    for (int t = 0; t < 8; t++) {
        __syncthreads();
        int kv0 = t * 128;
        for (int i = tid; i < 3072; i += 256) {
            int f4 = i % 24, r = i / 24;
            float4 v = *(const float4*)(kbase + (size_t)(kv0 + r) * 2304 + f4 * 4);
            Ks[(f4 * 4 + 0) * LDQ + r] = to_tf32(v.x);
            Ks[(f4 * 4 + 1) * LDQ + r] = to_tf32(v.y);
            Ks[(f4 * 4 + 2) * LDQ + r] = to_tf32(v.z);
            Ks[(f4 * 4 + 3) * LDQ + r] = to_tf32(v.w);
            float4 w = *(const float4*)(vbase + (size_t)(kv0 + r) * 2304 + f4 * 4);
            float4 wc = make_float4(to_tf32(w.x), to_tf32(w.y), to_tf32(w.z), to_tf32(w.w));
            *(float4*)&Vs[r * LDV + f4 * 4] = wc;
        }
        __syncthreads();

        // S = Q @ K^T for this warp's 16 rows x 128 cols
        float s[16][4] = {};
#pragma unroll
        for (int ks = 0; ks < 12; ks++) {
            uint32_t a[4];
            a[0] = __float_as_uint(Qs[(ks * 8 + tig) * LDQ + wrow + grp]);
            a[1] = __float_as_uint(Qs[(ks * 8 + tig) * LDQ + wrow + grp + 8]);
            a[2] = __float_as_uint(Qs[(ks * 8 + tig + 4) * LDQ + wrow + grp]);
            a[3] = __float_as_uint(Qs[(ks * 8 + tig + 4) * LDQ + wrow + grp + 8]);
#pragma unroll
            for (int n = 0; n < 16; n++) {
                uint32_t bb[2];
                bb[0] = __float_as_uint(Ks[(ks * 8 + tig) * LDQ + n * 8 + grp]);
                bb[1] = __float_as_uint(Ks[(ks * 8 + tig + 4) * LDQ + n * 8 + grp]);
                mma_tf32(s[n], a, bb);
            }
        }

        // online softmax (rows grp and grp+8; reduce over quad lanes)
        float mx0 = -1e30f, mx1 = -1e30f;
#pragma unroll
        for (int n = 0; n < 16; n++) {
            mx0 = fmaxf(mx0, fmaxf(s[n][0], s[n][1]));
            mx1 = fmaxf(mx1, fmaxf(s[n][2], s[n][3]));
        }
        mx0 = fmaxf(mx0, __shfl_xor_sync(~0u, mx0, 1));
        mx0 = fmaxf(mx0, __shfl_xor_sync(~0u, mx0, 2));
        mx1 = fmaxf(mx1, __shfl_xor_sync(~0u, mx1, 1));
        mx1 = fmaxf(mx1, __shfl_xor_sync(~0u, mx1, 2));
        float nm0 = fmaxf(m0, mx0 * scale);
        float nm1 = fmaxf(m1, mx1 * scale);
        float al0 = __expf(m0 - nm0), al1 = __expf(m1 - nm1);
        m0 = nm0; m1 = nm1;
        float sum0 = 0.f, sum1 = 0.f;
#pragma unroll
        for (int n = 0; n < 16; n++) {
            float p0 = __expf(s[n][0] * scale - nm0);
            float p1 = __expf(s[n][1] * scale - nm0);
            float p2 = __expf(s[n][2] * scale - nm1);
            float p3 = __expf(s[n][3] * scale - nm1);
            sum0 += p0 + p1; sum1 += p2 + p3;
            s[n][0] = to_tf32(p0); s[n][1] = to_tf32(p1);
            s[n][2] = to_tf32(p2); s[n][3] = to_tf32(p3);
        }
        sum0 += __shfl_xor_sync(~0u, sum0, 1);
        sum0 += __shfl_xor_sync(~0u, sum0, 2);
        sum1 += __shfl_xor_sync(~0u, sum1, 1);
        sum1 += __shfl_xor_sync(~0u, sum1, 2);
        l0 = l0 * al0 + sum0;
        l1 = l1 * al1 + sum1;
#pragma unroll
        for (int n = 0; n < 12; n++) {
            o[n][0] *= al0; o[n][1] *= al0;
            o[n][2] *= al1; o[n][3] *= al1;
        }

        // O += P @ V  (P acc-layout -> A-frag via quad shuffles)
        int sel = tig & 1;
        int srcb = (lane & ~3) | (tig >> 1);
#pragma unroll
        for (int j = 0; j < 16; j++) {
            float x0 = __shfl_sync(~0u, s[j][0], srcb);
            float x1 = __shfl_sync(~0u, s[j][1], srcb);
            float x2 = __shfl_sync(~0u, s[j][2], srcb);
            float x3 = __shfl_sync(~0u, s[j][3], srcb);
            float y0 = __shfl_sync(~0u, s[j][0], srcb + 2);
            float y1 = __shfl_sync(~0u, s[j][1], srcb + 2);
            float y2 = __shfl_sync(~0u, s[j][2], srcb + 2);
            float y3 = __shfl_sync(~0u, s[j][3], srcb + 2);
            uint32_t a[4];
            a[0] = __float_as_uint(sel ? x1 : x0);
            a[1] = __float_as_uint(sel ? x3 : x2);
            a[2] = __float_as_uint(sel ? y1 : y0);
            a[3] = __float_as_uint(sel ? y3 : y2);
#pragma unroll
            for (int n = 0; n < 12; n++) {
                uint32_t bb[2];
                bb[0] = __float_as_uint(Vs[(j * 8 + tig) * LDV + n * 8 + grp]);
                bb[1] = __float_as_uint(Vs[(j * 8 + tig + 4) * LDV + n * 8 + grp]);
                mma_tf32(o[n], a, bb);
            }
        }
    }

    // epilogue: normalize, gate blend with qout, write fused
    float inv0 = 1.f / l0, inv1 = 1.f / l1;
    int row0 = q0 + wrow + grp;
#pragma unroll
    for (int n = 0; n < 12; n++) {
        int c = n * 8 + tig * 2;
        float f0 = fw[b * Cdim + h * Dd + c];
        float f1 = fw[b * Cdim + h * Dd + c + 1];
        size_t ob0 = ((size_t)b * Nseq + row0) * Cdim + h * Dd + c;
        size_t ob1 = ((size_t)b * Nseq + row0 + 8) * Cdim + h * Dd + c;
        float2 qv0 = *(const float2*)(qout + ob0);
        float2 qv1 = *(const float2*)(qout + ob1);
        float2 lo = make_float2(f0 * qv0.x + (1.f - f0) * o[n][0] * inv0,
                                f1 * qv0.y + (1.f - f1) * o[n][1] * inv0);
        float2 hi = make_float2(f0 * qv1.x + (1.f - f0) * o[n][2] * inv1,
                                f1 * qv1.y + (1.f - f1) * o[n][3] * inv1);
        *(float2*)(fused + ob0) = lo;
        *(float2*)(fused + ob1) = hi;
    }
}

// ================= quantum: thread-per-token =================
__device__ __forceinline__ void embed_token(const float* __restrict__ row,
                                            const float* __restrict__ w1s,
                                            const float* __restrict__ w2s,
                                            const float* __restrict__ b1,
                                            const float* __restrict__ b2,
                                            float* sre, float* sim, bool accum) {
    float acc[64];
#pragma unroll
    for (int j = 0; j < 64; j++) acc[j] = __ldg(&b1[j]);
    const float4* r4 = (const float4*)row;
#pragma unroll 1
    for (int d4 = 0; d4 < 24; d4++) {
        float4 v4 = __ldg(&r4[d4]);
        float vv[4] = {v4.x, v4.y, v4.z, v4.w};
#pragma unroll
        for (int s = 0; s < 4; s++) {
            float vd = vv[s];
            const float4* wr = (const float4*)&w1s[(d4 * 4 + s) * 64];
#pragma unroll
            for (int j4 = 0; j4 < 16; j4++) {
                float4 w = wr[j4];
                acc[j4 * 4 + 0] += vd * w.x;
                acc[j4 * 4 + 1] += vd * w.y;
                acc[j4 * 4 + 2] += vd * w.z;
                acc[j4 * 4 + 3] += vd * w.w;
            }
        }
    }
    float e[16];
#pragma unroll
    for (int i = 0; i < 16; i++) e[i] = __ldg(&b2[i]);
#pragma unroll 4
    for (int j = 0; j < 64; j++) {
        float hj = fmaxf(acc[j], 0.f);
        const float4* wr = (const float4*)&w2s[j * 16];
#pragma unroll
        for (int i4 = 0; i4 < 4; i4++) {
            float4 w = wr[i4];
            e[i4 * 4 + 0] += hj * w.x; e[i4 * 4 + 1] += hj * w.y;
            e[i4 * 4 + 2] += hj * w.z; e[i4 * 4 + 3] += hj * w.w;
        }
    }
    float mx = e[0];
#pragma unroll
    for (int i = 1; i < 8; i++) mx = fmaxf(mx, e[i]);
    float ex[8], s = 0.f;
#pragma unroll
    for (int i = 0; i < 8; i++) { ex[i] = __expf(e[i] - mx); s += ex[i]; }
    float inv = 1.f / s;
#pragma unroll
    for (int i = 0; i < 8; i++) {
        float amp = ex[i] * inv;
        float ph = e[8 + i];
        float cr = amp * __cosf(ph), ci = amp * __sinf(ph);
        if (accum) { sre[i] += cr; sim[i] += ci; }
        else       { sre[i] = cr;  sim[i] = ci; }
    }
}

__global__ __launch_bounds__(128)
void quantum_kernel2(const float* __restrict__ qkv,
                     const float* __restrict__ qe_w1, const float* __restrict__ qe_b1,
                     const float* __restrict__ qe_w2, const float* __restrict__ qe_b2,
                     const float* __restrict__ ke_w1, const float* __restrict__ ke_b1,
                     const float* __restrict__ ke_w2, const float* __restrict__ ke_b2,
                     const float* __restrict__ gate_params, const float* __restrict__ ent_params,
                     const float* __restrict__ md_w1, const float* __restrict__ md_b1,
                     const float* __restrict__ md_w2, const float* __restrict__ md_b2,
                     const float* __restrict__ gumbel, float* __restrict__ qout) {
    __shared__ float w1s[96 * 64];
    __shared__ float w2s[64 * 16];
    __shared__ float gf[2][8], gcz[2][8], gsz[2][8], gs[2][8];

    int tid = threadIdx.x;
    {
        const float4* s1 = (const float4*)qe_w1;
        float4* d1 = (float4*)w1s;
        for (int i = tid; i < 96 * 64 / 4; i += 128) d1[i] = s1[i];
        const float4* s2 = (const float4*)qe_w2;
        float4* d2 = (float4*)w2s;
        for (int i = tid; i < 64 * 16 / 4; i += 128) d2[i] = s2[i];
        if (tid < 16) {
            int l = tid >> 3, i = tid & 7;
            float ry = gate_params[(l * 8 + i) * 3 + 1];
            float rz = gate_params[(l * 8 + i) * 3 + 2];
            gf[l][i] = cosf(0.5f * ry);
            gcz[l][i] = cosf(rz);
            gsz[l][i] = sinf(rz);
        } else if (tid < 30) {
            int t = tid - 16, l = t / 7, i = t % 7;
            gs[l][i + 1] = 1.f / (1.f + expf(-ent_params[l * 7 + i]));
        }
    }
    __syncthreads();

    int wg = blockIdx.x * 128 + tid;
    int b = wg >> 13, h = (wg >> 10) & 7, n = wg & 1023;
    const float* base = qkv + (size_t)(b * Nseq + n) * 2304 + h * Dd;

    float sre[8], sim[8];
    embed_token(base, w1s, w2s, qe_b1, qe_b2, sre, sim, false);
    __syncthreads();
    {
        const float4* s1 = (const float4*)ke_w1;
        float4* d1 = (float4*)w1s;
        for (int i = tid; i < 96 * 64 / 4; i += 128) d1[i] = s1[i];
        const float4* s2 = (const float4*)ke_w2;
        float4* d2 = (float4*)w2s;
        for (int i = tid; i < 64 * 16 / 4; i += 128) d2[i] = s2[i];
    }
    __syncthreads();
    embed_token(base + 768, w1s, w2s, ke_b1, ke_b2, sre, sim, true);

#pragma unroll
    for (int l = 0; l < 2; l++) {
#pragma unroll
        for (int i = 0; i < 8; i++) {
            float nr = sre[i] * gcz[l][i] - sim[i] * gsz[l][i];
            float ni = sre[i] * gsz[l][i] + sim[i] * gcz[l][i];
            sre[i] = nr * gf[l][i];
            sim[i] = ni * gf[l][i];
        }
#pragma unroll
        for (int i = 7; i >= 1; i--) {
            sre[i] += gs[l][i] * sre[i - 1];
            sim[i] += gs[l][i] * sim[i - 1];
        }
    }

    float p[8], mx = -1e30f;
#pragma unroll
    for (int i = 0; i < 8; i++) { p[i] = sre[i] * sre[i] + sim[i] * sim[i]; mx = fmaxf(mx, p[i]); }
    float ssum = 0.f;
#pragma unroll
    for (int i = 0; i < 8; i++) { p[i] = __expf(p[i] - mx); ssum += p[i]; }
    float sinv = 1.f / ssum;
    float4 g0 = __ldg((const float4*)(gumbel + (size_t)wg * 8));
    float4 g1 = __ldg((const float4*)(gumbel + (size_t)wg * 8 + 4));
    float gv[8] = {g0.x, g0.y, g0.z, g0.w, g1.x, g1.y, g1.z, g1.w};
    float lg[8], mx2 = -1e30f;
#pragma unroll
    for (int i = 0; i < 8; i++) {
        lg[i] = 2.f * (__logf(p[i] * sinv + 1e-10f) + gv[i]);
        mx2 = fmaxf(mx2, lg[i]);
    }
    float meas[8], msum = 0.f;
#pragma unroll
    for (int i = 0; i < 8; i++) { meas[i] = __expf(lg[i] - mx2); msum += meas[i]; }
    float minv = 1.f / msum;
#pragma unroll
    for (int i = 0; i < 8; i++) meas[i] *= minv;

    __syncthreads();
    {
        const float4* s1 = (const float4*)md_w2;
        float4* d1 = (float4*)w1s;
        for (int i = tid; i < 64 * 96 / 4; i += 128) d1[i] = s1[i];
        const float4* s2 = (const float4*)md_w1;
        float4* d2 = (float4*)w2s;
        for (int i = tid; i < 8 * 64 / 4; i += 128) d2[i] = s2[i];
    }
    __syncthreads();

    float acc[64];
#pragma unroll
    for (int j = 0; j < 64; j++) acc[j] = __ldg(&md_b1[j]);
#pragma unroll
    for (int i = 0; i < 8; i++) {
        float mi = meas[i];
        const float4* wr = (const float4*)&w2s[i * 64];
#pragma unroll
        for (int j4 = 0; j4 < 16; j4++) {
            float4 w = wr[j4];
            acc[j4 * 4 + 0] += mi * w.x;
            acc[j4 * 4 + 1] += mi * w.y;
            acc[j4 * 4 + 2] += mi * w.z;
            acc[j4 * 4 + 3] += mi * w.w;
        }
    }
#pragma unroll
    for (int j = 0; j < 64; j++) acc[j] = fmaxf(acc[j], 0.f);

    const float* vrow = base + 1536;
    float* orow = qout + (size_t)(b * Nseq + n) * Cdim + h * Dd;
#pragma unroll 1
    for (int t = 0; t < 4; t++) {
        float o[24];
#pragma unroll
        for (int u = 0; u < 24; u++) o[u] = __ldg(&md_b2[t * 24 + u]);
#pragma unroll 4
        for (int j = 0; j < 64; j++) {
            float hj = acc[j];
            const float4* wr = (const float4*)&w1s[j * 96 + t * 24];
#pragma unroll
            for (int u4 = 0; u4 < 6; u4++) {
                float4 w = wr[u4];
                o[u4 * 4 + 0] += hj * w.x;
                o[u4 * 4 + 1] += hj * w.y;
                o[u4 * 4 + 2] += hj * w.z;
                o[u4 * 4 + 3] += hj * w.w;
            }
        }
#pragma unroll
        for (int u4 = 0; u4 < 6; u4++) {
            float4 vv = __ldg((const float4*)(vrow + t * 24 + u4 * 4));
            float4 ov = make_float4(o[u4 * 4 + 0] * vv.x, o[u4 * 4 + 1] * vv.y,
                                    o[u4 * 4 + 2] * vv.z, o[u4 * 4 + 3] * vv.w);
            *(float4*)(orow + t * 24 + u4 * 4) = ov;
        }
    }
}

// ================= mean over N =================
__global__ void colmean_kernel(const float* __restrict__ x, float* __restrict__ xmean) {
    int b = blockIdx.y;
    int c = blockIdx.x * 256 + threadIdx.x;
    const float* p = x + (size_t)b * Nseq * Cdim + c;
    float s = 0.f;
    for (int n = 0; n < Nseq; n++) s += p[(size_t)n * Cdim];
    xmean[b * Cdim + c] = s * (1.0f / 1024.0f);
}

// ================= fw = sigmoid(xmean @ w_proj + b_proj) =================
__global__ void fw_kernel(const float* __restrict__ xmean, const float* __restrict__ w_proj,
                          const float* __restrict__ b_proj, float* __restrict__ fw) {
    __shared__ float xm[768];
    int b = blockIdx.x;
    int c = threadIdx.x;
    xm[c] = xmean[b * Cdim + c];
    __syncthreads();
    float s = b_proj[c];
    for (int k = 0; k < 768; k++) s += xm[k] * w_proj[(size_t)k * 768 + c];
    fw[b * Cdim + c] = 1.f / (1.f + expf(-s));
}

// ================= layernorm =================
__global__ void layernorm_kernel(const float* __restrict__ y, const float* __restrict__ gamma,
                                 const float* __restrict__ beta, float* __restrict__ out) {
    __shared__ float red1[8], red2[8];
    size_t row = blockIdx.x;
    const float* p = y + row * Cdim;
    int tid = threadIdx.x;
    float v[3];
    float s = 0.f;
#pragma unroll
    for (int i = 0; i < 3; i++) { v[i] = p[tid + i * 256]; s += v[i]; }
#pragma unroll
    for (int o = 16; o > 0; o >>= 1) s += __shfl_xor_sync(~0u, s, o);
    int w = tid >> 5, lane = tid & 31;
    if (lane == 0) red1[w] = s;
    __syncthreads();
    s = 0.f;
#pragma unroll
    for (int i = 0; i < 8; i++) s += red1[i];
    float mu = s * (1.0f / 768.0f);
    float vs = 0.f;
#pragma unroll
    for (int i = 0; i < 3; i++) { float d = v[i] - mu; vs += d * d; }
#pragma unroll
    for (int o = 16; o > 0; o >>= 1) vs += __shfl_xor_sync(~0u, vs, o);
    if (lane == 0) red2[w] = vs;
    __syncthreads();
    vs = 0.f;
#pragma unroll
    for (int i = 0; i < 8; i++) vs += red2[i];
    float inv = rsqrtf(vs * (1.0f / 768.0f) + 1e-5f);
#pragma unroll
    for (int i = 0; i < 3; i++) {
        int c = tid + i * 256;
        out[row * Cdim + c] = (v[i] - mu) * inv * gamma[c] + beta[c];
    }
}

// ================= launch =================
extern "C" void kernel_launch(void* const* d_in, const int* in_sizes, int n_in,
                              void* d_out, int out_size) {
    const float* x      = (const float*)d_in[0];
    const float* w_qkv  = (const float*)d_in[1];
    const float* b_qkv  = (const float*)d_in[2];
    const float* w_proj = (const float*)d_in[3];
    const float* b_proj = (const float*)d_in[4];
    const float* gamma  = (const float*)d_in[5];
    const float* beta   = (const float*)d_in[6];
    const float* qe_w1  = (const float*)d_in[7];
    const float* qe_b1  = (const float*)d_in[8];
    const float* qe_w2  = (const float*)d_in[9];
    const float* qe_b2  = (const float*)d_in[10];
    const float* ke_w1  = (const float*)d_in[11];
    const float* ke_b1  = (const float*)d_in[12];
    const float* ke_w2  = (const float*)d_in[13];
    const float* ke_b2  = (const float*)d_in[14];
    const float* gate_params = (const float*)d_in[19];
    const float* ent_params  = (const float*)d_in[20];
    const float* md_w1  = (const float*)d_in[21];
    const float* md_b1  = (const float*)d_in[22];
    const float* md_w2  = (const float*)d_in[23];
    const float* md_b2  = (const float*)d_in[24];
    const float* gumbel = (const float*)d_in[25];
    float* out = (float*)d_out;

    float *qkv, *qout, *fused, *xmean, *fw;
    cudaGetSymbolAddress((void**)&qkv, g_qkv);
    cudaGetSymbolAddress((void**)&qout, g_qout);
    cudaGetSymbolAddress((void**)&fused, g_fused);
    cudaGetSymbolAddress((void**)&xmean, g_xmean);
    cudaGetSymbolAddress((void**)&fw, g_fw);

    cudaFuncSetAttribute(flash_kernel, cudaFuncAttributeMaxDynamicSharedMemorySize, FLASH_SMEM);

    // gate path (depends only on x)
    colmean_kernel<<<dim3(3, 8), 256>>>(x, xmean);
    fw_kernel<<<8, 768>>>(xmean, w_proj, b_proj, fw);
    // qkv = x @ w_qkv + b_qkv
    mma_nn<<<dim3(2304 / 128, 8192 / 128), 256>>>(x, w_qkv, b_qkv, nullptr, qkv,
                                                  768, 768, 2304, 2304);
    // quantum path -> qout (thread per token)
    quantum_kernel2<<<512, 128>>>(qkv, qe_w1, qe_b1, qe_w2, qe_b2,
                                  ke_w1, ke_b1, ke_w2, ke_b2,
                                  gate_params, ent_params,
                                  md_w1, md_b1, md_w2, md_b2, gumbel, qout);
    // fused classical attention + gate blend -> fused
    flash_kernel<<<dim3(8, 64), 256, FLASH_SMEM>>>(qkv, qout, fw, fused);
    // y = x + fused @ w_proj + b_proj  (reuse qout as y)
    mma_nn<<<dim3(768 / 128, 8192 / 128), 256>>>(fused, w_proj, b_proj, x, qout,
                                                 768, 768, 768, 768);
    // layernorm
    layernorm_kernel<<<8192, 256>>>(qout, gamma, beta, out);
}

// round 6
// speedup vs baseline: 3.4730x; 1.1947x over previous
#include <cuda_runtime.h>
#include <math.h>
#include <stdint.h>

// ---------------- scratch ----------------
#define Bsz 8
#define Nseq 1024
#define Cdim 768
#define Hh 8
#define Dd 96
#define Qq 8
#define NTOK (Bsz * Hh * Nseq)   // 65536, ordered m=(b,n,h)

__device__ float g_qkv[Bsz * Nseq * 3 * Cdim];
__device__ float g_qout[Bsz * Nseq * Cdim];
__device__ float g_fused[Bsz * Nseq * Cdim];
__device__ float g_xmean[Bsz * Cdim];
__device__ float g_fw[Bsz * Cdim];
__device__ float g_hq[NTOK * 64];
__device__ float g_hk[NTOK * 64];
__device__ float g_meas[NTOK * 8];

// ---------------- tf32 mma helpers ----------------
__device__ __forceinline__ float to_tf32(float x) {
    uint32_t u;
    asm("cvt.rna.tf32.f32 %0, %1;" : "=r"(u) : "f"(x));
    return __uint_as_float(u);
}

__device__ __forceinline__ void mma_tf32(float* c, const uint32_t* a, const uint32_t* b) {
    asm volatile(
        "mma.sync.aligned.m16n8k8.row.col.f32.tf32.tf32.f32 "
        "{%0,%1,%2,%3}, {%4,%5,%6,%7}, {%8,%9}, {%0,%1,%2,%3};"
        : "+f"(c[0]), "+f"(c[1]), "+f"(c[2]), "+f"(c[3])
        : "r"(a[0]), "r"(a[1]), "r"(a[2]), "r"(a[3]), "r"(b[0]), "r"(b[1]));
}

// ================= tf32 MMA GEMM (NN): C = A@B (+bias)(+resid) =================
__global__ __launch_bounds__(256)
void mma_nn(const float* __restrict__ A, const float* __restrict__ B,
            const float* __restrict__ bias, const float* __restrict__ resid,
            float* __restrict__ C, int K, int lda, int ldb, int ldc) {
    __shared__ float As[2][8][136];
    __shared__ float Bs[2][8][136];
    int tid = threadIdx.x;
    int m0 = blockIdx.y * 128, n0 = blockIdx.x * 128;
    int arow = tid >> 1, ak = (tid & 1) * 4;
    int bk = tid >> 5, bcol = (tid & 31) * 4;
    const float* Ap = A + (size_t)(m0 + arow) * lda + ak;
    const float* Bp = B + (size_t)bk * ldb + n0 + bcol;

    int wid = tid >> 5, lane = tid & 31;
    int wm = (wid >> 2) * 64, wn = (wid & 3) * 32;
    int grp = lane >> 2, tig = lane & 3;
    float acc[4][4][4] = {};

    {
        float4 av = *(const float4*)Ap;
        float4 bv = *(const float4*)Bp;
        As[0][ak + 0][arow] = to_tf32(av.x); As[0][ak + 1][arow] = to_tf32(av.y);
        As[0][ak + 2][arow] = to_tf32(av.z); As[0][ak + 3][arow] = to_tf32(av.w);
        float4 bc = make_float4(to_tf32(bv.x), to_tf32(bv.y), to_tf32(bv.z), to_tf32(bv.w));
        *(float4*)&Bs[0][bk][bcol] = bc;
    }
    __syncthreads();

    int S = K / 8, buf = 0;
    for (int s = 1; s <= S; s++) {
        bool more = (s < S);
        float4 av, bv;
        if (more) {
            av = *(const float4*)(Ap + s * 8);
            bv = *(const float4*)(Bp + (size_t)s * 8 * ldb);
        }
        uint32_t a[4][4], b[4][2];
#pragma unroll
        for (int mi = 0; mi < 4; mi++) {
            int r = wm + mi * 16 + grp;
            a[mi][0] = __float_as_uint(As[buf][tig][r]);
            a[mi][1] = __float_as_uint(As[buf][tig][r + 8]);
            a[mi][2] = __float_as_uint(As[buf][tig + 4][r]);
            a[mi][3] = __float_as_uint(As[buf][tig + 4][r + 8]);
        }
#pragma unroll
        for (int nj = 0; nj < 4; nj++) {
            int c = wn + nj * 8 + grp;
            b[nj][0] = __float_as_uint(Bs[buf][tig][c]);
            b[nj][1] = __float_as_uint(Bs[buf][tig + 4][c]);
        }
#pragma unroll
        for (int mi = 0; mi < 4; mi++)
#pragma unroll
            for (int nj = 0; nj < 4; nj++) mma_tf32(acc[mi][nj], a[mi], b[nj]);
        if (more) {
            As[buf ^ 1][ak + 0][arow] = to_tf32(av.x); As[buf ^ 1][ak + 1][arow] = to_tf32(av.y);
            As[buf ^ 1][ak + 2][arow] = to_tf32(av.z); As[buf ^ 1][ak + 3][arow] = to_tf32(av.w);
            float4 bc = make_float4(to_tf32(bv.x), to_tf32(bv.y), to_tf32(bv.z), to_tf32(bv.w));
            *(float4*)&Bs[buf ^ 1][bk][bcol] = bc;
            __syncthreads();
            buf ^= 1;
        }
    }

#pragma unroll
    for (int nj = 0; nj < 4; nj++) {
        int c = n0 + wn + nj * 8 + tig * 2;
        float bi0 = bias ? bias[c] : 0.f;
        float bi1 = bias ? bias[c + 1] : 0.f;
#pragma unroll
        for (int mi = 0; mi < 4; mi++) {
            size_t r = m0 + wm + mi * 16 + grp;
            float2 lo = make_float2(acc[mi][nj][0] + bi0, acc[mi][nj][1] + bi1);
            float2 hi = make_float2(acc[mi][nj][2] + bi0, acc[mi][nj][3] + bi1);
            if (resid) {
                float2 r0 = *(const float2*)(resid + r * ldc + c);
                float2 r1 = *(const float2*)(resid + (r + 8) * ldc + c);
                lo.x += r0.x; lo.y += r0.y; hi.x += r1.x; hi.y += r1.y;
            }
            *(float2*)(C + r * ldc + c) = lo;
            *(float2*)(C + (r + 8) * ldc + c) = hi;
        }
    }
}

// ================= fused flash attention + gate blend =================
#define LDQ 136
#define LDV 104
#define FLASH_SMEM ((2 * 96 * LDQ + 128 * LDV) * 4)

__global__ __launch_bounds__(256, 1)
void flash_kernel(const float* __restrict__ qkv, const float* __restrict__ qout,
                  const float* __restrict__ fw, float* __restrict__ fused) {
    extern __shared__ float smf[];
    float* Qs = smf;
    float* Ks = smf + 96 * LDQ;
    float* Vs = smf + 2 * 96 * LDQ;

    int tid = threadIdx.x;
    int z = blockIdx.y;
    int b = z >> 3, h = z & 7;
    int q0 = blockIdx.x * 128;
    const float* qbase = qkv + (size_t)b * Nseq * 2304 + h * Dd;
    const float* kbase = qbase + 768;
    const float* vbase = qbase + 1536;

    int lane = tid & 31, wid = tid >> 5;
    int grp = lane >> 2, tig = lane & 3;
    int wrow = wid * 16;

    for (int i = tid; i < 3072; i += 256) {
        int f4 = i % 24, r = i / 24;
        float4 v = *(const float4*)(qbase + (size_t)(q0 + r) * 2304 + f4 * 4);
        Qs[(f4 * 4 + 0) * LDQ + r] = to_tf32(v.x);
        Qs[(f4 * 4 + 1) * LDQ + r] = to_tf32(v.y);
        Qs[(f4 * 4 + 2) * LDQ + r] = to_tf32(v.z);
        Qs[(f4 * 4 + 3) * LDQ + r] = to_tf32(v.w);
    }

    float o[12][4] = {};
    float m0 = -1e30f, m1 = -1e30f, l0 = 0.f, l1 = 0.f;
    const float scale = 0.10206207261596577f;

    for (int t = 0; t < 8; t++) {
        __syncthreads();
        int kv0 = t * 128;
        for (int i = tid; i < 3072; i += 256) {
            int f4 = i % 24, r = i / 24;
            float4 v = *(const float4*)(kbase + (size_t)(kv0 + r) * 2304 + f4 * 4);
            Ks[(f4 * 4 + 0) * LDQ + r] = to_tf32(v.x);
            Ks[(f4 * 4 + 1) * LDQ + r] = to_tf32(v.y);
            Ks[(f4 * 4 + 2) * LDQ + r] = to_tf32(v.z);
            Ks[(f4 * 4 + 3) * LDQ + r] = to_tf32(v.w);
            float4 w = *(const float4*)(vbase + (size_t)(kv0 + r) * 2304 + f4 * 4);
            float4 wc = make_float4(to_tf32(w.x), to_tf32(w.y), to_tf32(w.z), to_tf32(w.w));
            *(float4*)&Vs[r * LDV + f4 * 4] = wc;
        }
        __syncthreads();

        float s[16][4] = {};
#pragma unroll
        for (int ks = 0; ks < 12; ks++) {
            uint32_t a[4];
            a[0] = __float_as_uint(Qs[(ks * 8 + tig) * LDQ + wrow + grp]);
            a[1] = __float_as_uint(Qs[(ks * 8 + tig) * LDQ + wrow + grp + 8]);
            a[2] = __float_as_uint(Qs[(ks * 8 + tig + 4) * LDQ + wrow + grp]);
            a[3] = __float_as_uint(Qs[(ks * 8 + tig + 4) * LDQ + wrow + grp + 8]);
#pragma unroll
            for (int n = 0; n < 16; n++) {
                uint32_t bb[2];
                bb[0] = __float_as_uint(Ks[(ks * 8 + tig) * LDQ + n * 8 + grp]);
                bb[1] = __float_as_uint(Ks[(ks * 8 + tig + 4) * LDQ + n * 8 + grp]);
                mma_tf32(s[n], a, bb);
            }
        }

        float mx0 = -1e30f, mx1 = -1e30f;
#pragma unroll
        for (int n = 0; n < 16; n++) {
            mx0 = fmaxf(mx0, fmaxf(s[n][0], s[n][1]));
            mx1 = fmaxf(mx1, fmaxf(s[n][2], s[n][3]));
        }
        mx0 = fmaxf(mx0, __shfl_xor_sync(~0u, mx0, 1));
        mx0 = fmaxf(mx0, __shfl_xor_sync(~0u, mx0, 2));
        mx1 = fmaxf(mx1, __shfl_xor_sync(~0u, mx1, 1));
        mx1 = fmaxf(mx1, __shfl_xor_sync(~0u, mx1, 2));
        float nm0 = fmaxf(m0, mx0 * scale);
        float nm1 = fmaxf(m1, mx1 * scale);
        float al0 = __expf(m0 - nm0), al1 = __expf(m1 - nm1);
        m0 = nm0; m1 = nm1;
        float sum0 = 0.f, sum1 = 0.f;
#pragma unroll
        for (int n = 0; n < 16; n++) {
            float p0 = __expf(s[n][0] * scale - nm0);
            float p1 = __expf(s[n][1] * scale - nm0);
            float p2 = __expf(s[n][2] * scale - nm1);
            float p3 = __expf(s[n][3] * scale - nm1);
            sum0 += p0 + p1; sum1 += p2 + p3;
            s[n][0] = to_tf32(p0); s[n][1] = to_tf32(p1);
            s[n][2] = to_tf32(p2); s[n][3] = to_tf32(p3);
        }
        sum0 += __shfl_xor_sync(~0u, sum0, 1);
        sum0 += __shfl_xor_sync(~0u, sum0, 2);
        sum1 += __shfl_xor_sync(~0u, sum1, 1);
        sum1 += __shfl_xor_sync(~0u, sum1, 2);
        l0 = l0 * al0 + sum0;
        l1 = l1 * al1 + sum1;
#pragma unroll
        for (int n = 0; n < 12; n++) {
            o[n][0] *= al0; o[n][1] *= al0;
            o[n][2] *= al1; o[n][3] *= al1;
        }

        int sel = tig & 1;
        int srcb = (lane & ~3) | (tig >> 1);
#pragma unroll
        for (int j = 0; j < 16; j++) {
            float x0 = __shfl_sync(~0u, s[j][0], srcb);
            float x1 = __shfl_sync(~0u, s[j][1], srcb);
            float x2 = __shfl_sync(~0u, s[j][2], srcb);
            float x3 = __shfl_sync(~0u, s[j][3], srcb);
            float y0 = __shfl_sync(~0u, s[j][0], srcb + 2);
            float y1 = __shfl_sync(~0u, s[j][1], srcb + 2);
            float y2 = __shfl_sync(~0u, s[j][2], srcb + 2);
            float y3 = __shfl_sync(~0u, s[j][3], srcb + 2);
            uint32_t a[4];
            a[0] = __float_as_uint(sel ? x1 : x0);
            a[1] = __float_as_uint(sel ? x3 : x2);
            a[2] = __float_as_uint(sel ? y1 : y0);
            a[3] = __float_as_uint(sel ? y3 : y2);
#pragma unroll
            for (int n = 0; n < 12; n++) {
                uint32_t bb[2];
                bb[0] = __float_as_uint(Vs[(j * 8 + tig) * LDV + n * 8 + grp]);
                bb[1] = __float_as_uint(Vs[(j * 8 + tig + 4) * LDV + n * 8 + grp]);
                mma_tf32(o[n], a, bb);
            }
        }
    }

    float inv0 = 1.f / l0, inv1 = 1.f / l1;
    int row0 = q0 + wrow + grp;
#pragma unroll
    for (int n = 0; n < 12; n++) {
        int c = n * 8 + tig * 2;
        float f0 = fw[b * Cdim + h * Dd + c];
        float f1 = fw[b * Cdim + h * Dd + c + 1];
        size_t ob0 = ((size_t)b * Nseq + row0) * Cdim + h * Dd + c;
        size_t ob1 = ((size_t)b * Nseq + row0 + 8) * Cdim + h * Dd + c;
        float2 qv0 = *(const float2*)(qout + ob0);
        float2 qv1 = *(const float2*)(qout + ob1);
        float2 lo = make_float2(f0 * qv0.x + (1.f - f0) * o[n][0] * inv0,
                                f1 * qv0.y + (1.f - f1) * o[n][1] * inv0);
        float2 hi = make_float2(f0 * qv1.x + (1.f - f0) * o[n][2] * inv1,
                                f1 * qv1.y + (1.f - f1) * o[n][3] * inv1);
        *(float2*)(fused + ob0) = lo;
        *(float2*)(fused + ob1) = hi;
    }
}

// ================= quantum embed GEMM: H = relu(A @ W1 + b1) =================
// A[m,d] = qkv[(m>>3)*2304 + qk_off + (m&7)*96 + d], M=65536, K=96, N=64.
__global__ __launch_bounds__(256)
void embed_gemm(const float* __restrict__ qkv, int qk_off,
                const float* __restrict__ W1, const float* __restrict__ b1,
                float* __restrict__ H) {
    __shared__ float As[2][8][136];
    __shared__ float Bs[96][72];
    int tid = threadIdx.x;
    int m0 = blockIdx.x * 128;

    // stage full W1 [96][64] (tf32)
    for (int i = tid; i < 96 * 16; i += 256) {
        int d = i >> 4, n4 = i & 15;
        float4 w = ((const float4*)W1)[i];
        float4 wc = make_float4(to_tf32(w.x), to_tf32(w.y), to_tf32(w.z), to_tf32(w.w));
        *(float4*)&Bs[d][n4 * 4] = wc;
    }

    int arow = tid >> 1, ak = (tid & 1) * 4;
    const float* Ap = qkv + (size_t)((m0 + arow) >> 3) * 2304 + qk_off + (arow & 7) * 96 + ak;

    int wid = tid >> 5, lane = tid & 31;
    int wm = (wid >> 2) * 64, wn = (wid & 3) * 16;
    int grp = lane >> 2, tig = lane & 3;
    float acc[4][2][4] = {};

    {
        float4 av = *(const float4*)Ap;
        As[0][ak + 0][arow] = to_tf32(av.x); As[0][ak + 1][arow] = to_tf32(av.y);
        As[0][ak + 2][arow] = to_tf32(av.z); As[0][ak + 3][arow] = to_tf32(av.w);
    }
    __syncthreads();

    int buf = 0;
    for (int s = 1; s <= 12; s++) {
        bool more = (s < 12);
        float4 av;
        if (more) av = *(const float4*)(Ap + s * 8);
        int k0 = (s - 1) * 8;
        uint32_t a[4][4], b[2][2];
#pragma unroll
        for (int mi = 0; mi < 4; mi++) {
            int r = wm + mi * 16 + grp;
            a[mi][0] = __float_as_uint(As[buf][tig][r]);
            a[mi][1] = __float_as_uint(As[buf][tig][r + 8]);
            a[mi][2] = __float_as_uint(As[buf][tig + 4][r]);
            a[mi][3] = __float_as_uint(As[buf][tig + 4][r + 8]);
        }
#pragma unroll
        for (int nj = 0; nj < 2; nj++) {
            int c = wn + nj * 8 + grp;
            b[nj][0] = __float_as_uint(Bs[k0 + tig][c]);
            b[nj][1] = __float_as_uint(Bs[k0 + tig + 4][c]);
        }
#pragma unroll
        for (int mi = 0; mi < 4; mi++)
#pragma unroll
            for (int nj = 0; nj < 2; nj++) mma_tf32(acc[mi][nj], a[mi], b[nj]);
        if (more) {
            As[buf ^ 1][ak + 0][arow] = to_tf32(av.x); As[buf ^ 1][ak + 1][arow] = to_tf32(av.y);
            As[buf ^ 1][ak + 2][arow] = to_tf32(av.z); As[buf ^ 1][ak + 3][arow] = to_tf32(av.w);
            __syncthreads();
            buf ^= 1;
        }
    }

#pragma unroll
    for (int nj = 0; nj < 2; nj++) {
        int c = wn + nj * 8 + tig * 2;
        float bi0 = __ldg(&b1[c]), bi1 = __ldg(&b1[c + 1]);
#pragma unroll
        for (int mi = 0; mi < 4; mi++) {
            size_t r = m0 + wm + mi * 16 + grp;
            float2 lo = make_float2(fmaxf(acc[mi][nj][0] + bi0, 0.f), fmaxf(acc[mi][nj][1] + bi1, 0.f));
            float2 hi = make_float2(fmaxf(acc[mi][nj][2] + bi0, 0.f), fmaxf(acc[mi][nj][3] + bi1, 0.f));
            *(float2*)(H + r * 64 + c) = lo;
            *(float2*)(H + (r + 8) * 64 + c) = hi;
        }
    }
}

// ================= quantum middle: e -> state -> meas =================
__global__ __launch_bounds__(128)
void quantum_mid(const float* __restrict__ Hq, const float* __restrict__ Hk,
                 const float* __restrict__ qe_w2, const float* __restrict__ qe_b2,
                 const float* __restrict__ ke_w2, const float* __restrict__ ke_b2,
                 const float* __restrict__ gate_params, const float* __restrict__ ent_params,
                 const float* __restrict__ gumbel, float* __restrict__ meas_out) {
    __shared__ float w2q[1024], w2k[1024];
    __shared__ float gf[2][8], gcz[2][8], gsz[2][8], gs[2][8];
    int tid = threadIdx.x;
    for (int i = tid; i < 256; i += 128) {
        ((float4*)w2q)[i] = ((const float4*)qe_w2)[i];
        ((float4*)w2k)[i] = ((const float4*)ke_w2)[i];
    }
    if (tid < 16) {
        int l = tid >> 3, i = tid & 7;
        float ry = gate_params[(l * 8 + i) * 3 + 1];
        float rz = gate_params[(l * 8 + i) * 3 + 2];
        gf[l][i] = cosf(0.5f * ry);
        gcz[l][i] = cosf(rz);
        gsz[l][i] = sinf(rz);
    } else if (tid < 30) {
        int t = tid - 16, l = t / 7, i = t % 7;
        gs[l][i + 1] = 1.f / (1.f + expf(-ent_params[l * 7 + i]));
    }
    __syncthreads();

    int m = blockIdx.x * 128 + tid;
    float sre[8], sim[8];

    // q embed tail: e = Hq_row @ w2 + b2, then amp/phase
#pragma unroll
    for (int pass = 0; pass < 2; pass++) {
        const float* Hrow = (pass == 0 ? Hq : Hk) + (size_t)m * 64;
        const float* w2 = (pass == 0 ? w2q : w2k);
        const float* b2 = (pass == 0 ? qe_b2 : ke_b2);
        float e[16];
#pragma unroll
        for (int i = 0; i < 16; i++) e[i] = __ldg(&b2[i]);
        const float4* h4 = (const float4*)Hrow;
#pragma unroll
        for (int j4 = 0; j4 < 16; j4++) {
            float4 hv = h4[j4];
            float hs[4] = {hv.x, hv.y, hv.z, hv.w};
#pragma unroll
            for (int s = 0; s < 4; s++) {
                float hj = hs[s];
                const float4* wr = (const float4*)&w2[(j4 * 4 + s) * 16];
#pragma unroll
                for (int i4 = 0; i4 < 4; i4++) {
                    float4 w = wr[i4];
                    e[i4 * 4 + 0] += hj * w.x; e[i4 * 4 + 1] += hj * w.y;
                    e[i4 * 4 + 2] += hj * w.z; e[i4 * 4 + 3] += hj * w.w;
                }
            }
        }
        float mx = e[0];
#pragma unroll
        for (int i = 1; i < 8; i++) mx = fmaxf(mx, e[i]);
        float ex[8], ssum = 0.f;
#pragma unroll
        for (int i = 0; i < 8; i++) { ex[i] = __expf(e[i] - mx); ssum += ex[i]; }
        float inv = 1.f / ssum;
#pragma unroll
        for (int i = 0; i < 8; i++) {
            float amp = ex[i] * inv;
            float cr = amp * __cosf(e[8 + i]), ci = amp * __sinf(e[8 + i]);
            if (pass == 0) { sre[i] = cr; sim[i] = ci; }
            else           { sre[i] += cr; sim[i] += ci; }
        }
    }

#pragma unroll
    for (int l = 0; l < 2; l++) {
#pragma unroll
        for (int i = 0; i < 8; i++) {
            float nr = sre[i] * gcz[l][i] - sim[i] * gsz[l][i];
            float ni = sre[i] * gsz[l][i] + sim[i] * gcz[l][i];
            sre[i] = nr * gf[l][i];
            sim[i] = ni * gf[l][i];
        }
#pragma unroll
        for (int i = 7; i >= 1; i--) {
            sre[i] += gs[l][i] * sre[i - 1];
            sim[i] += gs[l][i] * sim[i - 1];
        }
    }

    float p[8], mx = -1e30f;
#pragma unroll
    for (int i = 0; i < 8; i++) { p[i] = sre[i] * sre[i] + sim[i] * sim[i]; mx = fmaxf(mx, p[i]); }
    float ssum = 0.f;
#pragma unroll
    for (int i = 0; i < 8; i++) { p[i] = __expf(p[i] - mx); ssum += p[i]; }
    float sinv = 1.f / ssum;
    // m ordered (b,n,h); gumbel ordered (b,h,n,q)
    int b = m >> 13, n = (m >> 3) & 1023, h = m & 7;
    size_t goff = (size_t)(((b * 8 + h) << 10) + n) * 8;
    float4 g0 = __ldg((const float4*)(gumbel + goff));
    float4 g1 = __ldg((const float4*)(gumbel + goff + 4));
    float gv[8] = {g0.x, g0.y, g0.z, g0.w, g1.x, g1.y, g1.z, g1.w};
    float lg[8], mx2 = -1e30f;
#pragma unroll
    for (int i = 0; i < 8; i++) {
        lg[i] = 2.f * (__logf(p[i] * sinv + 1e-10f) + gv[i]);
        mx2 = fmaxf(mx2, lg[i]);
    }
    float meas[8], msum = 0.f;
#pragma unroll
    for (int i = 0; i < 8; i++) { meas[i] = __expf(lg[i] - mx2); msum += meas[i]; }
    float minv = 1.f / msum;
    float4 o0 = make_float4(meas[0] * minv, meas[1] * minv, meas[2] * minv, meas[3] * minv);
    float4 o1 = make_float4(meas[4] * minv, meas[5] * minv, meas[6] * minv, meas[7] * minv);
    *(float4*)(meas_out + (size_t)m * 8) = o0;
    *(float4*)(meas_out + (size_t)m * 8 + 4) = o1;
}

// ================= fused measure MLP: qout = (relu(meas@W1+b1)@W2+b2)*v =================
// M=65536, K1=8, N1=64, K2=64, N2=96.
#define MD_T1_LD 136
#define MD_W2_LD 104
#define MD_SMEM ((8 * 136 + 8 * 72 + 64 * MD_T1_LD + 64 * MD_W2_LD) * 4)

__global__ __launch_bounds__(256)
void md_fused(const float* __restrict__ meas,
              const float* __restrict__ W1, const float* __restrict__ b1,
              const float* __restrict__ W2, const float* __restrict__ b2,
              const float* __restrict__ qkv, float* __restrict__ qout) {
    extern __shared__ float sm[];
    float* As8 = sm;                       // [8][136]
    float* W1s = sm + 8 * 136;             // [8][72]
    float* T1  = sm + 8 * 136 + 8 * 72;    // [64][136]  (k-major)
    float* W2s = T1 + 64 * MD_T1_LD;       // [64][104]

    int tid = threadIdx.x;
    int m0 = blockIdx.x * 128;
    int wid = tid >> 5, lane = tid & 31;
    int grp = lane >> 2, tig = lane & 3;
    int wm = (wid >> 2) * 64;

    // stage meas tile (transposed), W1, W2
    {
        int arow = tid >> 1, ak = (tid & 1) * 4;
        float4 v = *(const float4*)(meas + (size_t)(m0 + arow) * 8 + ak);
        As8[(ak + 0) * 136 + arow] = to_tf32(v.x);
        As8[(ak + 1) * 136 + arow] = to_tf32(v.y);
        As8[(ak + 2) * 136 + arow] = to_tf32(v.z);
        As8[(ak + 3) * 136 + arow] = to_tf32(v.w);
    }
    for (int i = tid; i < 128; i += 256) {
        int d = i >> 4, n4 = i & 15;
        float4 w = ((const float4*)W1)[i];
        float4 wc = make_float4(to_tf32(w.x), to_tf32(w.y), to_tf32(w.z), to_tf32(w.w));
        *(float4*)&W1s[d * 72 + n4 * 4] = wc;
    }
    for (int i = tid; i < 1536; i += 256) {
        int d = i / 24, n4 = i % 24;
        float4 w = ((const float4*)W2)[i];
        float4 wc = make_float4(to_tf32(w.x), to_tf32(w.y), to_tf32(w.z), to_tf32(w.w));
        *(float4*)&W2s[d * MD_W2_LD + n4 * 4] = wc;
    }
    __syncthreads();

    // GEMM1: T1 = relu(meas @ W1 + b1), single K=8 step, warp tile 64x16
    {
        int wn1 = (wid & 3) * 16;
        float acc1[4][2][4] = {};
        uint32_t a[4][4], b[2][2];
#pragma unroll
        for (int mi = 0; mi < 4; mi++) {
            int r = wm + mi * 16 + grp;
            a[mi][0] = __float_as_uint(As8[tig * 136 + r]);
            a[mi][1] = __float_as_uint(As8[tig * 136 + r + 8]);
            a[mi][2] = __float_as_uint(As8[(tig + 4) * 136 + r]);
            a[mi][3] = __float_as_uint(As8[(tig + 4) * 136 + r + 8]);
        }
#pragma unroll
        for (int nj = 0; nj < 2; nj++) {
            int c = wn1 + nj * 8 + grp;
            b[nj][0] = __float_as_uint(W1s[tig * 72 + c]);
            b[nj][1] = __float_as_uint(W1s[(tig + 4) * 72 + c]);
        }
#pragma unroll
        for (int mi = 0; mi < 4; mi++)
#pragma unroll
            for (int nj = 0; nj < 2; nj++) mma_tf32(acc1[mi][nj], a[mi], b[nj]);

        // write T1 transposed [col][row], relu+bias, tf32
#pragma unroll
        for (int nj = 0; nj < 2; nj++) {
            int c = wn1 + nj * 8 + tig * 2;
            float bi0 = __ldg(&b1[c]), bi1 = __ldg(&b1[c + 1]);
#pragma unroll
            for (int mi = 0; mi < 4; mi++) {
                int r = wm + mi * 16 + grp;
                T1[c * MD_T1_LD + r]           = to_tf32(fmaxf(acc1[mi][nj][0] + bi0, 0.f));
                T1[(c + 1) * MD_T1_LD + r]     = to_tf32(fmaxf(acc1[mi][nj][1] + bi1, 0.f));
                T1[c * MD_T1_LD + r + 8]       = to_tf32(fmaxf(acc1[mi][nj][2] + bi0, 0.f));
                T1[(c + 1) * MD_T1_LD + r + 8] = to_tf32(fmaxf(acc1[mi][nj][3] + bi1, 0.f));
            }
        }
    }
    __syncthreads();

    // GEMM2: out = (T1 @ W2 + b2) * v, warp tile 64x24, K=64
    int wn = (wid & 3) * 24;
    float acc2[4][3][4] = {};
#pragma unroll
    for (int ks = 0; ks < 8; ks++) {
        uint32_t a[4][4], b[3][2];
#pragma unroll
        for (int mi = 0; mi < 4; mi++) {
            int r = wm + mi * 16 + grp;
            a[mi][0] = __float_as_uint(T1[(ks * 8 + tig) * MD_T1_LD + r]);
            a[mi][1] = __float_as_uint(T1[(ks * 8 + tig) * MD_T1_LD + r + 8]);
            a[mi][2] = __float_as_uint(T1[(ks * 8 + tig + 4) * MD_T1_LD + r]);
            a[mi][3] = __float_as_uint(T1[(ks * 8 + tig + 4) * MD_T1_LD + r + 8]);
        }
#pragma unroll
        for (int nj = 0; nj < 3; nj++) {
            int c = wn + nj * 8 + grp;
            b[nj][0] = __float_as_uint(W2s[(ks * 8 + tig) * MD_W2_LD + c]);
            b[nj][1] = __float_as_uint(W2s[(ks * 8 + tig + 4) * MD_W2_LD + c]);
        }
#pragma unroll
        for (int mi = 0; mi < 4; mi++)
#pragma unroll
            for (int nj = 0; nj < 3; nj++) mma_tf32(acc2[mi][nj], a[mi], b[nj]);
    }

#pragma unroll
    for (int nj = 0; nj < 3; nj++) {
        int c = wn + nj * 8 + tig * 2;
        float bi0 = __ldg(&b2[c]), bi1 = __ldg(&b2[c + 1]);
#pragma unroll
        for (int mi = 0; mi < 4; mi++) {
            int m = m0 + wm + mi * 16 + grp;
#pragma unroll
            for (int half = 0; half < 2; half++) {
                int mm = m + half * 8;
                size_t qrow = (size_t)(mm >> 3);
                int hh = mm & 7;
                float2 vv = *(const float2*)(qkv + qrow * 2304 + 1536 + hh * 96 + c);
                float o0 = (acc2[mi][nj][half * 2 + 0] + bi0) * vv.x;
                float o1 = (acc2[mi][nj][half * 2 + 1] + bi1) * vv.y;
                *(float2*)(qout + qrow * 768 + hh * 96 + c) = make_float2(o0, o1);
            }
        }
    }
}

// ================= mean over N =================
__global__ void colmean_kernel(const float* __restrict__ x, float* __restrict__ xmean) {
    int b = blockIdx.y;
    int c = blockIdx.x * 256 + threadIdx.x;
    const float* p = x + (size_t)b * Nseq * Cdim + c;
    float s = 0.f;
    for (int n = 0; n < Nseq; n++) s += p[(size_t)n * Cdim];
    xmean[b * Cdim + c] = s * (1.0f / 1024.0f);
}

// ================= fw = sigmoid(xmean @ w_proj + b_proj) =================
__global__ void fw_kernel(const float* __restrict__ xmean, const float* __restrict__ w_proj,
                          const float* __restrict__ b_proj, float* __restrict__ fw) {
    __shared__ float xm[768];
    int b = blockIdx.x;
    int c = threadIdx.x;
    xm[c] = xmean[b * Cdim + c];
    __syncthreads();
    float s = b_proj[c];
    for (int k = 0; k < 768; k++) s += xm[k] * w_proj[(size_t)k * 768 + c];
    fw[b * Cdim + c] = 1.f / (1.f + expf(-s));
}

// ================= layernorm =================
__global__ void layernorm_kernel(const float* __restrict__ y, const float* __restrict__ gamma,
                                 const float* __restrict__ beta, float* __restrict__ out) {
    __shared__ float red1[8], red2[8];
    size_t row = blockIdx.x;
    const float* p = y + row * Cdim;
    int tid = threadIdx.x;
    float v[3];
    float s = 0.f;
#pragma unroll
    for (int i = 0; i < 3; i++) { v[i] = p[tid + i * 256]; s += v[i]; }
#pragma unroll
    for (int o = 16; o > 0; o >>= 1) s += __shfl_xor_sync(~0u, s, o);
    int w = tid >> 5, lane = tid & 31;
    if (lane == 0) red1[w] = s;
    __syncthreads();
    s = 0.f;
#pragma unroll
    for (int i = 0; i < 8; i++) s += red1[i];
    float mu = s * (1.0f / 768.0f);
    float vs = 0.f;
#pragma unroll
    for (int i = 0; i < 3; i++) { float d = v[i] - mu; vs += d * d; }
#pragma unroll
    for (int o = 16; o > 0; o >>= 1) vs += __shfl_xor_sync(~0u, vs, o);
    if (lane == 0) red2[w] = vs;
    __syncthreads();
    vs = 0.f;
#pragma unroll
    for (int i = 0; i < 8; i++) vs += red2[i];
    float inv = rsqrtf(vs * (1.0f / 768.0f) + 1e-5f);
#pragma unroll
    for (int i = 0; i < 3; i++) {
        int c = tid + i * 256;
        out[row * Cdim + c] = (v[i] - mu) * inv * gamma[c] + beta[c];
    }
}

// ================= launch =================
extern "C" void kernel_launch(void* const* d_in, const int* in_sizes, int n_in,
                              void* d_out, int out_size) {
    const float* x      = (const float*)d_in[0];
    const float* w_qkv  = (const float*)d_in[1];
    const float* b_qkv  = (const float*)d_in[2];
    const float* w_proj = (const float*)d_in[3];
    const float* b_proj = (const float*)d_in[4];
    const float* gamma  = (const float*)d_in[5];
    const float* beta   = (const float*)d_in[6];
    const float* qe_w1  = (const float*)d_in[7];
    const float* qe_b1  = (const float*)d_in[8];
    const float* qe_w2  = (const float*)d_in[9];
    const float* qe_b2  = (const float*)d_in[10];
    const float* ke_w1  = (const float*)d_in[11];
    const float* ke_b1  = (const float*)d_in[12];
    const float* ke_w2  = (const float*)d_in[13];
    const float* ke_b2  = (const float*)d_in[14];
    const float* gate_params = (const float*)d_in[19];
    const float* ent_params  = (const float*)d_in[20];
    const float* md_w1  = (const float*)d_in[21];
    const float* md_b1  = (const float*)d_in[22];
    const float* md_w2  = (const float*)d_in[23];
    const float* md_b2  = (const float*)d_in[24];
    const float* gumbel = (const float*)d_in[25];
    float* out = (float*)d_out;

    float *qkv, *qout, *fused, *xmean, *fw, *hq, *hk, *meas;
    cudaGetSymbolAddress((void**)&qkv, g_qkv);
    cudaGetSymbolAddress((void**)&qout, g_qout);
    cudaGetSymbolAddress((void**)&fused, g_fused);
    cudaGetSymbolAddress((void**)&xmean, g_xmean);
    cudaGetSymbolAddress((void**)&fw, g_fw);
    cudaGetSymbolAddress((void**)&hq, g_hq);
    cudaGetSymbolAddress((void**)&hk, g_hk);
    cudaGetSymbolAddress((void**)&meas, g_meas);

    cudaFuncSetAttribute(flash_kernel, cudaFuncAttributeMaxDynamicSharedMemorySize, FLASH_SMEM);
    cudaFuncSetAttribute(md_fused, cudaFuncAttributeMaxDynamicSharedMemorySize, MD_SMEM);

    // gate path (depends only on x)
    colmean_kernel<<<dim3(3, 8), 256>>>(x, xmean);
    fw_kernel<<<8, 768>>>(xmean, w_proj, b_proj, fw);
    // qkv = x @ w_qkv + b_qkv
    mma_nn<<<dim3(2304 / 128, 8192 / 128), 256>>>(x, w_qkv, b_qkv, nullptr, qkv,
                                                  768, 768, 2304, 2304);
    // quantum path: embeds (GEMM) -> mid -> measure MLP (GEMM) -> qout
    embed_gemm<<<NTOK / 128, 256>>>(qkv, 0, qe_w1, qe_b1, hq);
    embed_gemm<<<NTOK / 128, 256>>>(qkv, 768, ke_w1, ke_b1, hk);
    quantum_mid<<<NTOK / 128, 128>>>(hq, hk, qe_w2, qe_b2, ke_w2, ke_b2,
                                     gate_params, ent_params, gumbel, meas);
    md_fused<<<NTOK / 128, 256, MD_SMEM>>>(meas, md_w1, md_b1, md_w2, md_b2, qkv, qout);
    // fused classical attention + gate blend -> fused
    flash_kernel<<<dim3(8, 64), 256, FLASH_SMEM>>>(qkv, qout, fw, fused);
    // y = x + fused @ w_proj + b_proj  (reuse qout as y)
    mma_nn<<<dim3(768 / 128, 8192 / 128), 256>>>(fused, w_proj, b_proj, x, qout,
                                                 768, 768, 768, 768);
    // layernorm
    layernorm_kernel<<<8192, 256>>>(qout, gamma, beta, out);
}

// round 7
// speedup vs baseline: 4.3525x; 1.2532x over previous
#include <cuda_runtime.h>
#include <cuda_bf16.h>
#include <math.h>
#include <stdint.h>

// ---------------- scratch ----------------
#define Bsz 8
#define Nseq 1024
#define Cdim 768
#define Hh 8
#define Dd 96
#define Qq 8
#define NTOK (Bsz * Hh * Nseq)   // 65536, ordered m=(b,n,h)

__device__ float g_qkv[Bsz * Nseq * 3 * Cdim];
__device__ float g_qout[Bsz * Nseq * Cdim];
__device__ float g_fused[Bsz * Nseq * Cdim];
__device__ float g_xmean[Bsz * Cdim];
__device__ float g_fw[Bsz * Cdim];
__device__ float g_hq[NTOK * 64];
__device__ float g_hk[NTOK * 64];
__device__ float g_meas[NTOK * 8];

// ---------------- mma helpers ----------------
__device__ __forceinline__ float to_tf32(float x) {
    uint32_t u;
    asm("cvt.rna.tf32.f32 %0, %1;" : "=r"(u) : "f"(x));
    return __uint_as_float(u);
}

__device__ __forceinline__ uint32_t pkbf(float x, float y) {
    __nv_bfloat162 t = __floats2bfloat162_rn(x, y);
    return *(uint32_t*)&t;
}

__device__ __forceinline__ void mma_tf32(float* c, const uint32_t* a, const uint32_t* b) {
    asm volatile(
        "mma.sync.aligned.m16n8k8.row.col.f32.tf32.tf32.f32 "
        "{%0,%1,%2,%3}, {%4,%5,%6,%7}, {%8,%9}, {%0,%1,%2,%3};"
        : "+f"(c[0]), "+f"(c[1]), "+f"(c[2]), "+f"(c[3])
        : "r"(a[0]), "r"(a[1]), "r"(a[2]), "r"(a[3]), "r"(b[0]), "r"(b[1]));
}

__device__ __forceinline__ void mma_bf16(float* c, const uint32_t* a, const uint32_t* b) {
    asm volatile(
        "mma.sync.aligned.m16n8k16.row.col.f32.bf16.bf16.f32 "
        "{%0,%1,%2,%3}, {%4,%5,%6,%7}, {%8,%9}, {%0,%1,%2,%3};"
        : "+f"(c[0]), "+f"(c[1]), "+f"(c[2]), "+f"(c[3])
        : "r"(a[0]), "r"(a[1]), "r"(a[2]), "r"(a[3]), "r"(b[0]), "r"(b[1]));
}

// ================= bf16 MMA GEMM (NN): C = A@B (+bias)(+resid) =================
// BM=128, BN=128, BK=16. K%16==0. smem holds bf16x2 packed along K.
__global__ __launch_bounds__(256)
void mma_nn(const float* __restrict__ A, const float* __restrict__ B,
            const float* __restrict__ bias, const float* __restrict__ resid,
            float* __restrict__ C, int K, int lda, int ldb, int ldc) {
    __shared__ uint32_t As[2][8][136];   // [k2][row]
    __shared__ uint32_t Bs[2][8][136];   // [k2][col]
    int tid = threadIdx.x;
    int m0 = blockIdx.y * 128, n0 = blockIdx.x * 128;
    int arow = tid >> 1, apart = tid & 1;
    int bk2 = tid >> 5, bcol = (tid & 31) * 4;
    const float* Ap = A + (size_t)(m0 + arow) * lda;
    const float* Bp0 = B + (size_t)(2 * bk2) * ldb + n0 + bcol;
    const float* Bp1 = B + (size_t)(2 * bk2 + 1) * ldb + n0 + bcol;

    int wid = tid >> 5, lane = tid & 31;
    int wm = (wid >> 2) * 64, wn = (wid & 3) * 32;
    int grp = lane >> 2, tig = lane & 3;
    float acc[4][4][4] = {};

    {
        float4 a0 = *(const float4*)(Ap + apart * 4);
        float4 a1 = *(const float4*)(Ap + apart * 4 + 8);
        As[0][apart * 2 + 0][arow] = pkbf(a0.x, a0.y);
        As[0][apart * 2 + 1][arow] = pkbf(a0.z, a0.w);
        As[0][apart * 2 + 4][arow] = pkbf(a1.x, a1.y);
        As[0][apart * 2 + 5][arow] = pkbf(a1.z, a1.w);
        float4 b0 = *(const float4*)Bp0;
        float4 b1 = *(const float4*)Bp1;
        *(uint4*)&Bs[0][bk2][bcol] = make_uint4(pkbf(b0.x, b1.x), pkbf(b0.y, b1.y),
                                                pkbf(b0.z, b1.z), pkbf(b0.w, b1.w));
    }
    __syncthreads();

    int S = K / 16, buf = 0;
    for (int s = 1; s <= S; s++) {
        bool more = (s < S);
        float4 a0, a1, b0, b1;
        if (more) {
            int k0 = s * 16;
            a0 = *(const float4*)(Ap + k0 + apart * 4);
            a1 = *(const float4*)(Ap + k0 + apart * 4 + 8);
            b0 = *(const float4*)(Bp0 + (size_t)k0 * ldb);
            b1 = *(const float4*)(Bp1 + (size_t)k0 * ldb);
        }
        uint32_t a[4][4], b[4][2];
#pragma unroll
        for (int mi = 0; mi < 4; mi++) {
            int r = wm + mi * 16 + grp;
            a[mi][0] = As[buf][tig][r];
            a[mi][1] = As[buf][tig][r + 8];
            a[mi][2] = As[buf][tig + 4][r];
            a[mi][3] = As[buf][tig + 4][r + 8];
        }
#pragma unroll
        for (int nj = 0; nj < 4; nj++) {
            int c = wn + nj * 8 + grp;
            b[nj][0] = Bs[buf][tig][c];
            b[nj][1] = Bs[buf][tig + 4][c];
        }
#pragma unroll
        for (int mi = 0; mi < 4; mi++)
#pragma unroll
            for (int nj = 0; nj < 4; nj++) mma_bf16(acc[mi][nj], a[mi], b[nj]);
        if (more) {
            As[buf ^ 1][apart * 2 + 0][arow] = pkbf(a0.x, a0.y);
            As[buf ^ 1][apart * 2 + 1][arow] = pkbf(a0.z, a0.w);
            As[buf ^ 1][apart * 2 + 4][arow] = pkbf(a1.x, a1.y);
            As[buf ^ 1][apart * 2 + 5][arow] = pkbf(a1.z, a1.w);
            *(uint4*)&Bs[buf ^ 1][bk2][bcol] = make_uint4(pkbf(b0.x, b1.x), pkbf(b0.y, b1.y),
                                                          pkbf(b0.z, b1.z), pkbf(b0.w, b1.w));
            __syncthreads();
            buf ^= 1;
        }
    }

#pragma unroll
    for (int nj = 0; nj < 4; nj++) {
        int c = n0 + wn + nj * 8 + tig * 2;
        float bi0 = bias ? bias[c] : 0.f;
        float bi1 = bias ? bias[c + 1] : 0.f;
#pragma unroll
        for (int mi = 0; mi < 4; mi++) {
            size_t r = m0 + wm + mi * 16 + grp;
            float2 lo = make_float2(acc[mi][nj][0] + bi0, acc[mi][nj][1] + bi1);
            float2 hi = make_float2(acc[mi][nj][2] + bi0, acc[mi][nj][3] + bi1);
            if (resid) {
                float2 r0 = *(const float2*)(resid + r * ldc + c);
                float2 r1 = *(const float2*)(resid + (r + 8) * ldc + c);
                lo.x += r0.x; lo.y += r0.y; hi.x += r1.x; hi.y += r1.y;
            }
            *(float2*)(C + r * ldc + c) = lo;
            *(float2*)(C + (r + 8) * ldc + c) = hi;
        }
    }
}

// ================= fused flash attention (bf16) + gate blend =================
// Qs/Ks: [48][LDQ] bf16x2 packed along d.  Vs: [64][LDV] bf16x2 packed along position.
#define LDQ 136
#define LDV 104
#define FLASH_SMEM ((2 * 48 * LDQ + 64 * LDV) * 4)

__global__ __launch_bounds__(256, 1)
void flash_kernel(const float* __restrict__ qkv, const float* __restrict__ qout,
                  const float* __restrict__ fw, float* __restrict__ fused) {
    extern __shared__ uint32_t smu[];
    uint32_t* Qs = smu;
    uint32_t* Ks = smu + 48 * LDQ;
    uint32_t* Vs = smu + 2 * 48 * LDQ;

    int tid = threadIdx.x;
    int z = blockIdx.y;
    int b = z >> 3, h = z & 7;
    int q0 = blockIdx.x * 128;
    const float* qbase = qkv + (size_t)b * Nseq * 2304 + h * Dd;
    const float* kbase = qbase + 768;
    const float* vbase = qbase + 1536;

    int lane = tid & 31, wid = tid >> 5;
    int grp = lane >> 2, tig = lane & 3;
    int wrow = wid * 16;

    for (int i = tid; i < 3072; i += 256) {
        int f4 = i % 24, r = i / 24;
        float4 v = *(const float4*)(qbase + (size_t)(q0 + r) * 2304 + f4 * 4);
        Qs[(f4 * 2 + 0) * LDQ + r] = pkbf(v.x, v.y);
        Qs[(f4 * 2 + 1) * LDQ + r] = pkbf(v.z, v.w);
    }

    float o[12][4] = {};
    float m0 = -1e30f, m1 = -1e30f, l0 = 0.f, l1 = 0.f;
    const float scale = 0.10206207261596577f;

    for (int t = 0; t < 8; t++) {
        __syncthreads();
        int kv0 = t * 128;
        for (int i = tid; i < 3072; i += 256) {
            int f4 = i % 24, r = i / 24;
            float4 v = *(const float4*)(kbase + (size_t)(kv0 + r) * 2304 + f4 * 4);
            Ks[(f4 * 2 + 0) * LDQ + r] = pkbf(v.x, v.y);
            Ks[(f4 * 2 + 1) * LDQ + r] = pkbf(v.z, v.w);
        }
        for (int i = tid; i < 1536; i += 256) {
            int j2 = i / 24, c4 = i % 24;
            const float* p0 = vbase + (size_t)(kv0 + 2 * j2) * 2304 + c4 * 4;
            float4 v0 = *(const float4*)p0;
            float4 v1 = *(const float4*)(p0 + 2304);
            *(uint4*)&Vs[j2 * LDV + c4 * 4] = make_uint4(pkbf(v0.x, v1.x), pkbf(v0.y, v1.y),
                                                         pkbf(v0.z, v1.z), pkbf(v0.w, v1.w));
        }
        __syncthreads();

        // S = Q @ K^T (16 rows x 128 cols per warp), 6 k16-steps
        float s[16][4] = {};
#pragma unroll
        for (int ks = 0; ks < 6; ks++) {
            uint32_t a[4];
            a[0] = Qs[(ks * 8 + tig) * LDQ + wrow + grp];
            a[1] = Qs[(ks * 8 + tig) * LDQ + wrow + grp + 8];
            a[2] = Qs[(ks * 8 + tig + 4) * LDQ + wrow + grp];
            a[3] = Qs[(ks * 8 + tig + 4) * LDQ + wrow + grp + 8];
#pragma unroll
            for (int n = 0; n < 16; n++) {
                uint32_t bb[2];
                bb[0] = Ks[(ks * 8 + tig) * LDQ + n * 8 + grp];
                bb[1] = Ks[(ks * 8 + tig + 4) * LDQ + n * 8 + grp];
                mma_bf16(s[n], a, bb);
            }
        }

        // online softmax
        float mx0 = -1e30f, mx1 = -1e30f;
#pragma unroll
        for (int n = 0; n < 16; n++) {
            mx0 = fmaxf(mx0, fmaxf(s[n][0], s[n][1]));
            mx1 = fmaxf(mx1, fmaxf(s[n][2], s[n][3]));
        }
        mx0 = fmaxf(mx0, __shfl_xor_sync(~0u, mx0, 1));
        mx0 = fmaxf(mx0, __shfl_xor_sync(~0u, mx0, 2));
        mx1 = fmaxf(mx1, __shfl_xor_sync(~0u, mx1, 1));
        mx1 = fmaxf(mx1, __shfl_xor_sync(~0u, mx1, 2));
        float nm0 = fmaxf(m0, mx0 * scale);
        float nm1 = fmaxf(m1, mx1 * scale);
        float al0 = __expf(m0 - nm0), al1 = __expf(m1 - nm1);
        m0 = nm0; m1 = nm1;
        float sum0 = 0.f, sum1 = 0.f;
#pragma unroll
        for (int n = 0; n < 16; n++) {
            float p0 = __expf(s[n][0] * scale - nm0);
            float p1 = __expf(s[n][1] * scale - nm0);
            float p2 = __expf(s[n][2] * scale - nm1);
            float p3 = __expf(s[n][3] * scale - nm1);
            sum0 += p0 + p1; sum1 += p2 + p3;
            s[n][0] = p0; s[n][1] = p1; s[n][2] = p2; s[n][3] = p3;
        }
        sum0 += __shfl_xor_sync(~0u, sum0, 1);
        sum0 += __shfl_xor_sync(~0u, sum0, 2);
        sum1 += __shfl_xor_sync(~0u, sum1, 1);
        sum1 += __shfl_xor_sync(~0u, sum1, 2);
        l0 = l0 * al0 + sum0;
        l1 = l1 * al1 + sum1;
#pragma unroll
        for (int n = 0; n < 12; n++) {
            o[n][0] *= al0; o[n][1] *= al0;
            o[n][2] *= al1; o[n][3] *= al1;
        }

        // O += P @ V : acc layout == bf16 A-frag layout, no shuffles
#pragma unroll
        for (int jb = 0; jb < 8; jb++) {
            uint32_t a[4];
            a[0] = pkbf(s[2 * jb][0], s[2 * jb][1]);
            a[1] = pkbf(s[2 * jb][2], s[2 * jb][3]);
            a[2] = pkbf(s[2 * jb + 1][0], s[2 * jb + 1][1]);
            a[3] = pkbf(s[2 * jb + 1][2], s[2 * jb + 1][3]);
#pragma unroll
            for (int n = 0; n < 12; n++) {
                uint32_t bb[2];
                bb[0] = Vs[(jb * 8 + tig) * LDV + n * 8 + grp];
                bb[1] = Vs[(jb * 8 + tig + 4) * LDV + n * 8 + grp];
                mma_bf16(o[n], a, bb);
            }
        }
    }

    float inv0 = 1.f / l0, inv1 = 1.f / l1;
    int row0 = q0 + wrow + grp;
#pragma unroll
    for (int n = 0; n < 12; n++) {
        int c = n * 8 + tig * 2;
        float f0 = fw[b * Cdim + h * Dd + c];
        float f1 = fw[b * Cdim + h * Dd + c + 1];
        size_t ob0 = ((size_t)b * Nseq + row0) * Cdim + h * Dd + c;
        size_t ob1 = ((size_t)b * Nseq + row0 + 8) * Cdim + h * Dd + c;
        float2 qv0 = *(const float2*)(qout + ob0);
        float2 qv1 = *(const float2*)(qout + ob1);
        float2 lo = make_float2(f0 * qv0.x + (1.f - f0) * o[n][0] * inv0,
                                f1 * qv0.y + (1.f - f1) * o[n][1] * inv0);
        float2 hi = make_float2(f0 * qv1.x + (1.f - f0) * o[n][2] * inv1,
                                f1 * qv1.y + (1.f - f1) * o[n][3] * inv1);
        *(float2*)(fused + ob0) = lo;
        *(float2*)(fused + ob1) = hi;
    }
}

// ================= quantum embed GEMM (bf16): H = relu(A @ W1 + b1) =================
__global__ __launch_bounds__(256)
void embed_gemm(const float* __restrict__ qkv, int qk_off,
                const float* __restrict__ W1, const float* __restrict__ b1,
                float* __restrict__ H) {
    __shared__ uint32_t As[2][8][136];
    __shared__ uint32_t Bs[48][72];
    int tid = threadIdx.x;
    int m0 = blockIdx.x * 128;

    for (int i = tid; i < 768; i += 256) {
        int k2 = i >> 4, c4 = i & 15;
        float4 w0 = *(const float4*)(W1 + (2 * k2) * 64 + c4 * 4);
        float4 w1 = *(const float4*)(W1 + (2 * k2 + 1) * 64 + c4 * 4);
        *(uint4*)&Bs[k2][c4 * 4] = make_uint4(pkbf(w0.x, w1.x), pkbf(w0.y, w1.y),
                                              pkbf(w0.z, w1.z), pkbf(w0.w, w1.w));
    }

    int arow = tid >> 1, apart = tid & 1;
    const float* Ap = qkv + (size_t)((m0 + arow) >> 3) * 2304 + qk_off + ((m0 + arow) & 7) * 96;

    int wid = tid >> 5, lane = tid & 31;
    int wm = (wid >> 2) * 64, wn = (wid & 3) * 16;
    int grp = lane >> 2, tig = lane & 3;
    float acc[4][2][4] = {};

    {
        float4 a0 = *(const float4*)(Ap + apart * 4);
        float4 a1 = *(const float4*)(Ap + apart * 4 + 8);
        As[0][apart * 2 + 0][arow] = pkbf(a0.x, a0.y);
        As[0][apart * 2 + 1][arow] = pkbf(a0.z, a0.w);
        As[0][apart * 2 + 4][arow] = pkbf(a1.x, a1.y);
        As[0][apart * 2 + 5][arow] = pkbf(a1.z, a1.w);
    }
    __syncthreads();

    int buf = 0;
    for (int s = 1; s <= 6; s++) {
        bool more = (s < 6);
        float4 a0, a1;
        if (more) {
            a0 = *(const float4*)(Ap + s * 16 + apart * 4);
            a1 = *(const float4*)(Ap + s * 16 + apart * 4 + 8);
        }
        int kb = (s - 1) * 8;
        uint32_t a[4][4], b[2][2];
#pragma unroll
        for (int mi = 0; mi < 4; mi++) {
            int r = wm + mi * 16 + grp;
            a[mi][0] = As[buf][tig][r];
            a[mi][1] = As[buf][tig][r + 8];
            a[mi][2] = As[buf][tig + 4][r];
            a[mi][3] = As[buf][tig + 4][r + 8];
        }
#pragma unroll
        for (int nj = 0; nj < 2; nj++) {
            int c = wn + nj * 8 + grp;
            b[nj][0] = Bs[kb + tig][c];
            b[nj][1] = Bs[kb + tig + 4][c];
        }
#pragma unroll
        for (int mi = 0; mi < 4; mi++)
#pragma unroll
            for (int nj = 0; nj < 2; nj++) mma_bf16(acc[mi][nj], a[mi], b[nj]);
        if (more) {
            As[buf ^ 1][apart * 2 + 0][arow] = pkbf(a0.x, a0.y);
            As[buf ^ 1][apart * 2 + 1][arow] = pkbf(a0.z, a0.w);
            As[buf ^ 1][apart * 2 + 4][arow] = pkbf(a1.x, a1.y);
            As[buf ^ 1][apart * 2 + 5][arow] = pkbf(a1.z, a1.w);
            __syncthreads();
            buf ^= 1;
        }
    }

#pragma unroll
    for (int nj = 0; nj < 2; nj++) {
        int c = wn + nj * 8 + tig * 2;
        float bi0 = __ldg(&b1[c]), bi1 = __ldg(&b1[c + 1]);
#pragma unroll
        for (int mi = 0; mi < 4; mi++) {
            size_t r = m0 + wm + mi * 16 + grp;
            float2 lo = make_float2(fmaxf(acc[mi][nj][0] + bi0, 0.f), fmaxf(acc[mi][nj][1] + bi1, 0.f));
            float2 hi = make_float2(fmaxf(acc[mi][nj][2] + bi0, 0.f), fmaxf(acc[mi][nj][3] + bi1, 0.f));
            *(float2*)(H + r * 64 + c) = lo;
            *(float2*)(H + (r + 8) * 64 + c) = hi;
        }
    }
}

// ================= quantum middle: e -> state -> meas =================
__global__ __launch_bounds__(128)
void quantum_mid(const float* __restrict__ Hq, const float* __restrict__ Hk,
                 const float* __restrict__ qe_w2, const float* __restrict__ qe_b2,
                 const float* __restrict__ ke_w2, const float* __restrict__ ke_b2,
                 const float* __restrict__ gate_params, const float* __restrict__ ent_params,
                 const float* __restrict__ gumbel, float* __restrict__ meas_out) {
    __shared__ float w2q[1024], w2k[1024];
    __shared__ float gf[2][8], gcz[2][8], gsz[2][8], gs[2][8];
    int tid = threadIdx.x;
    for (int i = tid; i < 256; i += 128) {
        ((float4*)w2q)[i] = ((const float4*)qe_w2)[i];
        ((float4*)w2k)[i] = ((const float4*)ke_w2)[i];
    }
    if (tid < 16) {
        int l = tid >> 3, i = tid & 7;
        float ry = gate_params[(l * 8 + i) * 3 + 1];
        float rz = gate_params[(l * 8 + i) * 3 + 2];
        gf[l][i] = cosf(0.5f * ry);
        gcz[l][i] = cosf(rz);
        gsz[l][i] = sinf(rz);
    } else if (tid < 30) {
        int t = tid - 16, l = t / 7, i = t % 7;
        gs[l][i + 1] = 1.f / (1.f + expf(-ent_params[l * 7 + i]));
    }
    __syncthreads();

    int m = blockIdx.x * 128 + tid;
    float sre[8], sim[8];

#pragma unroll
    for (int pass = 0; pass < 2; pass++) {
        const float* Hrow = (pass == 0 ? Hq : Hk) + (size_t)m * 64;
        const float* w2 = (pass == 0 ? w2q : w2k);
        const float* b2 = (pass == 0 ? qe_b2 : ke_b2);
        float e[16];
#pragma unroll
        for (int i = 0; i < 16; i++) e[i] = __ldg(&b2[i]);
        const float4* h4 = (const float4*)Hrow;
#pragma unroll
        for (int j4 = 0; j4 < 16; j4++) {
            float4 hv = h4[j4];
            float hs[4] = {hv.x, hv.y, hv.z, hv.w};
#pragma unroll
            for (int s = 0; s < 4; s++) {
                float hj = hs[s];
                const float4* wr = (const float4*)&w2[(j4 * 4 + s) * 16];
#pragma unroll
                for (int i4 = 0; i4 < 4; i4++) {
                    float4 w = wr[i4];
                    e[i4 * 4 + 0] += hj * w.x; e[i4 * 4 + 1] += hj * w.y;
                    e[i4 * 4 + 2] += hj * w.z; e[i4 * 4 + 3] += hj * w.w;
                }
            }
        }
        float mx = e[0];
#pragma unroll
        for (int i = 1; i < 8; i++) mx = fmaxf(mx, e[i]);
        float ex[8], ssum = 0.f;
#pragma unroll
        for (int i = 0; i < 8; i++) { ex[i] = __expf(e[i] - mx); ssum += ex[i]; }
        float inv = 1.f / ssum;
#pragma unroll
        for (int i = 0; i < 8; i++) {
            float amp = ex[i] * inv;
            float cr = amp * __cosf(e[8 + i]), ci = amp * __sinf(e[8 + i]);
            if (pass == 0) { sre[i] = cr; sim[i] = ci; }
            else           { sre[i] += cr; sim[i] += ci; }
        }
    }

#pragma unroll
    for (int l = 0; l < 2; l++) {
#pragma unroll
        for (int i = 0; i < 8; i++) {
            float nr = sre[i] * gcz[l][i] - sim[i] * gsz[l][i];
            float ni = sre[i] * gsz[l][i] + sim[i] * gcz[l][i];
            sre[i] = nr * gf[l][i];
            sim[i] = ni * gf[l][i];
        }
#pragma unroll
        for (int i = 7; i >= 1; i--) {
            sre[i] += gs[l][i] * sre[i - 1];
            sim[i] += gs[l][i] * sim[i - 1];
        }
    }

    float p[8], mx = -1e30f;
#pragma unroll
    for (int i = 0; i < 8; i++) { p[i] = sre[i] * sre[i] + sim[i] * sim[i]; mx = fmaxf(mx, p[i]); }
    float ssum = 0.f;
#pragma unroll
    for (int i = 0; i < 8; i++) { p[i] = __expf(p[i] - mx); ssum += p[i]; }
    float sinv = 1.f / ssum;
    int b = m >> 13, n = (m >> 3) & 1023, h = m & 7;
    size_t goff = (size_t)(((b * 8 + h) << 10) + n) * 8;
    float4 g0 = __ldg((const float4*)(gumbel + goff));
    float4 g1 = __ldg((const float4*)(gumbel + goff + 4));
    float gv[8] = {g0.x, g0.y, g0.z, g0.w, g1.x, g1.y, g1.z, g1.w};
    float lg[8], mx2 = -1e30f;
#pragma unroll
    for (int i = 0; i < 8; i++) {
        lg[i] = 2.f * (__logf(p[i] * sinv + 1e-10f) + gv[i]);
        mx2 = fmaxf(mx2, lg[i]);
    }
    float meas[8], msum = 0.f;
#pragma unroll
    for (int i = 0; i < 8; i++) { meas[i] = __expf(lg[i] - mx2); msum += meas[i]; }
    float minv = 1.f / msum;
    float4 o0 = make_float4(meas[0] * minv, meas[1] * minv, meas[2] * minv, meas[3] * minv);
    float4 o1 = make_float4(meas[4] * minv, meas[5] * minv, meas[6] * minv, meas[7] * minv);
    *(float4*)(meas_out + (size_t)m * 8) = o0;
    *(float4*)(meas_out + (size_t)m * 8 + 4) = o1;
}

// ================= fused measure MLP (tf32): qout = (relu(meas@W1+b1)@W2+b2)*v =================
#define MD_T1_LD 136
#define MD_W2_LD 104
#define MD_SMEM ((8 * 136 + 8 * 72 + 64 * MD_T1_LD + 64 * MD_W2_LD) * 4)

__global__ __launch_bounds__(256)
void md_fused(const float* __restrict__ meas,
              const float* __restrict__ W1, const float* __restrict__ b1,
              const float* __restrict__ W2, const float* __restrict__ b2,
              const float* __restrict__ qkv, float* __restrict__ qout) {
    extern __shared__ float sm[];
    float* As8 = sm;
    float* W1s = sm + 8 * 136;
    float* T1  = sm + 8 * 136 + 8 * 72;
    float* W2s = T1 + 64 * MD_T1_LD;

    int tid = threadIdx.x;
    int m0 = blockIdx.x * 128;
    int wid = tid >> 5, lane = tid & 31;
    int grp = lane >> 2, tig = lane & 3;
    int wm = (wid >> 2) * 64;

    {
        int arow = tid >> 1, ak = (tid & 1) * 4;
        float4 v = *(const float4*)(meas + (size_t)(m0 + arow) * 8 + ak);
        As8[(ak + 0) * 136 + arow] = to_tf32(v.x);
        As8[(ak + 1) * 136 + arow] = to_tf32(v.y);
        As8[(ak + 2) * 136 + arow] = to_tf32(v.z);
        As8[(ak + 3) * 136 + arow] = to_tf32(v.w);
    }
    for (int i = tid; i < 128; i += 256) {
        int d = i >> 4, n4 = i & 15;
        float4 w = ((const float4*)W1)[i];
        float4 wc = make_float4(to_tf32(w.x), to_tf32(w.y), to_tf32(w.z), to_tf32(w.w));
        *(float4*)&W1s[d * 72 + n4 * 4] = wc;
    }
    for (int i = tid; i < 1536; i += 256) {
        int d = i / 24, n4 = i % 24;
        float4 w = ((const float4*)W2)[i];
        float4 wc = make_float4(to_tf32(w.x), to_tf32(w.y), to_tf32(w.z), to_tf32(w.w));
        *(float4*)&W2s[d * MD_W2_LD + n4 * 4] = wc;
    }
    __syncthreads();

    {
        int wn1 = (wid & 3) * 16;
        float acc1[4][2][4] = {};
        uint32_t a[4][4], b[2][2];
#pragma unroll
        for (int mi = 0; mi < 4; mi++) {
            int r = wm + mi * 16 + grp;
            a[mi][0] = __float_as_uint(As8[tig * 136 + r]);
            a[mi][1] = __float_as_uint(As8[tig * 136 + r + 8]);
            a[mi][2] = __float_as_uint(As8[(tig + 4) * 136 + r]);
            a[mi][3] = __float_as_uint(As8[(tig + 4) * 136 + r + 8]);
        }
#pragma unroll
        for (int nj = 0; nj < 2; nj++) {
            int c = wn1 + nj * 8 + grp;
            b[nj][0] = __float_as_uint(W1s[tig * 72 + c]);
            b[nj][1] = __float_as_uint(W1s[(tig + 4) * 72 + c]);
        }
#pragma unroll
        for (int mi = 0; mi < 4; mi++)
#pragma unroll
            for (int nj = 0; nj < 2; nj++) mma_tf32(acc1[mi][nj], a[mi], b[nj]);

#pragma unroll
        for (int nj = 0; nj < 2; nj++) {
            int c = wn1 + nj * 8 + tig * 2;
            float bi0 = __ldg(&b1[c]), bi1 = __ldg(&b1[c + 1]);
#pragma unroll
            for (int mi = 0; mi < 4; mi++) {
                int r = wm + mi * 16 + grp;
                T1[c * MD_T1_LD + r]           = to_tf32(fmaxf(acc1[mi][nj][0] + bi0, 0.f));
                T1[(c + 1) * MD_T1_LD + r]     = to_tf32(fmaxf(acc1[mi][nj][1] + bi1, 0.f));
                T1[c * MD_T1_LD + r + 8]       = to_tf32(fmaxf(acc1[mi][nj][2] + bi0, 0.f));
                T1[(c + 1) * MD_T1_LD + r + 8] = to_tf32(fmaxf(acc1[mi][nj][3] + bi1, 0.f));
            }
        }
    }
    __syncthreads();

    int wn = (wid & 3) * 24;
    float acc2[4][3][4] = {};
#pragma unroll
    for (int ks = 0; ks < 8; ks++) {
        uint32_t a[4][4], b[3][2];
#pragma unroll
        for (int mi = 0; mi < 4; mi++) {
            int r = wm + mi * 16 + grp;
            a[mi][0] = __float_as_uint(T1[(ks * 8 + tig) * MD_T1_LD + r]);
            a[mi][1] = __float_as_uint(T1[(ks * 8 + tig) * MD_T1_LD + r + 8]);
            a[mi][2] = __float_as_uint(T1[(ks * 8 + tig + 4) * MD_T1_LD + r]);
            a[mi][3] = __float_as_uint(T1[(ks * 8 + tig + 4) * MD_T1_LD + r + 8]);
        }
#pragma unroll
        for (int nj = 0; nj < 3; nj++) {
            int c = wn + nj * 8 + grp;
            b[nj][0] = __float_as_uint(W2s[(ks * 8 + tig) * MD_W2_LD + c]);
            b[nj][1] = __float_as_uint(W2s[(ks * 8 + tig + 4) * MD_W2_LD + c]);
        }
#pragma unroll
        for (int mi = 0; mi < 4; mi++)
#pragma unroll
            for (int nj = 0; nj < 3; nj++) mma_tf32(acc2[mi][nj], a[mi], b[nj]);
    }

#pragma unroll
    for (int nj = 0; nj < 3; nj++) {
        int c = wn + nj * 8 + tig * 2;
        float bi0 = __ldg(&b2[c]), bi1 = __ldg(&b2[c + 1]);
#pragma unroll
        for (int mi = 0; mi < 4; mi++) {
            int m = m0 + wm + mi * 16 + grp;
#pragma unroll
            for (int half = 0; half < 2; half++) {
                int mm = m + half * 8;
                size_t qrow = (size_t)(mm >> 3);
                int hh = mm & 7;
                float2 vv = *(const float2*)(qkv + qrow * 2304 + 1536 + hh * 96 + c);
                float o0 = (acc2[mi][nj][half * 2 + 0] + bi0) * vv.x;
                float o1 = (acc2[mi][nj][half * 2 + 1] + bi1) * vv.y;
                *(float2*)(qout + qrow * 768 + hh * 96 + c) = make_float2(o0, o1);
            }
        }
    }
}

// ================= mean over N =================
__global__ void colmean_kernel(const float* __restrict__ x, float* __restrict__ xmean) {
    int b = blockIdx.y;
    int c = blockIdx.x * 256 + threadIdx.x;
    const float* p = x + (size_t)b * Nseq * Cdim + c;
    float s = 0.f;
    for (int n = 0; n < Nseq; n++) s += p[(size_t)n * Cdim];
    xmean[b * Cdim + c] = s * (1.0f / 1024.0f);
}

// ================= fw = sigmoid(xmean @ w_proj + b_proj) =================
__global__ void fw_kernel(const float* __restrict__ xmean, const float* __restrict__ w_proj,
                          const float* __restrict__ b_proj, float* __restrict__ fw) {
    __shared__ float xm[768];
    int b = blockIdx.x;
    int c = threadIdx.x;
    xm[c] = xmean[b * Cdim + c];
    __syncthreads();
    float s = b_proj[c];
    for (int k = 0; k < 768; k++) s += xm[k] * w_proj[(size_t)k * 768 + c];
    fw[b * Cdim + c] = 1.f / (1.f + expf(-s));
}

// ================= layernorm =================
__global__ void layernorm_kernel(const float* __restrict__ y, const float* __restrict__ gamma,
                                 const float* __restrict__ beta, float* __restrict__ out) {
    __shared__ float red1[8], red2[8];
    size_t row = blockIdx.x;
    const float* p = y + row * Cdim;
    int tid = threadIdx.x;
    float v[3];
    float s = 0.f;
#pragma unroll
    for (int i = 0; i < 3; i++) { v[i] = p[tid + i * 256]; s += v[i]; }
#pragma unroll
    for (int o = 16; o > 0; o >>= 1) s += __shfl_xor_sync(~0u, s, o);
    int w = tid >> 5, lane = tid & 31;
    if (lane == 0) red1[w] = s;
    __syncthreads();
    s = 0.f;
#pragma unroll
    for (int i = 0; i < 8; i++) s += red1[i];
    float mu = s * (1.0f / 768.0f);
    float vs = 0.f;
#pragma unroll
    for (int i = 0; i < 3; i++) { float d = v[i] - mu; vs += d * d; }
#pragma unroll
    for (int o = 16; o > 0; o >>= 1) vs += __shfl_xor_sync(~0u, vs, o);
    if (lane == 0) red2[w] = vs;
    __syncthreads();
    vs = 0.f;
#pragma unroll
    for (int i = 0; i < 8; i++) vs += red2[i];
    float inv = rsqrtf(vs * (1.0f / 768.0f) + 1e-5f);
#pragma unroll
    for (int i = 0; i < 3; i++) {
        int c = tid + i * 256;
        out[row * Cdim + c] = (v[i] - mu) * inv * gamma[c] + beta[c];
    }
}

// ================= launch =================
extern "C" void kernel_launch(void* const* d_in, const int* in_sizes, int n_in,
                              void* d_out, int out_size) {
    const float* x      = (const float*)d_in[0];
    const float* w_qkv  = (const float*)d_in[1];
    const float* b_qkv  = (const float*)d_in[2];
    const float* w_proj = (const float*)d_in[3];
    const float* b_proj = (const float*)d_in[4];
    const float* gamma  = (const float*)d_in[5];
    const float* beta   = (const float*)d_in[6];
    const float* qe_w1  = (const float*)d_in[7];
    const float* qe_b1  = (const float*)d_in[8];
    const float* qe_w2  = (const float*)d_in[9];
    const float* qe_b2  = (const float*)d_in[10];
    const float* ke_w1  = (const float*)d_in[11];
    const float* ke_b1  = (const float*)d_in[12];
    const float* ke_w2  = (const float*)d_in[13];
    const float* ke_b2  = (const float*)d_in[14];
    const float* gate_params = (const float*)d_in[19];
    const float* ent_params  = (const float*)d_in[20];
    const float* md_w1  = (const float*)d_in[21];
    const float* md_b1  = (const float*)d_in[22];
    const float* md_w2  = (const float*)d_in[23];
    const float* md_b2  = (const float*)d_in[24];
    const float* gumbel = (const float*)d_in[25];
    float* out = (float*)d_out;

    float *qkv, *qout, *fused, *xmean, *fw, *hq, *hk, *meas;
    cudaGetSymbolAddress((void**)&qkv, g_qkv);
    cudaGetSymbolAddress((void**)&qout, g_qout);
    cudaGetSymbolAddress((void**)&fused, g_fused);
    cudaGetSymbolAddress((void**)&xmean, g_xmean);
    cudaGetSymbolAddress((void**)&fw, g_fw);
    cudaGetSymbolAddress((void**)&hq, g_hq);
    cudaGetSymbolAddress((void**)&hk, g_hk);
    cudaGetSymbolAddress((void**)&meas, g_meas);

    cudaFuncSetAttribute(flash_kernel, cudaFuncAttributeMaxDynamicSharedMemorySize, FLASH_SMEM);
    cudaFuncSetAttribute(md_fused, cudaFuncAttributeMaxDynamicSharedMemorySize, MD_SMEM);

    // gate path (depends only on x)
    colmean_kernel<<<dim3(3, 8), 256>>>(x, xmean);
    fw_kernel<<<8, 768>>>(xmean, w_proj, b_proj, fw);
    // qkv = x @ w_qkv + b_qkv
    mma_nn<<<dim3(2304 / 128, 8192 / 128), 256>>>(x, w_qkv, b_qkv, nullptr, qkv,
                                                  768, 768, 2304, 2304);
    // quantum path: embeds (GEMM) -> mid -> measure MLP (GEMM) -> qout
    embed_gemm<<<NTOK / 128, 256>>>(qkv, 0, qe_w1, qe_b1, hq);
    embed_gemm<<<NTOK / 128, 256>>>(qkv, 768, ke_w1, ke_b1, hk);
    quantum_mid<<<NTOK / 128, 128>>>(hq, hk, qe_w2, qe_b2, ke_w2, ke_b2,
                                     gate_params, ent_params, gumbel, meas);
    md_fused<<<NTOK / 128, 256, MD_SMEM>>>(meas, md_w1, md_b1, md_w2, md_b2, qkv, qout);
    // fused classical attention + gate blend -> fused
    flash_kernel<<<dim3(8, 64), 256, FLASH_SMEM>>>(qkv, qout, fw, fused);
    // y = x + fused @ w_proj + b_proj  (reuse qout as y)
    mma_nn<<<dim3(768 / 128, 8192 / 128), 256>>>(fused, w_proj, b_proj, x, qout,
                                                 768, 768, 768, 768);
    // layernorm
    layernorm_kernel<<<8192, 256>>>(qout, gamma, beta, out);
}

// round 8
// speedup vs baseline: 4.9281x; 1.1322x over previous
#include <cuda_runtime.h>
#include <cuda_bf16.h>
#include <math.h>
#include <stdint.h>

// ---------------- scratch ----------------
#define Bsz 8
#define Nseq 1024
#define Cdim 768
#define Hh 8
#define Dd 96
#define Qq 8
#define NTOK (Bsz * Hh * Nseq)   // 65536, ordered m=(b,n,h)

__device__ uint32_t g_qkv_bf[Bsz * Nseq * 3 * Cdim / 2];   // bf16x2
__device__ uint32_t g_fused_bf[Bsz * Nseq * Cdim / 2];     // bf16x2
__device__ float g_qout[Bsz * Nseq * Cdim];
__device__ float g_y[Bsz * Nseq * Cdim];
__device__ float g_xmean[Bsz * Cdim];
__device__ float g_fw[Bsz * Cdim];
__device__ float g_hq[NTOK * 64];
__device__ float g_hk[NTOK * 64];
__device__ float g_meas[NTOK * 8];

// ---------------- mma helpers ----------------
__device__ __forceinline__ float to_tf32(float x) {
    uint32_t u;
    asm("cvt.rna.tf32.f32 %0, %1;" : "=r"(u) : "f"(x));
    return __uint_as_float(u);
}

__device__ __forceinline__ uint32_t pkbf(float x, float y) {
    __nv_bfloat162 t = __floats2bfloat162_rn(x, y);
    return *(uint32_t*)&t;
}

__device__ __forceinline__ void mma_tf32(float* c, const uint32_t* a, const uint32_t* b) {
    asm volatile(
        "mma.sync.aligned.m16n8k8.row.col.f32.tf32.tf32.f32 "
        "{%0,%1,%2,%3}, {%4,%5,%6,%7}, {%8,%9}, {%0,%1,%2,%3};"
        : "+f"(c[0]), "+f"(c[1]), "+f"(c[2]), "+f"(c[3])
        : "r"(a[0]), "r"(a[1]), "r"(a[2]), "r"(a[3]), "r"(b[0]), "r"(b[1]));
}

__device__ __forceinline__ void mma_bf16(float* c, const uint32_t* a, const uint32_t* b) {
    asm volatile(
        "mma.sync.aligned.m16n8k16.row.col.f32.bf16.bf16.f32 "
        "{%0,%1,%2,%3}, {%4,%5,%6,%7}, {%8,%9}, {%0,%1,%2,%3};"
        : "+f"(c[0]), "+f"(c[1]), "+f"(c[2]), "+f"(c[3])
        : "r"(a[0]), "r"(a[1]), "r"(a[2]), "r"(a[3]), "r"(b[0]), "r"(b[1]));
}

// ================= qkv GEMM: bf16 out. A fp32, B fp32 =================
// BM=128, BN=128, BK=16. C (bf16x2) = A@B + bias.
__global__ __launch_bounds__(256)
void mma_qkv(const float* __restrict__ A, const float* __restrict__ B,
             const float* __restrict__ bias, uint32_t* __restrict__ Cbf,
             int K, int lda, int ldb, int ldc) {
    __shared__ uint32_t As[2][8][136];
    __shared__ uint32_t Bs[2][8][136];
    int tid = threadIdx.x;
    int m0 = blockIdx.y * 128, n0 = blockIdx.x * 128;
    int arow = tid >> 1, apart = tid & 1;
    int bk2 = tid >> 5, bcol = (tid & 31) * 4;
    const float* Ap = A + (size_t)(m0 + arow) * lda;
    const float* Bp0 = B + (size_t)(2 * bk2) * ldb + n0 + bcol;
    const float* Bp1 = B + (size_t)(2 * bk2 + 1) * ldb + n0 + bcol;

    int wid = tid >> 5, lane = tid & 31;
    int wm = (wid >> 2) * 64, wn = (wid & 3) * 32;
    int grp = lane >> 2, tig = lane & 3;
    float acc[4][4][4] = {};

    {
        float4 a0 = *(const float4*)(Ap + apart * 4);
        float4 a1 = *(const float4*)(Ap + apart * 4 + 8);
        As[0][apart * 2 + 0][arow] = pkbf(a0.x, a0.y);
        As[0][apart * 2 + 1][arow] = pkbf(a0.z, a0.w);
        As[0][apart * 2 + 4][arow] = pkbf(a1.x, a1.y);
        As[0][apart * 2 + 5][arow] = pkbf(a1.z, a1.w);
        float4 b0 = *(const float4*)Bp0;
        float4 b1 = *(const float4*)Bp1;
        *(uint4*)&Bs[0][bk2][bcol] = make_uint4(pkbf(b0.x, b1.x), pkbf(b0.y, b1.y),
                                                pkbf(b0.z, b1.z), pkbf(b0.w, b1.w));
    }
    __syncthreads();

    int S = K / 16, buf = 0;
    for (int s = 1; s <= S; s++) {
        bool more = (s < S);
        float4 a0, a1, b0, b1;
        if (more) {
            int k0 = s * 16;
            a0 = *(const float4*)(Ap + k0 + apart * 4);
            a1 = *(const float4*)(Ap + k0 + apart * 4 + 8);
            b0 = *(const float4*)(Bp0 + (size_t)k0 * ldb);
            b1 = *(const float4*)(Bp1 + (size_t)k0 * ldb);
        }
        uint32_t a[4][4], b[4][2];
#pragma unroll
        for (int mi = 0; mi < 4; mi++) {
            int r = wm + mi * 16 + grp;
            a[mi][0] = As[buf][tig][r];
            a[mi][1] = As[buf][tig][r + 8];
            a[mi][2] = As[buf][tig + 4][r];
            a[mi][3] = As[buf][tig + 4][r + 8];
        }
#pragma unroll
        for (int nj = 0; nj < 4; nj++) {
            int c = wn + nj * 8 + grp;
            b[nj][0] = Bs[buf][tig][c];
            b[nj][1] = Bs[buf][tig + 4][c];
        }
#pragma unroll
        for (int mi = 0; mi < 4; mi++)
#pragma unroll
            for (int nj = 0; nj < 4; nj++) mma_bf16(acc[mi][nj], a[mi], b[nj]);
        if (more) {
            As[buf ^ 1][apart * 2 + 0][arow] = pkbf(a0.x, a0.y);
            As[buf ^ 1][apart * 2 + 1][arow] = pkbf(a0.z, a0.w);
            As[buf ^ 1][apart * 2 + 4][arow] = pkbf(a1.x, a1.y);
            As[buf ^ 1][apart * 2 + 5][arow] = pkbf(a1.z, a1.w);
            *(uint4*)&Bs[buf ^ 1][bk2][bcol] = make_uint4(pkbf(b0.x, b1.x), pkbf(b0.y, b1.y),
                                                          pkbf(b0.z, b1.z), pkbf(b0.w, b1.w));
            __syncthreads();
            buf ^= 1;
        }
    }

#pragma unroll
    for (int nj = 0; nj < 4; nj++) {
        int c = n0 + wn + nj * 8 + tig * 2;
        float bi0 = bias[c], bi1 = bias[c + 1];
#pragma unroll
        for (int mi = 0; mi < 4; mi++) {
            size_t r = m0 + wm + mi * 16 + grp;
            Cbf[(r * ldc + c) >> 1] = pkbf(acc[mi][nj][0] + bi0, acc[mi][nj][1] + bi1);
            Cbf[((r + 8) * ldc + c) >> 1] = pkbf(acc[mi][nj][2] + bi0, acc[mi][nj][3] + bi1);
        }
    }
}

// ================= proj GEMM: A bf16 (fused), B fp32, out fp32 + resid =================
__global__ __launch_bounds__(256)
void mma_proj(const uint32_t* __restrict__ Abf, const float* __restrict__ B,
              const float* __restrict__ bias, const float* __restrict__ resid,
              float* __restrict__ C, int K, int lda, int ldb, int ldc) {
    __shared__ uint32_t As[2][8][136];
    __shared__ uint32_t Bs[2][8][136];
    int tid = threadIdx.x;
    int m0 = blockIdx.y * 128, n0 = blockIdx.x * 128;
    int arow = tid >> 1, apart = tid & 1;
    int bk2 = tid >> 5, bcol = (tid & 31) * 4;
    const uint4* Ap4 = (const uint4*)(Abf + (size_t)(m0 + arow) * (lda / 2));
    const float* Bp0 = B + (size_t)(2 * bk2) * ldb + n0 + bcol;
    const float* Bp1 = B + (size_t)(2 * bk2 + 1) * ldb + n0 + bcol;

    int wid = tid >> 5, lane = tid & 31;
    int wm = (wid >> 2) * 64, wn = (wid & 3) * 32;
    int grp = lane >> 2, tig = lane & 3;
    float acc[4][4][4] = {};

    {
        uint4 av = Ap4[apart];
        As[0][apart * 4 + 0][arow] = av.x;
        As[0][apart * 4 + 1][arow] = av.y;
        As[0][apart * 4 + 2][arow] = av.z;
        As[0][apart * 4 + 3][arow] = av.w;
        float4 b0 = *(const float4*)Bp0;
        float4 b1 = *(const float4*)Bp1;
        *(uint4*)&Bs[0][bk2][bcol] = make_uint4(pkbf(b0.x, b1.x), pkbf(b0.y, b1.y),
                                                pkbf(b0.z, b1.z), pkbf(b0.w, b1.w));
    }
    __syncthreads();

    int S = K / 16, buf = 0;
    for (int s = 1; s <= S; s++) {
        bool more = (s < S);
        uint4 av;
        float4 b0, b1;
        if (more) {
            av = Ap4[s * 2 + apart];
            int k0 = s * 16;
            b0 = *(const float4*)(Bp0 + (size_t)k0 * ldb);
            b1 = *(const float4*)(Bp1 + (size_t)k0 * ldb);
        }
        uint32_t a[4][4], b[4][2];
#pragma unroll
        for (int mi = 0; mi < 4; mi++) {
            int r = wm + mi * 16 + grp;
            a[mi][0] = As[buf][tig][r];
            a[mi][1] = As[buf][tig][r + 8];
            a[mi][2] = As[buf][tig + 4][r];
            a[mi][3] = As[buf][tig + 4][r + 8];
        }
#pragma unroll
        for (int nj = 0; nj < 4; nj++) {
            int c = wn + nj * 8 + grp;
            b[nj][0] = Bs[buf][tig][c];
            b[nj][1] = Bs[buf][tig + 4][c];
        }
#pragma unroll
        for (int mi = 0; mi < 4; mi++)
#pragma unroll
            for (int nj = 0; nj < 4; nj++) mma_bf16(acc[mi][nj], a[mi], b[nj]);
        if (more) {
            As[buf ^ 1][apart * 4 + 0][arow] = av.x;
            As[buf ^ 1][apart * 4 + 1][arow] = av.y;
            As[buf ^ 1][apart * 4 + 2][arow] = av.z;
            As[buf ^ 1][apart * 4 + 3][arow] = av.w;
            *(uint4*)&Bs[buf ^ 1][bk2][bcol] = make_uint4(pkbf(b0.x, b1.x), pkbf(b0.y, b1.y),
                                                          pkbf(b0.z, b1.z), pkbf(b0.w, b1.w));
            __syncthreads();
            buf ^= 1;
        }
    }

#pragma unroll
    for (int nj = 0; nj < 4; nj++) {
        int c = n0 + wn + nj * 8 + tig * 2;
        float bi0 = bias[c], bi1 = bias[c + 1];
#pragma unroll
        for (int mi = 0; mi < 4; mi++) {
            size_t r = m0 + wm + mi * 16 + grp;
            float2 r0 = *(const float2*)(resid + r * ldc + c);
            float2 r1 = *(const float2*)(resid + (r + 8) * ldc + c);
            *(float2*)(C + r * ldc + c) =
                make_float2(acc[mi][nj][0] + bi0 + r0.x, acc[mi][nj][1] + bi1 + r0.y);
            *(float2*)(C + (r + 8) * ldc + c) =
                make_float2(acc[mi][nj][2] + bi0 + r1.x, acc[mi][nj][3] + bi1 + r1.y);
        }
    }
}

// ================= fused flash attention (bf16 in/out) + gate blend =================
#define LDQ 136
#define LDV 104
#define FLASH_SMEM ((2 * 48 * LDQ + 64 * LDV) * 4)

__global__ __launch_bounds__(256, 1)
void flash_kernel(const uint32_t* __restrict__ qkvbf, const float* __restrict__ qout,
                  const float* __restrict__ fw, uint32_t* __restrict__ fusedbf) {
    extern __shared__ uint32_t smu[];
    uint32_t* Qs = smu;
    uint32_t* Ks = smu + 48 * LDQ;
    uint32_t* Vs = smu + 2 * 48 * LDQ;

    int tid = threadIdx.x;
    int z = blockIdx.y;
    int b = z >> 3, h = z & 7;
    int q0 = blockIdx.x * 128;
    const uint32_t* qb32 = qkvbf + (size_t)b * Nseq * 1152 + h * 48;
    const uint32_t* kb32 = qb32 + 384;
    const uint32_t* vb32 = qb32 + 768;

    int lane = tid & 31, wid = tid >> 5;
    int grp = lane >> 2, tig = lane & 3;
    int wrow = wid * 16;

    for (int i = tid; i < 6144; i += 256) {
        int d2 = i % 48, r = i / 48;
        Qs[d2 * LDQ + r] = qb32[(size_t)(q0 + r) * 1152 + d2];
    }

    float o[12][4] = {};
    float m0 = -1e30f, m1 = -1e30f, l0 = 0.f, l1 = 0.f;
    const float scale = 0.10206207261596577f;

    for (int t = 0; t < 8; t++) {
        __syncthreads();
        int kv0 = t * 128;
        for (int i = tid; i < 6144; i += 256) {
            int d2 = i % 48, r = i / 48;
            Ks[d2 * LDQ + r] = kb32[(size_t)(kv0 + r) * 1152 + d2];
        }
        for (int i = tid; i < 3072; i += 256) {
            int j2 = i / 48, k = i % 48;
            uint32_t u0 = vb32[(size_t)(kv0 + 2 * j2) * 1152 + k];
            uint32_t u1 = vb32[(size_t)(kv0 + 2 * j2 + 1) * 1152 + k];
            Vs[j2 * LDV + 2 * k]     = __byte_perm(u0, u1, 0x5410);
            Vs[j2 * LDV + 2 * k + 1] = __byte_perm(u0, u1, 0x7632);
        }
        __syncthreads();

        float s[16][4] = {};
#pragma unroll
        for (int ks = 0; ks < 6; ks++) {
            uint32_t a[4];
            a[0] = Qs[(ks * 8 + tig) * LDQ + wrow + grp];
            a[1] = Qs[(ks * 8 + tig) * LDQ + wrow + grp + 8];
            a[2] = Qs[(ks * 8 + tig + 4) * LDQ + wrow + grp];
            a[3] = Qs[(ks * 8 + tig + 4) * LDQ + wrow + grp + 8];
#pragma unroll
            for (int n = 0; n < 16; n++) {
                uint32_t bb[2];
                bb[0] = Ks[(ks * 8 + tig) * LDQ + n * 8 + grp];
                bb[1] = Ks[(ks * 8 + tig + 4) * LDQ + n * 8 + grp];
                mma_bf16(s[n], a, bb);
            }
        }

        float mx0 = -1e30f, mx1 = -1e30f;
#pragma unroll
        for (int n = 0; n < 16; n++) {
            mx0 = fmaxf(mx0, fmaxf(s[n][0], s[n][1]));
            mx1 = fmaxf(mx1, fmaxf(s[n][2], s[n][3]));
        }
        mx0 = fmaxf(mx0, __shfl_xor_sync(~0u, mx0, 1));
        mx0 = fmaxf(mx0, __shfl_xor_sync(~0u, mx0, 2));
        mx1 = fmaxf(mx1, __shfl_xor_sync(~0u, mx1, 1));
        mx1 = fmaxf(mx1, __shfl_xor_sync(~0u, mx1, 2));
        float nm0 = fmaxf(m0, mx0 * scale);
        float nm1 = fmaxf(m1, mx1 * scale);
        float al0 = __expf(m0 - nm0), al1 = __expf(m1 - nm1);
        m0 = nm0; m1 = nm1;
        float sum0 = 0.f, sum1 = 0.f;
#pragma unroll
        for (int n = 0; n < 16; n++) {
            float p0 = __expf(s[n][0] * scale - nm0);
            float p1 = __expf(s[n][1] * scale - nm0);
            float p2 = __expf(s[n][2] * scale - nm1);
            float p3 = __expf(s[n][3] * scale - nm1);
            sum0 += p0 + p1; sum1 += p2 + p3;
            s[n][0] = p0; s[n][1] = p1; s[n][2] = p2; s[n][3] = p3;
        }
        sum0 += __shfl_xor_sync(~0u, sum0, 1);
        sum0 += __shfl_xor_sync(~0u, sum0, 2);
        sum1 += __shfl_xor_sync(~0u, sum1, 1);
        sum1 += __shfl_xor_sync(~0u, sum1, 2);
        l0 = l0 * al0 + sum0;
        l1 = l1 * al1 + sum1;
#pragma unroll
        for (int n = 0; n < 12; n++) {
            o[n][0] *= al0; o[n][1] *= al0;
            o[n][2] *= al1; o[n][3] *= al1;
        }

#pragma unroll
        for (int jb = 0; jb < 8; jb++) {
            uint32_t a[4];
            a[0] = pkbf(s[2 * jb][0], s[2 * jb][1]);
            a[1] = pkbf(s[2 * jb][2], s[2 * jb][3]);
            a[2] = pkbf(s[2 * jb + 1][0], s[2 * jb + 1][1]);
            a[3] = pkbf(s[2 * jb + 1][2], s[2 * jb + 1][3]);
#pragma unroll
            for (int n = 0; n < 12; n++) {
                uint32_t bb[2];
                bb[0] = Vs[(jb * 8 + tig) * LDV + n * 8 + grp];
                bb[1] = Vs[(jb * 8 + tig + 4) * LDV + n * 8 + grp];
                mma_bf16(o[n], a, bb);
            }
        }
    }

    float inv0 = 1.f / l0, inv1 = 1.f / l1;
    int row0 = q0 + wrow + grp;
#pragma unroll
    for (int n = 0; n < 12; n++) {
        int c = n * 8 + tig * 2;
        float f0 = fw[b * Cdim + h * Dd + c];
        float f1 = fw[b * Cdim + h * Dd + c + 1];
        size_t ob0 = ((size_t)b * Nseq + row0) * Cdim + h * Dd + c;
        size_t ob1 = ((size_t)b * Nseq + row0 + 8) * Cdim + h * Dd + c;
        float2 qv0 = *(const float2*)(qout + ob0);
        float2 qv1 = *(const float2*)(qout + ob1);
        fusedbf[ob0 >> 1] = pkbf(f0 * qv0.x + (1.f - f0) * o[n][0] * inv0,
                                 f1 * qv0.y + (1.f - f1) * o[n][1] * inv0);
        fusedbf[ob1 >> 1] = pkbf(f0 * qv1.x + (1.f - f0) * o[n][2] * inv1,
                                 f1 * qv1.y + (1.f - f1) * o[n][3] * inv1);
    }
}

// ================= quantum embed GEMM (bf16 A): H = relu(A @ W1 + b1) =================
// grid.y: 0 = q-embed, 1 = k-embed
__global__ __launch_bounds__(256)
void embed_gemm(const uint32_t* __restrict__ qkvbf,
                const float* __restrict__ qW1, const float* __restrict__ qb1,
                const float* __restrict__ kW1, const float* __restrict__ kb1,
                float* __restrict__ Hq, float* __restrict__ Hk) {
    __shared__ uint32_t As[2][8][136];
    __shared__ uint32_t Bs[48][72];
    int tid = threadIdx.x;
    int m0 = blockIdx.x * 128;
    int pass = blockIdx.y;
    const float* W1 = pass ? kW1 : qW1;
    const float* b1 = pass ? kb1 : qb1;
    float* H = pass ? Hk : Hq;
    int qk_off32 = pass * 384;

    for (int i = tid; i < 768; i += 256) {
        int k2 = i >> 4, c4 = i & 15;
        float4 w0 = *(const float4*)(W1 + (2 * k2) * 64 + c4 * 4);
        float4 w1 = *(const float4*)(W1 + (2 * k2 + 1) * 64 + c4 * 4);
        *(uint4*)&Bs[k2][c4 * 4] = make_uint4(pkbf(w0.x, w1.x), pkbf(w0.y, w1.y),
                                              pkbf(w0.z, w1.z), pkbf(w0.w, w1.w));
    }

    int arow = tid >> 1, apart = tid & 1;
    int mrow = m0 + arow;
    const uint4* Ap4 = (const uint4*)(qkvbf + (size_t)(mrow >> 3) * 1152 + qk_off32 + (mrow & 7) * 48);

    int wid = tid >> 5, lane = tid & 31;
    int wm = (wid >> 2) * 64, wn = (wid & 3) * 16;
    int grp = lane >> 2, tig = lane & 3;
    float acc[4][2][4] = {};

    {
        uint4 av = Ap4[apart];
        As[0][apart * 4 + 0][arow] = av.x;
        As[0][apart * 4 + 1][arow] = av.y;
        As[0][apart * 4 + 2][arow] = av.z;
        As[0][apart * 4 + 3][arow] = av.w;
    }
    __syncthreads();

    int buf = 0;
    for (int s = 1; s <= 6; s++) {
        bool more = (s < 6);
        uint4 av;
        if (more) av = Ap4[s * 2 + apart];
        int kb = (s - 1) * 8;
        uint32_t a[4][4], b[2][2];
#pragma unroll
        for (int mi = 0; mi < 4; mi++) {
            int r = wm + mi * 16 + grp;
            a[mi][0] = As[buf][tig][r];
            a[mi][1] = As[buf][tig][r + 8];
            a[mi][2] = As[buf][tig + 4][r];
            a[mi][3] = As[buf][tig + 4][r + 8];
        }
#pragma unroll
        for (int nj = 0; nj < 2; nj++) {
            int c = wn + nj * 8 + grp;
            b[nj][0] = Bs[kb + tig][c];
            b[nj][1] = Bs[kb + tig + 4][c];
        }
#pragma unroll
        for (int mi = 0; mi < 4; mi++)
#pragma unroll
            for (int nj = 0; nj < 2; nj++) mma_bf16(acc[mi][nj], a[mi], b[nj]);
        if (more) {
            As[buf ^ 1][apart * 4 + 0][arow] = av.x;
            As[buf ^ 1][apart * 4 + 1][arow] = av.y;
            As[buf ^ 1][apart * 4 + 2][arow] = av.z;
            As[buf ^ 1][apart * 4 + 3][arow] = av.w;
            __syncthreads();
            buf ^= 1;
        }
    }

#pragma unroll
    for (int nj = 0; nj < 2; nj++) {
        int c = wn + nj * 8 + tig * 2;
        float bi0 = __ldg(&b1[c]), bi1 = __ldg(&b1[c + 1]);
#pragma unroll
        for (int mi = 0; mi < 4; mi++) {
            size_t r = m0 + wm + mi * 16 + grp;
            *(float2*)(H + r * 64 + c) =
                make_float2(fmaxf(acc[mi][nj][0] + bi0, 0.f), fmaxf(acc[mi][nj][1] + bi1, 0.f));
            *(float2*)(H + (r + 8) * 64 + c) =
                make_float2(fmaxf(acc[mi][nj][2] + bi0, 0.f), fmaxf(acc[mi][nj][3] + bi1, 0.f));
        }
    }
}

// ================= quantum middle: e -> state -> meas =================
__global__ __launch_bounds__(128)
void quantum_mid(const float* __restrict__ Hq, const float* __restrict__ Hk,
                 const float* __restrict__ qe_w2, const float* __restrict__ qe_b2,
                 const float* __restrict__ ke_w2, const float* __restrict__ ke_b2,
                 const float* __restrict__ gate_params, const float* __restrict__ ent_params,
                 const float* __restrict__ gumbel, float* __restrict__ meas_out) {
    __shared__ float w2q[1024], w2k[1024];
    __shared__ float gf[2][8], gcz[2][8], gsz[2][8], gs[2][8];
    int tid = threadIdx.x;
    for (int i = tid; i < 256; i += 128) {
        ((float4*)w2q)[i] = ((const float4*)qe_w2)[i];
        ((float4*)w2k)[i] = ((const float4*)ke_w2)[i];
    }
    if (tid < 16) {
        int l = tid >> 3, i = tid & 7;
        float ry = gate_params[(l * 8 + i) * 3 + 1];
        float rz = gate_params[(l * 8 + i) * 3 + 2];
        gf[l][i] = cosf(0.5f * ry);
        gcz[l][i] = cosf(rz);
        gsz[l][i] = sinf(rz);
    } else if (tid < 30) {
        int t = tid - 16, l = t / 7, i = t % 7;
        gs[l][i + 1] = 1.f / (1.f + expf(-ent_params[l * 7 + i]));
    }
    __syncthreads();

    int m = blockIdx.x * 128 + tid;
    float sre[8], sim[8];

#pragma unroll
    for (int pass = 0; pass < 2; pass++) {
        const float* Hrow = (pass == 0 ? Hq : Hk) + (size_t)m * 64;
        const float* w2 = (pass == 0 ? w2q : w2k);
        const float* b2 = (pass == 0 ? qe_b2 : ke_b2);
        float e[16];
#pragma unroll
        for (int i = 0; i < 16; i++) e[i] = __ldg(&b2[i]);
        const float4* h4 = (const float4*)Hrow;
#pragma unroll
        for (int j4 = 0; j4 < 16; j4++) {
            float4 hv = h4[j4];
            float hs[4] = {hv.x, hv.y, hv.z, hv.w};
#pragma unroll
            for (int s = 0; s < 4; s++) {
                float hj = hs[s];
                const float4* wr = (const float4*)&w2[(j4 * 4 + s) * 16];
#pragma unroll
                for (int i4 = 0; i4 < 4; i4++) {
                    float4 w = wr[i4];
                    e[i4 * 4 + 0] += hj * w.x; e[i4 * 4 + 1] += hj * w.y;
                    e[i4 * 4 + 2] += hj * w.z; e[i4 * 4 + 3] += hj * w.w;
                }
            }
        }
        float mx = e[0];
#pragma unroll
        for (int i = 1; i < 8; i++) mx = fmaxf(mx, e[i]);
        float ex[8], ssum = 0.f;
#pragma unroll
        for (int i = 0; i < 8; i++) { ex[i] = __expf(e[i] - mx); ssum += ex[i]; }
        float inv = 1.f / ssum;
#pragma unroll
        for (int i = 0; i < 8; i++) {
            float amp = ex[i] * inv;
            float cr = amp * __cosf(e[8 + i]), ci = amp * __sinf(e[8 + i]);
            if (pass == 0) { sre[i] = cr; sim[i] = ci; }
            else           { sre[i] += cr; sim[i] += ci; }
        }
    }

#pragma unroll
    for (int l = 0; l < 2; l++) {
#pragma unroll
        for (int i = 0; i < 8; i++) {
            float nr = sre[i] * gcz[l][i] - sim[i] * gsz[l][i];
            float ni = sre[i] * gsz[l][i] + sim[i] * gcz[l][i];
            sre[i] = nr * gf[l][i];
            sim[i] = ni * gf[l][i];
        }
#pragma unroll
        for (int i = 7; i >= 1; i--) {
            sre[i] += gs[l][i] * sre[i - 1];
            sim[i] += gs[l][i] * sim[i - 1];
        }
    }

    float p[8], mx = -1e30f;
#pragma unroll
    for (int i = 0; i < 8; i++) { p[i] = sre[i] * sre[i] + sim[i] * sim[i]; mx = fmaxf(mx, p[i]); }
    float ssum = 0.f;
#pragma unroll
    for (int i = 0; i < 8; i++) { p[i] = __expf(p[i] - mx); ssum += p[i]; }
    float sinv = 1.f / ssum;
    int b = m >> 13, n = (m >> 3) & 1023, h = m & 7;
    size_t goff = (size_t)(((b * 8 + h) << 10) + n) * 8;
    float4 g0 = __ldg((const float4*)(gumbel + goff));
    float4 g1 = __ldg((const float4*)(gumbel + goff + 4));
    float gv[8] = {g0.x, g0.y, g0.z, g0.w, g1.x, g1.y, g1.z, g1.w};
    float lg[8], mx2 = -1e30f;
#pragma unroll
    for (int i = 0; i < 8; i++) {
        lg[i] = 2.f * (__logf(p[i] * sinv + 1e-10f) + gv[i]);
        mx2 = fmaxf(mx2, lg[i]);
    }
    float meas[8], msum = 0.f;
#pragma unroll
    for (int i = 0; i < 8; i++) { meas[i] = __expf(lg[i] - mx2); msum += meas[i]; }
    float minv = 1.f / msum;
    float4 o0 = make_float4(meas[0] * minv, meas[1] * minv, meas[2] * minv, meas[3] * minv);
    float4 o1 = make_float4(meas[4] * minv, meas[5] * minv, meas[6] * minv, meas[7] * minv);
    *(float4*)(meas_out + (size_t)m * 8) = o0;
    *(float4*)(meas_out + (size_t)m * 8 + 4) = o1;
}

// ================= fused measure MLP (tf32): qout = (relu(meas@W1+b1)@W2+b2)*v =================
#define MD_T1_LD 136
#define MD_W2_LD 104
#define MD_SMEM ((8 * 136 + 8 * 72 + 64 * MD_T1_LD + 64 * MD_W2_LD) * 4)

__global__ __launch_bounds__(256)
void md_fused(const float* __restrict__ meas,
              const float* __restrict__ W1, const float* __restrict__ b1,
              const float* __restrict__ W2, const float* __restrict__ b2,
              const uint32_t* __restrict__ qkvbf, float* __restrict__ qout) {
    extern __shared__ float sm[];
    float* As8 = sm;
    float* W1s = sm + 8 * 136;
    float* T1  = sm + 8 * 136 + 8 * 72;
    float* W2s = T1 + 64 * MD_T1_LD;

    int tid = threadIdx.x;
    int m0 = blockIdx.x * 128;
    int wid = tid >> 5, lane = tid & 31;
    int grp = lane >> 2, tig = lane & 3;
    int wm = (wid >> 2) * 64;

    {
        int arow = tid >> 1, ak = (tid & 1) * 4;
        float4 v = *(const float4*)(meas + (size_t)(m0 + arow) * 8 + ak);
        As8[(ak + 0) * 136 + arow] = to_tf32(v.x);
        As8[(ak + 1) * 136 + arow] = to_tf32(v.y);
        As8[(ak + 2) * 136 + arow] = to_tf32(v.z);
        As8[(ak + 3) * 136 + arow] = to_tf32(v.w);
    }
    for (int i = tid; i < 128; i += 256) {
        int d = i >> 4, n4 = i & 15;
        float4 w = ((const float4*)W1)[i];
        float4 wc = make_float4(to_tf32(w.x), to_tf32(w.y), to_tf32(w.z), to_tf32(w.w));
        *(float4*)&W1s[d * 72 + n4 * 4] = wc;
    }
    for (int i = tid; i < 1536; i += 256) {
        int d = i / 24, n4 = i % 24;
        float4 w = ((const float4*)W2)[i];
        float4 wc = make_float4(to_tf32(w.x), to_tf32(w.y), to_tf32(w.z), to_tf32(w.w));
        *(float4*)&W2s[d * MD_W2_LD + n4 * 4] = wc;
    }
    __syncthreads();

    {
        int wn1 = (wid & 3) * 16;
        float acc1[4][2][4] = {};
        uint32_t a[4][4], b[2][2];
#pragma unroll
        for (int mi = 0; mi < 4; mi++) {
            int r = wm + mi * 16 + grp;
            a[mi][0] = __float_as_uint(As8[tig * 136 + r]);
            a[mi][1] = __float_as_uint(As8[tig * 136 + r + 8]);
            a[mi][2] = __float_as_uint(As8[(tig + 4) * 136 + r]);
            a[mi][3] = __float_as_uint(As8[(tig + 4) * 136 + r + 8]);
        }
#pragma unroll
        for (int nj = 0; nj < 2; nj++) {
            int c = wn1 + nj * 8 + grp;
            b[nj][0] = __float_as_uint(W1s[tig * 72 + c]);
            b[nj][1] = __float_as_uint(W1s[(tig + 4) * 72 + c]);
        }
#pragma unroll
        for (int mi = 0; mi < 4; mi++)
#pragma unroll
            for (int nj = 0; nj < 2; nj++) mma_tf32(acc1[mi][nj], a[mi], b[nj]);

#pragma unroll
        for (int nj = 0; nj < 2; nj++) {
            int c = wn1 + nj * 8 + tig * 2;
            float bi0 = __ldg(&b1[c]), bi1 = __ldg(&b1[c + 1]);
#pragma unroll
            for (int mi = 0; mi < 4; mi++) {
                int r = wm + mi * 16 + grp;
                T1[c * MD_T1_LD + r]           = to_tf32(fmaxf(acc1[mi][nj][0] + bi0, 0.f));
                T1[(c + 1) * MD_T1_LD + r]     = to_tf32(fmaxf(acc1[mi][nj][1] + bi1, 0.f));
                T1[c * MD_T1_LD + r + 8]       = to_tf32(fmaxf(acc1[mi][nj][2] + bi0, 0.f));
                T1[(c + 1) * MD_T1_LD + r + 8] = to_tf32(fmaxf(acc1[mi][nj][3] + bi1, 0.f));
            }
        }
    }
    __syncthreads();

    int wn = (wid & 3) * 24;
    float acc2[4][3][4] = {};
#pragma unroll
    for (int ks = 0; ks < 8; ks++) {
        uint32_t a[4][4], b[3][2];
#pragma unroll
        for (int mi = 0; mi < 4; mi++) {
            int r = wm + mi * 16 + grp;
            a[mi][0] = __float_as_uint(T1[(ks * 8 + tig) * MD_T1_LD + r]);
            a[mi][1] = __float_as_uint(T1[(ks * 8 + tig) * MD_T1_LD + r + 8]);
            a[mi][2] = __float_as_uint(T1[(ks * 8 + tig + 4) * MD_T1_LD + r]);
            a[mi][3] = __float_as_uint(T1[(ks * 8 + tig + 4) * MD_T1_LD + r + 8]);
        }
#pragma unroll
        for (int nj = 0; nj < 3; nj++) {
            int c = wn + nj * 8 + grp;
            b[nj][0] = __float_as_uint(W2s[(ks * 8 + tig) * MD_W2_LD + c]);
            b[nj][1] = __float_as_uint(W2s[(ks * 8 + tig + 4) * MD_W2_LD + c]);
        }
#pragma unroll
        for (int mi = 0; mi < 4; mi++)
#pragma unroll
            for (int nj = 0; nj < 3; nj++) mma_tf32(acc2[mi][nj], a[mi], b[nj]);
    }

#pragma unroll
    for (int nj = 0; nj < 3; nj++) {
        int c = wn + nj * 8 + tig * 2;
        float bi0 = __ldg(&b2[c]), bi1 = __ldg(&b2[c + 1]);
#pragma unroll
        for (int mi = 0; mi < 4; mi++) {
            int m = m0 + wm + mi * 16 + grp;
#pragma unroll
            for (int half = 0; half < 2; half++) {
                int mm = m + half * 8;
                size_t qrow = (size_t)(mm >> 3);
                int hh = mm & 7;
                uint32_t u = qkvbf[(qrow * 2304 + 1536 + hh * 96 + c) >> 1];
                float2 vv = __bfloat1622float2(*(__nv_bfloat162*)&u);
                float o0 = (acc2[mi][nj][half * 2 + 0] + bi0) * vv.x;
                float o1 = (acc2[mi][nj][half * 2 + 1] + bi1) * vv.y;
                *(float2*)(qout + qrow * 768 + hh * 96 + c) = make_float2(o0, o1);
            }
        }
    }
}

// ================= mean over N =================
__global__ void colmean_kernel(const float* __restrict__ x, float* __restrict__ xmean) {
    int b = blockIdx.y;
    int c = blockIdx.x * 256 + threadIdx.x;
    const float* p = x + (size_t)b * Nseq * Cdim + c;
    float s = 0.f;
    for (int n = 0; n < Nseq; n++) s += p[(size_t)n * Cdim];
    xmean[b * Cdim + c] = s * (1.0f / 1024.0f);
}

// ================= fw = sigmoid(xmean @ w_proj + b_proj) =================
__global__ void fw_kernel(const float* __restrict__ xmean, const float* __restrict__ w_proj,
                          const float* __restrict__ b_proj, float* __restrict__ fw) {
    __shared__ float xm[768];
    int b = blockIdx.x;
    int c = threadIdx.x;
    xm[c] = xmean[b * Cdim + c];
    __syncthreads();
    float s = b_proj[c];
    for (int k = 0; k < 768; k++) s += xm[k] * w_proj[(size_t)k * 768 + c];
    fw[b * Cdim + c] = 1.f / (1.f + expf(-s));
}

// ================= layernorm =================
__global__ void layernorm_kernel(const float* __restrict__ y, const float* __restrict__ gamma,
                                 const float* __restrict__ beta, float* __restrict__ out) {
    __shared__ float red1[8], red2[8];
    size_t row = blockIdx.x;
    const float* p = y + row * Cdim;
    int tid = threadIdx.x;
    float v[3];
    float s = 0.f;
#pragma unroll
    for (int i = 0; i < 3; i++) { v[i] = p[tid + i * 256]; s += v[i]; }
#pragma unroll
    for (int o = 16; o > 0; o >>= 1) s += __shfl_xor_sync(~0u, s, o);
    int w = tid >> 5, lane = tid & 31;
    if (lane == 0) red1[w] = s;
    __syncthreads();
    s = 0.f;
#pragma unroll
    for (int i = 0; i < 8; i++) s += red1[i];
    float mu = s * (1.0f / 768.0f);
    float vs = 0.f;
#pragma unroll
    for (int i = 0; i < 3; i++) { float d = v[i] - mu; vs += d * d; }
#pragma unroll
    for (int o = 16; o > 0; o >>= 1) vs += __shfl_xor_sync(~0u, vs, o);
    if (lane == 0) red2[w] = vs;
    __syncthreads();
    vs = 0.f;
#pragma unroll
    for (int i = 0; i < 8; i++) vs += red2[i];
    float inv = rsqrtf(vs * (1.0f / 768.0f) + 1e-5f);
#pragma unroll
    for (int i = 0; i < 3; i++) {
        int c = tid + i * 256;
        out[row * Cdim + c] = (v[i] - mu) * inv * gamma[c] + beta[c];
    }
}

// ================= launch =================
extern "C" void kernel_launch(void* const* d_in, const int* in_sizes, int n_in,
                              void* d_out, int out_size) {
    const float* x      = (const float*)d_in[0];
    const float* w_qkv  = (const float*)d_in[1];
    const float* b_qkv  = (const float*)d_in[2];
    const float* w_proj = (const float*)d_in[3];
    const float* b_proj = (const float*)d_in[4];
    const float* gamma  = (const float*)d_in[5];
    const float* beta   = (const float*)d_in[6];
    const float* qe_w1  = (const float*)d_in[7];
    const float* qe_b1  = (const float*)d_in[8];
    const float* qe_w2  = (const float*)d_in[9];
    const float* qe_b2  = (const float*)d_in[10];
    const float* ke_w1  = (const float*)d_in[11];
    const float* ke_b1  = (const float*)d_in[12];
    const float* ke_w2  = (const float*)d_in[13];
    const float* ke_b2  = (const float*)d_in[14];
    const float* gate_params = (const float*)d_in[19];
    const float* ent_params  = (const float*)d_in[20];
    const float* md_w1  = (const float*)d_in[21];
    const float* md_b1  = (const float*)d_in[22];
    const float* md_w2  = (const float*)d_in[23];
    const float* md_b2  = (const float*)d_in[24];
    const float* gumbel = (const float*)d_in[25];
    float* out = (float*)d_out;

    uint32_t *qkvbf, *fusedbf;
    float *qout, *y, *xmean, *fw, *hq, *hk, *meas;
    cudaGetSymbolAddress((void**)&qkvbf, g_qkv_bf);
    cudaGetSymbolAddress((void**)&fusedbf, g_fused_bf);
    cudaGetSymbolAddress((void**)&qout, g_qout);
    cudaGetSymbolAddress((void**)&y, g_y);
    cudaGetSymbolAddress((void**)&xmean, g_xmean);
    cudaGetSymbolAddress((void**)&fw, g_fw);
    cudaGetSymbolAddress((void**)&hq, g_hq);
    cudaGetSymbolAddress((void**)&hk, g_hk);
    cudaGetSymbolAddress((void**)&meas, g_meas);

    cudaFuncSetAttribute(flash_kernel, cudaFuncAttributeMaxDynamicSharedMemorySize, FLASH_SMEM);
    cudaFuncSetAttribute(md_fused, cudaFuncAttributeMaxDynamicSharedMemorySize, MD_SMEM);

    // gate path (depends only on x)
    colmean_kernel<<<dim3(3, 8), 256>>>(x, xmean);
    fw_kernel<<<8, 768>>>(xmean, w_proj, b_proj, fw);
    // qkv = x @ w_qkv + b_qkv  -> bf16
    mma_qkv<<<dim3(2304 / 128, 8192 / 128), 256>>>(x, w_qkv, b_qkv, qkvbf,
                                                   768, 768, 2304, 2304);
    // quantum path: embeds (GEMM) -> mid -> measure MLP (GEMM) -> qout
    embed_gemm<<<dim3(NTOK / 128, 2), 256>>>(qkvbf, qe_w1, qe_b1, ke_w1, ke_b1, hq, hk);
    quantum_mid<<<NTOK / 128, 128>>>(hq, hk, qe_w2, qe_b2, ke_w2, ke_b2,
                                     gate_params, ent_params, gumbel, meas);
    md_fused<<<NTOK / 128, 256, MD_SMEM>>>(meas, md_w1, md_b1, md_w2, md_b2, qkvbf, qout);
    // fused classical attention + gate blend -> fused (bf16)
    flash_kernel<<<dim3(8, 64), 256, FLASH_SMEM>>>(qkvbf, qout, fw, fusedbf);
    // y = x + fused @ w_proj + b_proj
    mma_proj<<<dim3(768 / 128, 8192 / 128), 256>>>(fusedbf, w_proj, b_proj, x, y,
                                                   768, 768, 768, 768);
    // layernorm
    layernorm_kernel<<<8192, 256>>>(y, gamma, beta, out);
}